// round 11
// baseline (speedup 1.0000x reference)
#include <cuda_runtime.h>
#include <cuda_fp16.h>
#include <math.h>
#include <stdint.h>

// Problem constants
#define Bz   8
#define Cc   512
#define CQq  64
#define LL   96           // H == W == 96
#define HW   9216         // 96*96
#define BCHW 37748736     // 8*512*9216
#define BQKHW 9437184     // 8*128*9216 (stacked q||k)
#define ELN  7077888      // 8*96*96*96

// ---------------- scratch (device globals; allocation-free rule) ------------
__device__ __half g_xh [BCHW];      // fp16 copies of inputs [B][C][H][W]
__device__ __half g_yh [BCHW];
__device__ __half g_qk [2][BQKHW];  // [B][128][H][W]: ch 0..63 = q, 64..127 = k
__device__ __half g_qkT[2][BQKHW];  // [B][128][W][H]
__device__ __half g_v  [2][BCHW];   // [B][C][H][W]
__device__ __half g_vT [2][BCHW];   // [B][C][W][H]
__device__ float  g_eH [2][ELN];    // energies [B][W][H][Hk] (fp32 logits)
__device__ float  g_eW [2][ELN];    // [B][H][W][Wk]
__device__ __half g_aH [2][ELN];    // softmaxed attention, fp16
__device__ __half g_aW [2][ELN];
__device__ __half g_tH [2][BCHW];   // applyH out  [B][W][C][H]
__device__ __half g_tW [2][BCHW];   // applyW out  [B][H][C][W]
__device__ __half g_Wall[640 * 512]; // fp16 stacked Wq||Wk||Wv
__device__ float  g_ball[640];

// ---------------- helpers ----------------------------------------------------
__device__ __forceinline__ uint32_t pack2(float lo, float hi)
{
    __half2 h = __floats2half2_rn(lo, hi);
    return *reinterpret_cast<uint32_t*>(&h);
}

__device__ __forceinline__ void mma_f16(float& c0, float& c1, float& c2, float& c3,
                                        uint32_t a0, uint32_t a1, uint32_t a2, uint32_t a3,
                                        uint32_t b0, uint32_t b1)
{
    asm volatile(
        "mma.sync.aligned.m16n8k16.row.col.f32.f16.f16.f32 "
        "{%0,%1,%2,%3}, {%4,%5,%6,%7}, {%8,%9}, {%0,%1,%2,%3};"
        : "+f"(c0), "+f"(c1), "+f"(c2), "+f"(c3)
        : "r"(a0), "r"(a1), "r"(a2), "r"(a3), "r"(b0), "r"(b1));
}

__device__ __forceinline__ void ldsm_x4(uint32_t& r0, uint32_t& r1, uint32_t& r2, uint32_t& r3,
                                        uint32_t addr)
{
    asm volatile("ldmatrix.sync.aligned.m8n8.x4.shared.b16 {%0,%1,%2,%3}, [%4];"
                 : "=r"(r0), "=r"(r1), "=r"(r2), "=r"(r3) : "r"(addr));
}
__device__ __forceinline__ void ldsm_x4_t(uint32_t& r0, uint32_t& r1, uint32_t& r2, uint32_t& r3,
                                          uint32_t addr)
{
    asm volatile("ldmatrix.sync.aligned.m8n8.x4.trans.shared.b16 {%0,%1,%2,%3}, [%4];"
                 : "=r"(r0), "=r"(r1), "=r"(r2), "=r"(r3) : "r"(addr));
}
__device__ __forceinline__ void ldsm_x2(uint32_t& r0, uint32_t& r1, uint32_t addr)
{
    asm volatile("ldmatrix.sync.aligned.m8n8.x2.shared.b16 {%0,%1}, [%2];"
                 : "=r"(r0), "=r"(r1) : "r"(addr));
}
__device__ __forceinline__ void ldsm_x2_t(uint32_t& r0, uint32_t& r1, uint32_t addr)
{
    asm volatile("ldmatrix.sync.aligned.m8n8.x2.trans.shared.b16 {%0,%1}, [%2];"
                 : "=r"(r0), "=r"(r1) : "r"(addr));
}
__device__ __forceinline__ uint32_t smem_u32(const void* p)
{
    return (uint32_t)__cvta_generic_to_shared(p);
}
__device__ __forceinline__ void cp16(uint32_t dst, const void* src)
{
    asm volatile("cp.async.cg.shared.global [%0], [%1], 16;" :: "r"(dst), "l"(src));
}
__device__ __forceinline__ void cp_commit() { asm volatile("cp.async.commit_group;"); }

// ---------------- fp32 -> fp16 convert (both inputs, one launch) --------------
__global__ void f2h_kernel(const float* __restrict__ x, const float* __restrict__ y)
{
    const float* src = blockIdx.y ? y : x;
    __half* dst = blockIdx.y ? g_yh : g_xh;
    int i = (blockIdx.x * blockDim.x + threadIdx.x) * 8;
    float4 a = *(const float4*)&src[i];
    float4 b = *(const float4*)&src[i + 4];
    uint4 u = make_uint4(pack2(a.x, a.y), pack2(a.z, a.w), pack2(b.x, b.y), pack2(b.z, b.w));
    *(uint4*)&dst[i] = u;
}

// ---------------- weights: stack Wq||Wk||Wv (fp16) + biases -------------------
__global__ void weights_kernel(const float* __restrict__ Wq, const float* __restrict__ bq,
                               const float* __restrict__ Wk, const float* __restrict__ bk,
                               const float* __restrict__ Wv, const float* __restrict__ bv)
{
    int t = blockIdx.x * blockDim.x + threadIdx.x;   // 0..327679
    int m = t >> 9, k = t & 511;
    float w;
    if (m < 64)       w = Wq[m * 512 + k];
    else if (m < 128) w = Wk[(m - 64) * 512 + k];
    else              w = Wv[(m - 128) * 512 + k];
    g_Wall[t] = __float2half(w);
    if (t < 640) {
        float bb;
        if (t < 64)       bb = bq[t];
        else if (t < 128) bb = bk[t - 64];
        else              bb = bv[t - 128];
        g_ball[t] = bb;
    }
}

// ---------------- fused projection GEMM (qk + v), k-tile 64, 3-stage ---------
// out[m,n] = sum_k Wall[m,k] in[b,k,n] + ball[m]; m tile 0 -> qk, 1..4 -> v
#define A_STG 9216                  // halves per stage: 128 rows x stride 72
#define B_STG 8704                  // halves per stage: 64 rows x stride 136
#define STG_H (A_STG + B_STG)       // 17920 halves = 35840 B
#define PROJ_SMEM (3 * STG_H * 2)   // 107520 B
__global__ __launch_bounds__(256)
void proj_f16_kernel(const __half* __restrict__ xh, const __half* __restrict__ yh)
{
    extern __shared__ __align__(16) __half sm[];

    int inp = blockIdx.z >> 3;
    int b   = blockIdx.z & 7;
    int bm = blockIdx.y * 128;
    int bn = blockIdx.x * 128;
    int t  = threadIdx.x;
    int warp = t >> 5, lane = t & 31;
    int g = lane >> 2, tg = lane & 3;
    int mw = (warp >> 2) * 64;
    int nw = (warp & 3) * 32;

    const __half* in = inp ? yh : xh;
    const __half* inb = in + (size_t)b * Cc * HW;

    int aRow = (lane & 7) + ((lane >> 3) & 1) * 8;
    int aK8  = ((lane >> 4) & 1) * 8;
    int bRow = (lane & 7) + ((lane >> 3) & 1) * 8;

    float acc[4][4][4];
#pragma unroll
    for (int i = 0; i < 4; i++)
#pragma unroll
        for (int j = 0; j < 4; j++)
#pragma unroll
            for (int r = 0; r < 4; r++) acc[i][j][r] = 0.f;

    auto load_chunk = [&](int c, int s) {
        uint32_t aD = smem_u32(sm + s * STG_H);
        uint32_t bD = aD + A_STG * 2;
        int k0 = c * 64;
#pragma unroll
        for (int r = 0; r < 8; r++) {
            int idx = t + 256 * r;
            if (idx < 1024) {
                int row = idx >> 3, ch = idx & 7;
                cp16(aD + (uint32_t)((row * 72 + ch * 8) * 2),
                     &g_Wall[(size_t)(bm + row) * Cc + k0 + ch * 8]);
            } else {
                int j = idx - 1024;
                int row = j >> 4, ch = j & 15;
                cp16(bD + (uint32_t)((row * 136 + ch * 8) * 2),
                     &inb[(size_t)(k0 + row) * HW + bn + ch * 8]);
            }
        }
    };

    load_chunk(0, 0); cp_commit();
    load_chunk(1, 1); cp_commit();

    const int NK = Cc / 64;   // 8
    for (int i = 0; i < NK; i++) {
        asm volatile("cp.async.wait_group 1;" ::: "memory");
        __syncthreads();
        if (i + 2 < NK) load_chunk(i + 2, (i + 2) % 3);
        cp_commit();

        uint32_t aBase = smem_u32(sm + (i % 3) * STG_H);
        uint32_t bBase = aBase + A_STG * 2;
#pragma unroll
        for (int kk = 0; kk < 64; kk += 16) {
            uint32_t a[4][4], bb[4][2];
#pragma unroll
            for (int mt = 0; mt < 4; mt++) {
                uint32_t ad = aBase + (uint32_t)(((mw + mt * 16 + aRow) * 72 + kk + aK8) * 2);
                ldsm_x4(a[mt][0], a[mt][1], a[mt][2], a[mt][3], ad);
            }
#pragma unroll
            for (int nt = 0; nt < 4; nt++) {
                uint32_t bd = bBase + (uint32_t)(((kk + bRow) * 136 + nw + nt * 8) * 2);
                ldsm_x2_t(bb[nt][0], bb[nt][1], bd);
            }
#pragma unroll
            for (int mt = 0; mt < 4; mt++)
#pragma unroll
                for (int nt = 0; nt < 4; nt++)
                    mma_f16(acc[mt][nt][0], acc[mt][nt][1], acc[mt][nt][2], acc[mt][nt][3],
                            a[mt][0], a[mt][1], a[mt][2], a[mt][3],
                            bb[nt][0], bb[nt][1]);
        }
        __syncthreads();
    }

    __half* obase = (bm == 0)
        ? g_qk[inp] + (size_t)b * 128 * HW
        : g_v[inp]  + (size_t)b * Cc * HW + (size_t)(bm - 128) * HW;
#pragma unroll
    for (int mt = 0; mt < 4; mt++) {
        int mloc = mw + mt * 16 + g;
        float bi0 = g_ball[bm + mloc];
        float bi1 = g_ball[bm + mloc + 8];
        __half* op0 = obase + (size_t)mloc * HW + bn;
        __half* op1 = op0 + (size_t)8 * HW;
#pragma unroll
        for (int nt = 0; nt < 4; nt++) {
            int col = nw + nt * 8 + 2 * tg;
            *(__half2*)&op0[col] = __floats2half2_rn(acc[mt][nt][0] + bi0, acc[mt][nt][1] + bi0);
            *(__half2*)&op1[col] = __floats2half2_rn(acc[mt][nt][2] + bi1, acc[mt][nt][3] + bi1);
        }
    }
}

// ---------------- plane transpose: one 96x96 plane per block, uint4 I/O ------
__global__ __launch_bounds__(256)
void transposeP_kernel(const __half* __restrict__ in, __half* __restrict__ out)
{
    __shared__ __align__(16) __half s[96 * 104];   // s[w][h], pad 104
    int n = blockIdx.x;
    const __half* ip = in  + (size_t)n * HW;
    __half*       op = out + (size_t)n * HW;
    int t = threadIdx.x;

    // load: 96 rows x 12 uint4 chunks; scatter by element into s[w][h]
    for (int idx = t; idx < 1152; idx += 256) {
        int r = idx / 12, c8 = (idx % 12) * 8;
        uint4 v = *(const uint4*)&ip[r * LL + c8];
        const __half* hv = (const __half*)&v;
#pragma unroll
        for (int j = 0; j < 8; j++)
            s[(c8 + j) * 104 + r] = hv[j];
    }
    __syncthreads();
    // store: rows of s are transposed rows -> pure uint4 copy out
    for (int idx = t; idx < 1152; idx += 256) {
        int w = idx / 12, c8 = (idx % 12) * 8;
        *(uint4*)&op[w * LL + c8] = *(const uint4*)&s[w * 104 + c8];
    }
}

// ---------------- energy (merged 4 variants) via fp16 MMA --------------------
__global__ __launch_bounds__(256)
void energy_kernel()
{
    __shared__ __align__(16) __half Qs[64 * 104];   // [c][i] stride 104
    __shared__ __align__(16) __half Ks[64 * 104];
    int cfg = blockIdx.y;
    int dir = cfg & 1;
    int isH = (cfg < 2);
    const __half* Q = isH ? g_qkT[dir]     : g_qk[dir];
    const __half* K = isH ? g_qkT[1 - dir] : g_qk[1 - dir];
    K += (size_t)64 * HW;   // keys are channels 64..127
    float* E = isH ? g_eH[dir] : g_eW[dir];
    int maskDiag = isH;

    int bl = blockIdx.x;
    int b = bl / LL, line = bl % LL;
    const size_t QKB = (size_t)128 * HW;
    const __half* Qp = Q + (size_t)b * QKB + (size_t)line * LL;
    const __half* Kp = K + (size_t)b * QKB + (size_t)line * LL;
    int t = threadIdx.x;
    int warp = t >> 5, lane = t & 31;
    int g = lane >> 2, tg = lane & 3;
    int mw = (warp >> 2) * 48;
    int nw = (warp & 3) * 24;

    for (int idx = t; idx < 64 * 12; idx += 256) {
        int c = idx / 12, j8 = (idx % 12) * 8;
        *(uint4*)&Qs[c * 104 + j8] = *(const uint4*)&Qp[(size_t)c * HW + j8];
        *(uint4*)&Ks[c * 104 + j8] = *(const uint4*)&Kp[(size_t)c * HW + j8];
    }
    __syncthreads();

    uint32_t qsB = smem_u32(Qs);
    uint32_t ksB = smem_u32(Ks);
    int aMat = lane >> 3;
    int aC = ((aMat >> 1) & 1) * 8 + (lane & 7);
    int aI = (aMat & 1) * 8;
    int bC = ((lane >> 3) & 1) * 8 + (lane & 7);

    float acc[3][3][4];
#pragma unroll
    for (int i = 0; i < 3; i++)
#pragma unroll
        for (int j = 0; j < 3; j++)
#pragma unroll
            for (int r = 0; r < 4; r++) acc[i][j][r] = 0.f;

#pragma unroll
    for (int kk = 0; kk < 64; kk += 16) {
        uint32_t a[3][4], bb[3][2];
#pragma unroll
        for (int mt = 0; mt < 3; mt++) {
            uint32_t ad = qsB + (uint32_t)(((kk + aC) * 104 + mw + mt * 16 + aI) * 2);
            ldsm_x4_t(a[mt][0], a[mt][1], a[mt][2], a[mt][3], ad);
        }
#pragma unroll
        for (int nt = 0; nt < 3; nt++) {
            uint32_t bd = ksB + (uint32_t)(((kk + bC) * 104 + nw + nt * 8) * 2);
            ldsm_x2_t(bb[nt][0], bb[nt][1], bd);
        }
#pragma unroll
        for (int mt = 0; mt < 3; mt++)
#pragma unroll
            for (int nt = 0; nt < 3; nt++)
                mma_f16(acc[mt][nt][0], acc[mt][nt][1], acc[mt][nt][2], acc[mt][nt][3],
                        a[mt][0], a[mt][1], a[mt][2], a[mt][3],
                        bb[nt][0], bb[nt][1]);
    }

    float* Eb = E + (size_t)bl * LL * LL;
#pragma unroll
    for (int mt = 0; mt < 3; mt++) {
        int i0 = mw + mt * 16 + g;
        int i1 = i0 + 8;
#pragma unroll
        for (int nt = 0; nt < 3; nt++) {
            int j0 = nw + nt * 8 + 2 * tg;
            float v0 = acc[mt][nt][0], v1 = acc[mt][nt][1];
            float v2 = acc[mt][nt][2], v3 = acc[mt][nt][3];
            if (maskDiag) {
                if (i0 == j0)     v0 = -1e30f;
                if (i0 == j0 + 1) v1 = -1e30f;
                if (i1 == j0)     v2 = -1e30f;
                if (i1 == j0 + 1) v3 = -1e30f;
            }
            *(float2*)&Eb[(size_t)i0 * LL + j0] = make_float2(v0, v1);
            *(float2*)&Eb[(size_t)i1 * LL + j0] = make_float2(v2, v3);
        }
    }
}

// ---------------- joint softmax; fp32 logits in, fp16 attention out ----------
__global__ void softmax_kernel()
{
    int dir  = blockIdx.y;
    int warp = (blockIdx.x * blockDim.x + threadIdx.x) >> 5;
    int lane = threadIdx.x & 31;
    int b  = warp / HW;
    int hw = warp % HW;
    int h = hw / LL, w = hw % LL;
    size_t offH = (((size_t)b * LL + w) * LL + h) * LL;
    size_t offW = (((size_t)b * LL + h) * LL + w) * LL;
    const float* rH = &g_eH[dir][offH];
    const float* rW = &g_eW[dir][offW];
    __half* oH = &g_aH[dir][offH];
    __half* oW = &g_aW[dir][offW];
    float v[6];
#pragma unroll
    for (int i = 0; i < 3; i++) v[i]     = rH[lane + 32 * i];
#pragma unroll
    for (int i = 0; i < 3; i++) v[3 + i] = rW[lane + 32 * i];
    float m = v[0];
#pragma unroll
    for (int i = 1; i < 6; i++) m = fmaxf(m, v[i]);
#pragma unroll
    for (int o = 16; o > 0; o >>= 1) m = fmaxf(m, __shfl_xor_sync(0xffffffffu, m, o));
    float s = 0.f;
#pragma unroll
    for (int i = 0; i < 6; i++) { v[i] = __expf(v[i] - m); s += v[i]; }
#pragma unroll
    for (int o = 16; o > 0; o >>= 1) s += __shfl_xor_sync(0xffffffffu, s, o);
    float inv = 1.f / s;
#pragma unroll
    for (int i = 0; i < 3; i++) oH[lane + 32 * i] = __float2half(v[i]     * inv);
#pragma unroll
    for (int i = 0; i < 3; i++) oW[lane + 32 * i] = __float2half(v[3 + i] * inv);
}

// ---------------- apply (merged 4 variants) via fp16 MMA + ldmatrix ----------
__global__ __launch_bounds__(256)
void apply_f16_kernel()
{
    __shared__ __align__(16) __half Vs [128 * 104];   // [c][k] stride 104
    __shared__ __align__(16) __half As2[ 96 * 104];   // [i][k] stride 104
    int z = blockIdx.z;
    int half_ = z >> 1;
    int isW = z & 1;
    const __half* Vb = isW ? g_v[half_]  : g_vT[half_];
    const __half* Ab = isW ? g_aW[1 - half_] : g_aH[1 - half_];
    __half* Ob = isW ? g_tW[half_] : g_tH[half_];

    int ct0 = blockIdx.x * 128;
    int bl  = blockIdx.y;
    int b = bl / LL, line = bl % LL;
    int t = threadIdx.x;
    int warp = t >> 5, lane = t & 31;
    int g = lane >> 2, tg = lane & 3;
    int mw = (warp >> 2) * 64;
    int nw = (warp & 3) * 24;

    const __half* Vp = Vb + (((size_t)(b * Cc + ct0)) * LL + line) * LL;
#pragma unroll
    for (int r = 0; r < 6; r++) {
        int idx = t + 256 * r;
        int c = idx / 12, j8 = (idx % 12) * 8;
        *(uint4*)&Vs[c * 104 + j8] = *(const uint4*)&Vp[(size_t)c * HW + j8];
    }
    const __half* Ap = Ab + (size_t)bl * LL * LL;
    for (int idx = t; idx < 96 * 12; idx += 256) {
        int i = idx / 12, j8 = (idx % 12) * 8;
        *(uint4*)&As2[i * 104 + j8] = *(const uint4*)&Ap[i * LL + j8];
    }
    __syncthreads();

    uint32_t vsB = smem_u32(Vs);
    uint32_t asB = smem_u32(As2);
    int aRow = (lane & 7) + ((lane >> 3) & 1) * 8;
    int aK8  = ((lane >> 4) & 1) * 8;
    int bRowN = lane & 7;
    int bK8  = ((lane >> 3) & 1) * 8;

    float acc[4][3][4];
#pragma unroll
    for (int i = 0; i < 4; i++)
#pragma unroll
        for (int j = 0; j < 3; j++)
#pragma unroll
            for (int r = 0; r < 4; r++) acc[i][j][r] = 0.f;

#pragma unroll
    for (int kk = 0; kk < 96; kk += 16) {
        uint32_t a[4][4], bb[3][2];
#pragma unroll
        for (int mt = 0; mt < 4; mt++) {
            uint32_t ad = vsB + (uint32_t)(((mw + mt * 16 + aRow) * 104 + kk + aK8) * 2);
            ldsm_x4(a[mt][0], a[mt][1], a[mt][2], a[mt][3], ad);
        }
#pragma unroll
        for (int nt = 0; nt < 3; nt++) {
            uint32_t bd = asB + (uint32_t)(((nw + nt * 8 + bRowN) * 104 + kk + bK8) * 2);
            ldsm_x2(bb[nt][0], bb[nt][1], bd);
        }
#pragma unroll
        for (int mt = 0; mt < 4; mt++)
#pragma unroll
            for (int nt = 0; nt < 3; nt++)
                mma_f16(acc[mt][nt][0], acc[mt][nt][1], acc[mt][nt][2], acc[mt][nt][3],
                        a[mt][0], a[mt][1], a[mt][2], a[mt][3],
                        bb[nt][0], bb[nt][1]);
    }

    __half* Op = Ob + ((size_t)bl * Cc + ct0) * LL;
#pragma unroll
    for (int mt = 0; mt < 4; mt++) {
        int m0g = mw + mt * 16 + g;
        __half* o0 = Op + (size_t)m0g * LL;
        __half* o1 = o0 + (size_t)8 * LL;
#pragma unroll
        for (int nt = 0; nt < 3; nt++) {
            int col = nw + nt * 8 + 2 * tg;
            *(__half2*)&o0[col] = __floats2half2_rn(acc[mt][nt][0], acc[mt][nt][1]);
            *(__half2*)&o1[col] = __floats2half2_rn(acc[mt][nt][2], acc[mt][nt][3]);
        }
    }
}

// ---------------- final: out = gamma*(tH^T + tW) + residual (wide I/O) -------
// block: 32 h-rows x 96 w per (o,bc); grid (3, 2*B*C)
__global__ __launch_bounds__(256)
void final_kernel(const float* __restrict__ x, const float* __restrict__ y,
                  const float* __restrict__ gamma, float* __restrict__ out)
{
    __shared__ __align__(16) __half s[96 * 40];   // s[w][h_local], pad 40
    int z  = blockIdx.y;
    int o  = z >> 12;           // B*C = 4096
    int bc = z & 4095;
    int b  = bc >> 9;
    int c  = bc & 511;
    int h0 = blockIdx.x * 32;
    float g = gamma[0];
    const float* res = (o == 0 ? x : y) + (size_t)bc * HW;
    const __half* tH = g_tH[o];
    const __half* tW = g_tW[o];
    int t = threadIdx.x;

    // load tH slab: 96 w-rows x 32 h halves = 96 x 4 uint4 (pure copy)
    const __half* tHb = tH + (((size_t)b * LL) * Cc + c) * LL + h0;
    for (int idx = t; idx < 384; idx += 256) {
        int w = idx >> 2, c8 = (idx & 3) * 8;
        *(uint4*)&s[w * 40 + c8] = *(const uint4*)&tHb[(size_t)w * Cc * LL + c8];
    }
    __syncthreads();

    const __half* tWb = tW + (((size_t)b * LL + h0) * Cc + c) * LL;
    float* op = out + (size_t)o * BCHW + (size_t)bc * HW;
    // output: 32 h x 24 float4 chunks = 768
    for (int idx = t; idx < 768; idx += 256) {
        int h = idx / 24, c4 = (idx % 24) * 4;
        // tW: 4 halves contiguous in w
        uint2 twu = *(const uint2*)&tWb[(size_t)h * Cc * LL + c4];
        __half2 tw0 = *(__half2*)&twu.x;
        __half2 tw1 = *(__half2*)&twu.y;
        float4 rs = *(const float4*)&res[(size_t)(h0 + h) * LL + c4];
        float4 ov;
        ov.x = g * (__half2float(s[(c4 + 0) * 40 + h]) + __low2float(tw0))  + rs.x;
        ov.y = g * (__half2float(s[(c4 + 1) * 40 + h]) + __high2float(tw0)) + rs.y;
        ov.z = g * (__half2float(s[(c4 + 2) * 40 + h]) + __low2float(tw1))  + rs.z;
        ov.w = g * (__half2float(s[(c4 + 3) * 40 + h]) + __high2float(tw1)) + rs.w;
        *(float4*)&op[(size_t)(h0 + h) * LL + c4] = ov;
    }
}

// ---------------------------------------------------------------------------
extern "C" void kernel_launch(void* const* d_in, const int* in_sizes, int n_in,
                              void* d_out, int out_size)
{
    const float* x     = (const float*)d_in[0];
    const float* y     = (const float*)d_in[1];
    const float* Wq    = (const float*)d_in[2];
    const float* bq    = (const float*)d_in[3];
    const float* Wk    = (const float*)d_in[4];
    const float* bk    = (const float*)d_in[5];
    const float* Wv    = (const float*)d_in[6];
    const float* bv    = (const float*)d_in[7];
    const float* gamma = (const float*)d_in[8];
    float* out = (float*)d_out;
    (void)in_sizes; (void)n_in; (void)out_size;

    __half *xh, *yh, *qk, *qkT, *v, *vT;
    cudaGetSymbolAddress((void**)&xh,  g_xh);
    cudaGetSymbolAddress((void**)&yh,  g_yh);
    cudaGetSymbolAddress((void**)&qk,  g_qk);
    cudaGetSymbolAddress((void**)&qkT, g_qkT);
    cudaGetSymbolAddress((void**)&v,   g_v);
    cudaGetSymbolAddress((void**)&vT,  g_vT);

    cudaFuncSetAttribute(proj_f16_kernel, cudaFuncAttributeMaxDynamicSharedMemorySize, PROJ_SMEM);

    // 0) convert inputs + stack weights to fp16
    f2h_kernel<<<dim3(BCHW / 2048, 2), 256>>>(x, y);
    weights_kernel<<<1280, 256>>>(Wq, bq, Wk, bk, Wv, bv);

    // 1) fused projections: single launch computes qk and v for both inputs
    proj_f16_kernel<<<dim3(72, 5, 16), 256, PROJ_SMEM>>>(xh, yh);

    // 2) transposes (one plane per block, uint4 I/O)
    transposeP_kernel<<<2 * Bz * 128, 256>>>(qk, qkT);
    transposeP_kernel<<<2 * Bz * Cc,  256>>>(v, vT);

    // 3) energies (4 variants in one launch)
    energy_kernel<<<dim3(Bz * LL, 4), 256>>>();

    // 4) joint softmax -> fp16 attention
    softmax_kernel<<<dim3(9216, 2), 256>>>();

    // 5) applies (4 variants in one launch)
    apply_f16_kernel<<<dim3(4, Bz * LL, 4), 256>>>();

    // 6) combine + residual
    final_kernel<<<dim3(3, 2 * Bz * Cc), 256>>>(x, y, gamma, out);
}

// round 12
// speedup vs baseline: 1.0510x; 1.0510x over previous
#include <cuda_runtime.h>
#include <cuda_fp16.h>
#include <math.h>
#include <stdint.h>

// Problem constants
#define Bz   8
#define Cc   512
#define CQq  64
#define LL   96           // H == W == 96
#define HW   9216         // 96*96
#define BCHW 37748736     // 8*512*9216
#define BQKHW 9437184     // 8*128*9216 (stacked q||k)
#define ELN  7077888      // 8*96*96*96

// ---------------- scratch (device globals; allocation-free rule) ------------
__device__ __half g_xh [BCHW];      // fp16 copies of inputs [B][C][H][W]
__device__ __half g_yh [BCHW];
__device__ __half g_qk [2][BQKHW];  // [B][128][H][W]: ch 0..63 = q, 64..127 = k
__device__ __half g_qkT[2][BQKHW];  // [B][128][W][H]
__device__ __half g_v  [2][BCHW];   // [B][C][H][W]
__device__ __half g_vT [2][BCHW];   // [B][C][W][H]
__device__ float  g_eH [2][ELN];    // energies [B][W][H][Hk] (fp32 logits)
__device__ float  g_eW [2][ELN];    // [B][H][W][Wk]
__device__ __half g_aH [2][ELN];    // softmaxed attention, fp16
__device__ __half g_aW [2][ELN];
__device__ __half g_tH [2][BCHW];   // applyH out  [B][W][C][H]
__device__ __half g_tW [2][BCHW];   // applyW out  [B][H][C][W]
__device__ __half g_Wall[640 * 512]; // fp16 stacked Wq||Wk||Wv
__device__ float  g_ball[640];

// ---------------- helpers ----------------------------------------------------
__device__ __forceinline__ uint32_t pack2(float lo, float hi)
{
    __half2 h = __floats2half2_rn(lo, hi);
    return *reinterpret_cast<uint32_t*>(&h);
}

__device__ __forceinline__ void mma_f16(float& c0, float& c1, float& c2, float& c3,
                                        uint32_t a0, uint32_t a1, uint32_t a2, uint32_t a3,
                                        uint32_t b0, uint32_t b1)
{
    asm volatile(
        "mma.sync.aligned.m16n8k16.row.col.f32.f16.f16.f32 "
        "{%0,%1,%2,%3}, {%4,%5,%6,%7}, {%8,%9}, {%0,%1,%2,%3};"
        : "+f"(c0), "+f"(c1), "+f"(c2), "+f"(c3)
        : "r"(a0), "r"(a1), "r"(a2), "r"(a3), "r"(b0), "r"(b1));
}

__device__ __forceinline__ void ldsm_x4(uint32_t& r0, uint32_t& r1, uint32_t& r2, uint32_t& r3,
                                        uint32_t addr)
{
    asm volatile("ldmatrix.sync.aligned.m8n8.x4.shared.b16 {%0,%1,%2,%3}, [%4];"
                 : "=r"(r0), "=r"(r1), "=r"(r2), "=r"(r3) : "r"(addr));
}
__device__ __forceinline__ void ldsm_x4_t(uint32_t& r0, uint32_t& r1, uint32_t& r2, uint32_t& r3,
                                          uint32_t addr)
{
    asm volatile("ldmatrix.sync.aligned.m8n8.x4.trans.shared.b16 {%0,%1,%2,%3}, [%4];"
                 : "=r"(r0), "=r"(r1), "=r"(r2), "=r"(r3) : "r"(addr));
}
__device__ __forceinline__ void ldsm_x2(uint32_t& r0, uint32_t& r1, uint32_t addr)
{
    asm volatile("ldmatrix.sync.aligned.m8n8.x2.shared.b16 {%0,%1}, [%2];"
                 : "=r"(r0), "=r"(r1) : "r"(addr));
}
__device__ __forceinline__ void ldsm_x2_t(uint32_t& r0, uint32_t& r1, uint32_t addr)
{
    asm volatile("ldmatrix.sync.aligned.m8n8.x2.trans.shared.b16 {%0,%1}, [%2];"
                 : "=r"(r0), "=r"(r1) : "r"(addr));
}
__device__ __forceinline__ uint32_t smem_u32(const void* p)
{
    return (uint32_t)__cvta_generic_to_shared(p);
}
__device__ __forceinline__ void cp16(uint32_t dst, const void* src)
{
    asm volatile("cp.async.cg.shared.global [%0], [%1], 16;" :: "r"(dst), "l"(src));
}
__device__ __forceinline__ void cp_commit() { asm volatile("cp.async.commit_group;"); }

// ---------------- fp32 -> fp16 convert (both inputs, one launch) --------------
__global__ void f2h_kernel(const float* __restrict__ x, const float* __restrict__ y)
{
    const float* src = blockIdx.y ? y : x;
    __half* dst = blockIdx.y ? g_yh : g_xh;
    int i = (blockIdx.x * blockDim.x + threadIdx.x) * 8;
    float4 a = *(const float4*)&src[i];
    float4 b = *(const float4*)&src[i + 4];
    uint4 u = make_uint4(pack2(a.x, a.y), pack2(a.z, a.w), pack2(b.x, b.y), pack2(b.z, b.w));
    *(uint4*)&dst[i] = u;
}

// ---------------- weights: stack Wq||Wk||Wv (fp16) + biases -------------------
__global__ void weights_kernel(const float* __restrict__ Wq, const float* __restrict__ bq,
                               const float* __restrict__ Wk, const float* __restrict__ bk,
                               const float* __restrict__ Wv, const float* __restrict__ bv)
{
    int t = blockIdx.x * blockDim.x + threadIdx.x;   // 0..327679
    int m = t >> 9, k = t & 511;
    float w;
    if (m < 64)       w = Wq[m * 512 + k];
    else if (m < 128) w = Wk[(m - 64) * 512 + k];
    else              w = Wv[(m - 128) * 512 + k];
    g_Wall[t] = __float2half(w);
    if (t < 640) {
        float bb;
        if (t < 64)       bb = bq[t];
        else if (t < 128) bb = bk[t - 64];
        else              bb = bv[t - 128];
        g_ball[t] = bb;
    }
}

// ---------------- fused projection GEMM (qk + v), k-tile 64, 3-stage ---------
// out[m,n] = sum_k Wall[m,k] in[b,k,n] + ball[m]; m tile 0 -> qk, 1..4 -> v
#define A_STG 9216                  // halves per stage: 128 rows x stride 72
#define B_STG 8704                  // halves per stage: 64 rows x stride 136
#define STG_H (A_STG + B_STG)       // 17920 halves = 35840 B
#define PROJ_SMEM (3 * STG_H * 2)   // 107520 B
__global__ __launch_bounds__(256)
void proj_f16_kernel(const __half* __restrict__ xh, const __half* __restrict__ yh)
{
    extern __shared__ __align__(16) __half sm[];

    int inp = blockIdx.z >> 3;
    int b   = blockIdx.z & 7;
    int bm = blockIdx.y * 128;
    int bn = blockIdx.x * 128;
    int t  = threadIdx.x;
    int warp = t >> 5, lane = t & 31;
    int g = lane >> 2, tg = lane & 3;
    int mw = (warp >> 2) * 64;
    int nw = (warp & 3) * 32;

    const __half* in = inp ? yh : xh;
    const __half* inb = in + (size_t)b * Cc * HW;

    int aRow = (lane & 7) + ((lane >> 3) & 1) * 8;
    int aK8  = ((lane >> 4) & 1) * 8;
    int bRow = (lane & 7) + ((lane >> 3) & 1) * 8;

    float acc[4][4][4];
#pragma unroll
    for (int i = 0; i < 4; i++)
#pragma unroll
        for (int j = 0; j < 4; j++)
#pragma unroll
            for (int r = 0; r < 4; r++) acc[i][j][r] = 0.f;

    auto load_chunk = [&](int c, int s) {
        uint32_t aD = smem_u32(sm + s * STG_H);
        uint32_t bD = aD + A_STG * 2;
        int k0 = c * 64;
#pragma unroll
        for (int r = 0; r < 8; r++) {
            int idx = t + 256 * r;
            if (idx < 1024) {
                int row = idx >> 3, ch = idx & 7;
                cp16(aD + (uint32_t)((row * 72 + ch * 8) * 2),
                     &g_Wall[(size_t)(bm + row) * Cc + k0 + ch * 8]);
            } else {
                int j = idx - 1024;
                int row = j >> 4, ch = j & 15;
                cp16(bD + (uint32_t)((row * 136 + ch * 8) * 2),
                     &inb[(size_t)(k0 + row) * HW + bn + ch * 8]);
            }
        }
    };

    load_chunk(0, 0); cp_commit();
    load_chunk(1, 1); cp_commit();

    const int NK = Cc / 64;   // 8
    for (int i = 0; i < NK; i++) {
        asm volatile("cp.async.wait_group 1;" ::: "memory");
        __syncthreads();
        if (i + 2 < NK) load_chunk(i + 2, (i + 2) % 3);
        cp_commit();

        uint32_t aBase = smem_u32(sm + (i % 3) * STG_H);
        uint32_t bBase = aBase + A_STG * 2;
#pragma unroll
        for (int kk = 0; kk < 64; kk += 16) {
            uint32_t a[4][4], bb[4][2];
#pragma unroll
            for (int mt = 0; mt < 4; mt++) {
                uint32_t ad = aBase + (uint32_t)(((mw + mt * 16 + aRow) * 72 + kk + aK8) * 2);
                ldsm_x4(a[mt][0], a[mt][1], a[mt][2], a[mt][3], ad);
            }
#pragma unroll
            for (int nt = 0; nt < 4; nt++) {
                uint32_t bd = bBase + (uint32_t)(((kk + bRow) * 136 + nw + nt * 8) * 2);
                ldsm_x2_t(bb[nt][0], bb[nt][1], bd);
            }
#pragma unroll
            for (int mt = 0; mt < 4; mt++)
#pragma unroll
                for (int nt = 0; nt < 4; nt++)
                    mma_f16(acc[mt][nt][0], acc[mt][nt][1], acc[mt][nt][2], acc[mt][nt][3],
                            a[mt][0], a[mt][1], a[mt][2], a[mt][3],
                            bb[nt][0], bb[nt][1]);
        }
        __syncthreads();
    }

    __half* obase = (bm == 0)
        ? g_qk[inp] + (size_t)b * 128 * HW
        : g_v[inp]  + (size_t)b * Cc * HW + (size_t)(bm - 128) * HW;
#pragma unroll
    for (int mt = 0; mt < 4; mt++) {
        int mloc = mw + mt * 16 + g;
        float bi0 = g_ball[bm + mloc];
        float bi1 = g_ball[bm + mloc + 8];
        __half* op0 = obase + (size_t)mloc * HW + bn;
        __half* op1 = op0 + (size_t)8 * HW;
#pragma unroll
        for (int nt = 0; nt < 4; nt++) {
            int col = nw + nt * 8 + 2 * tg;
            *(__half2*)&op0[col] = __floats2half2_rn(acc[mt][nt][0] + bi0, acc[mt][nt][1] + bi0);
            *(__half2*)&op1[col] = __floats2half2_rn(acc[mt][nt][2] + bi1, acc[mt][nt][3] + bi1);
        }
    }
}

// ---------------- plane transpose (fp16, half2-vectorized, 32x32 tiles) ------
__global__ void transpose16_kernel(const __half* __restrict__ in, __half* __restrict__ out)
{
    __shared__ __half2 til[32][17];
    int n = blockIdx.z;
    int h0 = blockIdx.y * 32, w0 = blockIdx.x * 32;
    const __half* ip = in  + (size_t)n * HW;
    __half*       op = out + (size_t)n * HW;
    int tx = threadIdx.x, ty = threadIdx.y;   // 16 x 16
#pragma unroll
    for (int r = 0; r < 32; r += 16)
        til[ty + r][tx] = *(const __half2*)&ip[(size_t)(h0 + ty + r) * LL + w0 + 2 * tx];
    __syncthreads();
#pragma unroll
    for (int r = 0; r < 32; r += 16) {
        int w = ty + r;
        int k = w >> 1, ln = w & 1;
        __half2 A = til[2 * tx][k];
        __half2 B = til[2 * tx + 1][k];
        __half a = ln ? __high2half(A) : __low2half(A);
        __half b = ln ? __high2half(B) : __low2half(B);
        *(__half2*)&op[(size_t)(w0 + w) * LL + h0 + 2 * tx] = __halves2half2(a, b);
    }
}

// ---------------- energy (merged 4 variants) via fp16 MMA --------------------
__global__ __launch_bounds__(256)
void energy_kernel()
{
    __shared__ __align__(16) __half Qs[64 * 104];   // [c][i] stride 104
    __shared__ __align__(16) __half Ks[64 * 104];
    int cfg = blockIdx.y;
    int dir = cfg & 1;
    int isH = (cfg < 2);
    const __half* Q = isH ? g_qkT[dir]     : g_qk[dir];
    const __half* K = isH ? g_qkT[1 - dir] : g_qk[1 - dir];
    K += (size_t)64 * HW;   // keys are channels 64..127
    float* E = isH ? g_eH[dir] : g_eW[dir];
    int maskDiag = isH;

    int bl = blockIdx.x;
    int b = bl / LL, line = bl % LL;
    const size_t QKB = (size_t)128 * HW;
    const __half* Qp = Q + (size_t)b * QKB + (size_t)line * LL;
    const __half* Kp = K + (size_t)b * QKB + (size_t)line * LL;
    int t = threadIdx.x;
    int warp = t >> 5, lane = t & 31;
    int g = lane >> 2, tg = lane & 3;
    int mw = (warp >> 2) * 48;
    int nw = (warp & 3) * 24;

    for (int idx = t; idx < 64 * 12; idx += 256) {
        int c = idx / 12, j8 = (idx % 12) * 8;
        *(uint4*)&Qs[c * 104 + j8] = *(const uint4*)&Qp[(size_t)c * HW + j8];
        *(uint4*)&Ks[c * 104 + j8] = *(const uint4*)&Kp[(size_t)c * HW + j8];
    }
    __syncthreads();

    uint32_t qsB = smem_u32(Qs);
    uint32_t ksB = smem_u32(Ks);
    int aMat = lane >> 3;
    int aC = ((aMat >> 1) & 1) * 8 + (lane & 7);
    int aI = (aMat & 1) * 8;
    int bC = ((lane >> 3) & 1) * 8 + (lane & 7);

    float acc[3][3][4];
#pragma unroll
    for (int i = 0; i < 3; i++)
#pragma unroll
        for (int j = 0; j < 3; j++)
#pragma unroll
            for (int r = 0; r < 4; r++) acc[i][j][r] = 0.f;

#pragma unroll
    for (int kk = 0; kk < 64; kk += 16) {
        uint32_t a[3][4], bb[3][2];
#pragma unroll
        for (int mt = 0; mt < 3; mt++) {
            uint32_t ad = qsB + (uint32_t)(((kk + aC) * 104 + mw + mt * 16 + aI) * 2);
            ldsm_x4_t(a[mt][0], a[mt][1], a[mt][2], a[mt][3], ad);
        }
#pragma unroll
        for (int nt = 0; nt < 3; nt++) {
            uint32_t bd = ksB + (uint32_t)(((kk + bC) * 104 + nw + nt * 8) * 2);
            ldsm_x2_t(bb[nt][0], bb[nt][1], bd);
        }
#pragma unroll
        for (int mt = 0; mt < 3; mt++)
#pragma unroll
            for (int nt = 0; nt < 3; nt++)
                mma_f16(acc[mt][nt][0], acc[mt][nt][1], acc[mt][nt][2], acc[mt][nt][3],
                        a[mt][0], a[mt][1], a[mt][2], a[mt][3],
                        bb[nt][0], bb[nt][1]);
    }

    float* Eb = E + (size_t)bl * LL * LL;
#pragma unroll
    for (int mt = 0; mt < 3; mt++) {
        int i0 = mw + mt * 16 + g;
        int i1 = i0 + 8;
#pragma unroll
        for (int nt = 0; nt < 3; nt++) {
            int j0 = nw + nt * 8 + 2 * tg;
            float v0 = acc[mt][nt][0], v1 = acc[mt][nt][1];
            float v2 = acc[mt][nt][2], v3 = acc[mt][nt][3];
            if (maskDiag) {
                if (i0 == j0)     v0 = -1e30f;
                if (i0 == j0 + 1) v1 = -1e30f;
                if (i1 == j0)     v2 = -1e30f;
                if (i1 == j0 + 1) v3 = -1e30f;
            }
            *(float2*)&Eb[(size_t)i0 * LL + j0] = make_float2(v0, v1);
            *(float2*)&Eb[(size_t)i1 * LL + j0] = make_float2(v2, v3);
        }
    }
}

// ---------------- joint softmax; fp32 logits in, fp16 attention out ----------
__global__ void softmax_kernel()
{
    int dir  = blockIdx.y;
    int warp = (blockIdx.x * blockDim.x + threadIdx.x) >> 5;
    int lane = threadIdx.x & 31;
    int b  = warp / HW;
    int hw = warp % HW;
    int h = hw / LL, w = hw % LL;
    size_t offH = (((size_t)b * LL + w) * LL + h) * LL;
    size_t offW = (((size_t)b * LL + h) * LL + w) * LL;
    const float* rH = &g_eH[dir][offH];
    const float* rW = &g_eW[dir][offW];
    __half* oH = &g_aH[dir][offH];
    __half* oW = &g_aW[dir][offW];
    float v[6];
#pragma unroll
    for (int i = 0; i < 3; i++) v[i]     = rH[lane + 32 * i];
#pragma unroll
    for (int i = 0; i < 3; i++) v[3 + i] = rW[lane + 32 * i];
    float m = v[0];
#pragma unroll
    for (int i = 1; i < 6; i++) m = fmaxf(m, v[i]);
#pragma unroll
    for (int o = 16; o > 0; o >>= 1) m = fmaxf(m, __shfl_xor_sync(0xffffffffu, m, o));
    float s = 0.f;
#pragma unroll
    for (int i = 0; i < 6; i++) { v[i] = __expf(v[i] - m); s += v[i]; }
#pragma unroll
    for (int o = 16; o > 0; o >>= 1) s += __shfl_xor_sync(0xffffffffu, s, o);
    float inv = 1.f / s;
#pragma unroll
    for (int i = 0; i < 3; i++) oH[lane + 32 * i] = __float2half(v[i]     * inv);
#pragma unroll
    for (int i = 0; i < 3; i++) oW[lane + 32 * i] = __float2half(v[3 + i] * inv);
}

// ---------------- apply (merged 4 variants) via fp16 MMA + ldmatrix ----------
__global__ __launch_bounds__(256)
void apply_f16_kernel()
{
    __shared__ __align__(16) __half Vs [128 * 104];   // [c][k] stride 104
    __shared__ __align__(16) __half As2[ 96 * 104];   // [i][k] stride 104
    int z = blockIdx.z;
    int half_ = z >> 1;
    int isW = z & 1;
    const __half* Vb = isW ? g_v[half_]  : g_vT[half_];
    const __half* Ab = isW ? g_aW[1 - half_] : g_aH[1 - half_];
    __half* Ob = isW ? g_tW[half_] : g_tH[half_];

    int ct0 = blockIdx.x * 128;
    int bl  = blockIdx.y;
    int b = bl / LL, line = bl % LL;
    int t = threadIdx.x;
    int warp = t >> 5, lane = t & 31;
    int g = lane >> 2, tg = lane & 3;
    int mw = (warp >> 2) * 64;
    int nw = (warp & 3) * 24;

    const __half* Vp = Vb + (((size_t)(b * Cc + ct0)) * LL + line) * LL;
#pragma unroll
    for (int r = 0; r < 6; r++) {
        int idx = t + 256 * r;
        int c = idx / 12, j8 = (idx % 12) * 8;
        *(uint4*)&Vs[c * 104 + j8] = *(const uint4*)&Vp[(size_t)c * HW + j8];
    }
    const __half* Ap = Ab + (size_t)bl * LL * LL;
    for (int idx = t; idx < 96 * 12; idx += 256) {
        int i = idx / 12, j8 = (idx % 12) * 8;
        *(uint4*)&As2[i * 104 + j8] = *(const uint4*)&Ap[i * LL + j8];
    }
    __syncthreads();

    uint32_t vsB = smem_u32(Vs);
    uint32_t asB = smem_u32(As2);
    int aRow = (lane & 7) + ((lane >> 3) & 1) * 8;
    int aK8  = ((lane >> 4) & 1) * 8;
    int bRowN = lane & 7;
    int bK8  = ((lane >> 3) & 1) * 8;

    float acc[4][3][4];
#pragma unroll
    for (int i = 0; i < 4; i++)
#pragma unroll
        for (int j = 0; j < 3; j++)
#pragma unroll
            for (int r = 0; r < 4; r++) acc[i][j][r] = 0.f;

#pragma unroll
    for (int kk = 0; kk < 96; kk += 16) {
        uint32_t a[4][4], bb[3][2];
#pragma unroll
        for (int mt = 0; mt < 4; mt++) {
            uint32_t ad = vsB + (uint32_t)(((mw + mt * 16 + aRow) * 104 + kk + aK8) * 2);
            ldsm_x4(a[mt][0], a[mt][1], a[mt][2], a[mt][3], ad);
        }
#pragma unroll
        for (int nt = 0; nt < 3; nt++) {
            uint32_t bd = asB + (uint32_t)(((nw + nt * 8 + bRowN) * 104 + kk + bK8) * 2);
            ldsm_x2(bb[nt][0], bb[nt][1], bd);
        }
#pragma unroll
        for (int mt = 0; mt < 4; mt++)
#pragma unroll
            for (int nt = 0; nt < 3; nt++)
                mma_f16(acc[mt][nt][0], acc[mt][nt][1], acc[mt][nt][2], acc[mt][nt][3],
                        a[mt][0], a[mt][1], a[mt][2], a[mt][3],
                        bb[nt][0], bb[nt][1]);
    }

    __half* Op = Ob + ((size_t)bl * Cc + ct0) * LL;
#pragma unroll
    for (int mt = 0; mt < 4; mt++) {
        int m0g = mw + mt * 16 + g;
        __half* o0 = Op + (size_t)m0g * LL;
        __half* o1 = o0 + (size_t)8 * LL;
#pragma unroll
        for (int nt = 0; nt < 3; nt++) {
            int col = nw + nt * 8 + 2 * tg;
            *(__half2*)&o0[col] = __floats2half2_rn(acc[mt][nt][0], acc[mt][nt][1]);
            *(__half2*)&o1[col] = __floats2half2_rn(acc[mt][nt][2], acc[mt][nt][3]);
        }
    }
}

// ---------------- final: out = gamma*(tH^T + tW) + residual (wide I/O) -------
// block: 32 h-rows x 96 w per (o,bc); grid (3, 2*B*C)
__global__ __launch_bounds__(256)
void final_kernel(const float* __restrict__ x, const float* __restrict__ y,
                  const float* __restrict__ gamma, float* __restrict__ out)
{
    __shared__ __align__(16) __half s[96 * 40];   // s[w][h_local], pad 40
    int z  = blockIdx.y;
    int o  = z >> 12;           // B*C = 4096
    int bc = z & 4095;
    int b  = bc >> 9;
    int c  = bc & 511;
    int h0 = blockIdx.x * 32;
    float g = gamma[0];
    const float* res = (o == 0 ? x : y) + (size_t)bc * HW;
    const __half* tH = g_tH[o];
    const __half* tW = g_tW[o];
    int t = threadIdx.x;

    // load tH slab: 96 w-rows x 32 h halves = 96 x 4 uint4 (pure copy)
    const __half* tHb = tH + (((size_t)b * LL) * Cc + c) * LL + h0;
    for (int idx = t; idx < 384; idx += 256) {
        int w = idx >> 2, c8 = (idx & 3) * 8;
        *(uint4*)&s[w * 40 + c8] = *(const uint4*)&tHb[(size_t)w * Cc * LL + c8];
    }
    __syncthreads();

    const __half* tWb = tW + (((size_t)b * LL + h0) * Cc + c) * LL;
    float* op = out + (size_t)o * BCHW + (size_t)bc * HW;
    // output: 32 h x 24 float4 chunks = 768
    for (int idx = t; idx < 768; idx += 256) {
        int h = idx / 24, c4 = (idx % 24) * 4;
        uint2 twu = *(const uint2*)&tWb[(size_t)h * Cc * LL + c4];
        __half2 tw0 = *(__half2*)&twu.x;
        __half2 tw1 = *(__half2*)&twu.y;
        float4 rs = *(const float4*)&res[(size_t)(h0 + h) * LL + c4];
        float4 ov;
        ov.x = g * (__half2float(s[(c4 + 0) * 40 + h]) + __low2float(tw0))  + rs.x;
        ov.y = g * (__half2float(s[(c4 + 1) * 40 + h]) + __high2float(tw0)) + rs.y;
        ov.z = g * (__half2float(s[(c4 + 2) * 40 + h]) + __low2float(tw1))  + rs.z;
        ov.w = g * (__half2float(s[(c4 + 3) * 40 + h]) + __high2float(tw1)) + rs.w;
        *(float4*)&op[(size_t)(h0 + h) * LL + c4] = ov;
    }
}

// ---------------------------------------------------------------------------
extern "C" void kernel_launch(void* const* d_in, const int* in_sizes, int n_in,
                              void* d_out, int out_size)
{
    const float* x     = (const float*)d_in[0];
    const float* y     = (const float*)d_in[1];
    const float* Wq    = (const float*)d_in[2];
    const float* bq    = (const float*)d_in[3];
    const float* Wk    = (const float*)d_in[4];
    const float* bk    = (const float*)d_in[5];
    const float* Wv    = (const float*)d_in[6];
    const float* bv    = (const float*)d_in[7];
    const float* gamma = (const float*)d_in[8];
    float* out = (float*)d_out;
    (void)in_sizes; (void)n_in; (void)out_size;

    __half *xh, *yh, *qk, *qkT, *v, *vT;
    cudaGetSymbolAddress((void**)&xh,  g_xh);
    cudaGetSymbolAddress((void**)&yh,  g_yh);
    cudaGetSymbolAddress((void**)&qk,  g_qk);
    cudaGetSymbolAddress((void**)&qkT, g_qkT);
    cudaGetSymbolAddress((void**)&v,   g_v);
    cudaGetSymbolAddress((void**)&vT,  g_vT);

    cudaFuncSetAttribute(proj_f16_kernel, cudaFuncAttributeMaxDynamicSharedMemorySize, PROJ_SMEM);

    // 0) convert inputs + stack weights to fp16
    f2h_kernel<<<dim3(BCHW / 2048, 2), 256>>>(x, y);
    weights_kernel<<<1280, 256>>>(Wq, bq, Wk, bk, Wv, bv);

    // 1) fused projections: single launch computes qk and v for both inputs
    proj_f16_kernel<<<dim3(72, 5, 16), 256, PROJ_SMEM>>>(xh, yh);

    // 2) transposes (half2 32x32 tiles)
    dim3 tb(16, 16);
    transpose16_kernel<<<dim3(3, 3, 2 * Bz * 128), tb>>>(qk, qkT);
    transpose16_kernel<<<dim3(3, 3, 2 * Bz * Cc),  tb>>>(v, vT);

    // 3) energies (4 variants in one launch)
    energy_kernel<<<dim3(Bz * LL, 4), 256>>>();

    // 4) joint softmax -> fp16 attention
    softmax_kernel<<<dim3(9216, 2), 256>>>();

    // 5) applies (4 variants in one launch)
    apply_f16_kernel<<<dim3(4, Bz * LL, 4), 256>>>();

    // 6) combine + residual
    final_kernel<<<dim3(3, 2 * Bz * Cc), 256>>>(x, y, gamma, out);
}

// round 13
// speedup vs baseline: 1.1283x; 1.0735x over previous
#include <cuda_runtime.h>
#include <cuda_fp16.h>
#include <math.h>
#include <stdint.h>

// Problem constants
#define Bz   8
#define Cc   512
#define CQq  64
#define LL   96           // H == W == 96
#define HW   9216         // 96*96
#define BCHW 37748736     // 8*512*9216
#define BQKHW 9437184     // 8*128*9216 (stacked q||k)
#define ELN  7077888      // 8*96*96*96

// ---------------- scratch (device globals; allocation-free rule) ------------
__device__ __half g_xh [BCHW];      // fp16 copies of inputs [B][C][H][W]
__device__ __half g_yh [BCHW];
__device__ __half g_qk [2][BQKHW];  // [B][128][H][W]: ch 0..63 = q, 64..127 = k
__device__ __half g_qkT[2][BQKHW];  // [B][128][W][H]
__device__ __half g_v  [2][BCHW];   // [B][C][H][W]
__device__ __half g_vT [2][BCHW];   // [B][C][W][H]
__device__ float  g_eH [2][ELN];    // energies [B][W][H][Hk] (fp32 logits)
__device__ float  g_eW [2][ELN];    // [B][H][W][Wk]
__device__ __half g_aH [2][ELN];    // softmaxed attention, fp16
__device__ __half g_aW [2][ELN];
__device__ __half g_tH [2][BCHW];   // applyH out  [B][W][C][H]
__device__ __half g_tW [2][BCHW];   // applyW out  [B][H][C][W]
__device__ __half g_Wall[640 * 512]; // fp16 stacked Wq||Wk||Wv
__device__ float  g_ball[640];

// ---------------- helpers ----------------------------------------------------
__device__ __forceinline__ uint32_t pack2(float lo, float hi)
{
    __half2 h = __floats2half2_rn(lo, hi);
    return *reinterpret_cast<uint32_t*>(&h);
}

__device__ __forceinline__ void mma_f16(float& c0, float& c1, float& c2, float& c3,
                                        uint32_t a0, uint32_t a1, uint32_t a2, uint32_t a3,
                                        uint32_t b0, uint32_t b1)
{
    asm volatile(
        "mma.sync.aligned.m16n8k16.row.col.f32.f16.f16.f32 "
        "{%0,%1,%2,%3}, {%4,%5,%6,%7}, {%8,%9}, {%0,%1,%2,%3};"
        : "+f"(c0), "+f"(c1), "+f"(c2), "+f"(c3)
        : "r"(a0), "r"(a1), "r"(a2), "r"(a3), "r"(b0), "r"(b1));
}

__device__ __forceinline__ void ldsm_x4(uint32_t& r0, uint32_t& r1, uint32_t& r2, uint32_t& r3,
                                        uint32_t addr)
{
    asm volatile("ldmatrix.sync.aligned.m8n8.x4.shared.b16 {%0,%1,%2,%3}, [%4];"
                 : "=r"(r0), "=r"(r1), "=r"(r2), "=r"(r3) : "r"(addr));
}
__device__ __forceinline__ void ldsm_x4_t(uint32_t& r0, uint32_t& r1, uint32_t& r2, uint32_t& r3,
                                          uint32_t addr)
{
    asm volatile("ldmatrix.sync.aligned.m8n8.x4.trans.shared.b16 {%0,%1,%2,%3}, [%4];"
                 : "=r"(r0), "=r"(r1), "=r"(r2), "=r"(r3) : "r"(addr));
}
__device__ __forceinline__ void ldsm_x2(uint32_t& r0, uint32_t& r1, uint32_t addr)
{
    asm volatile("ldmatrix.sync.aligned.m8n8.x2.shared.b16 {%0,%1}, [%2];"
                 : "=r"(r0), "=r"(r1) : "r"(addr));
}
__device__ __forceinline__ void ldsm_x2_t(uint32_t& r0, uint32_t& r1, uint32_t addr)
{
    asm volatile("ldmatrix.sync.aligned.m8n8.x2.trans.shared.b16 {%0,%1}, [%2];"
                 : "=r"(r0), "=r"(r1) : "r"(addr));
}
__device__ __forceinline__ uint32_t smem_u32(const void* p)
{
    return (uint32_t)__cvta_generic_to_shared(p);
}
__device__ __forceinline__ void cp16(uint32_t dst, const void* src)
{
    asm volatile("cp.async.cg.shared.global [%0], [%1], 16;" :: "r"(dst), "l"(src));
}
__device__ __forceinline__ void cp_commit() { asm volatile("cp.async.commit_group;"); }

// ---------------- fp32 -> fp16 convert (both inputs, one launch) --------------
__global__ void f2h_kernel(const float* __restrict__ x, const float* __restrict__ y)
{
    const float* src = blockIdx.y ? y : x;
    __half* dst = blockIdx.y ? g_yh : g_xh;
    int i = (blockIdx.x * blockDim.x + threadIdx.x) * 8;
    float4 a = *(const float4*)&src[i];
    float4 b = *(const float4*)&src[i + 4];
    uint4 u = make_uint4(pack2(a.x, a.y), pack2(a.z, a.w), pack2(b.x, b.y), pack2(b.z, b.w));
    *(uint4*)&dst[i] = u;
}

// ---------------- weights: stack Wq||Wk||Wv (fp16) + biases -------------------
__global__ void weights_kernel(const float* __restrict__ Wq, const float* __restrict__ bq,
                               const float* __restrict__ Wk, const float* __restrict__ bk,
                               const float* __restrict__ Wv, const float* __restrict__ bv)
{
    int t = blockIdx.x * blockDim.x + threadIdx.x;   // 0..327679
    int m = t >> 9, k = t & 511;
    float w;
    if (m < 64)       w = Wq[m * 512 + k];
    else if (m < 128) w = Wk[(m - 64) * 512 + k];
    else              w = Wv[(m - 128) * 512 + k];
    g_Wall[t] = __float2half(w);
    if (t < 640) {
        float bb;
        if (t < 64)       bb = bq[t];
        else if (t < 128) bb = bk[t - 64];
        else              bb = bv[t - 128];
        g_ball[t] = bb;
    }
}

// ---------------- fused projection GEMM (qk + v), k-tile 64, 3-stage ---------
#define A_STG 9216                  // halves per stage: 128 rows x stride 72
#define B_STG 8704                  // halves per stage: 64 rows x stride 136
#define STG_H (A_STG + B_STG)       // 17920 halves = 35840 B
#define PROJ_SMEM (3 * STG_H * 2)   // 107520 B
__global__ __launch_bounds__(256)
void proj_f16_kernel(const __half* __restrict__ xh, const __half* __restrict__ yh)
{
    extern __shared__ __align__(16) __half sm[];

    int inp = blockIdx.z >> 3;
    int b   = blockIdx.z & 7;
    int bm = blockIdx.y * 128;
    int bn = blockIdx.x * 128;
    int t  = threadIdx.x;
    int warp = t >> 5, lane = t & 31;
    int g = lane >> 2, tg = lane & 3;
    int mw = (warp >> 2) * 64;
    int nw = (warp & 3) * 32;

    const __half* in = inp ? yh : xh;
    const __half* inb = in + (size_t)b * Cc * HW;

    int aRow = (lane & 7) + ((lane >> 3) & 1) * 8;
    int aK8  = ((lane >> 4) & 1) * 8;
    int bRow = (lane & 7) + ((lane >> 3) & 1) * 8;

    float acc[4][4][4];
#pragma unroll
    for (int i = 0; i < 4; i++)
#pragma unroll
        for (int j = 0; j < 4; j++)
#pragma unroll
            for (int r = 0; r < 4; r++) acc[i][j][r] = 0.f;

    auto load_chunk = [&](int c, int s) {
        uint32_t aD = smem_u32(sm + s * STG_H);
        uint32_t bD = aD + A_STG * 2;
        int k0 = c * 64;
#pragma unroll
        for (int r = 0; r < 8; r++) {
            int idx = t + 256 * r;
            if (idx < 1024) {
                int row = idx >> 3, ch = idx & 7;
                cp16(aD + (uint32_t)((row * 72 + ch * 8) * 2),
                     &g_Wall[(size_t)(bm + row) * Cc + k0 + ch * 8]);
            } else {
                int j = idx - 1024;
                int row = j >> 4, ch = j & 15;
                cp16(bD + (uint32_t)((row * 136 + ch * 8) * 2),
                     &inb[(size_t)(k0 + row) * HW + bn + ch * 8]);
            }
        }
    };

    load_chunk(0, 0); cp_commit();
    load_chunk(1, 1); cp_commit();

    const int NK = Cc / 64;   // 8
    for (int i = 0; i < NK; i++) {
        asm volatile("cp.async.wait_group 1;" ::: "memory");
        __syncthreads();
        if (i + 2 < NK) load_chunk(i + 2, (i + 2) % 3);
        cp_commit();

        uint32_t aBase = smem_u32(sm + (i % 3) * STG_H);
        uint32_t bBase = aBase + A_STG * 2;
#pragma unroll
        for (int kk = 0; kk < 64; kk += 16) {
            uint32_t a[4][4], bb[4][2];
#pragma unroll
            for (int mt = 0; mt < 4; mt++) {
                uint32_t ad = aBase + (uint32_t)(((mw + mt * 16 + aRow) * 72 + kk + aK8) * 2);
                ldsm_x4(a[mt][0], a[mt][1], a[mt][2], a[mt][3], ad);
            }
#pragma unroll
            for (int nt = 0; nt < 4; nt++) {
                uint32_t bd = bBase + (uint32_t)(((kk + bRow) * 136 + nw + nt * 8) * 2);
                ldsm_x2_t(bb[nt][0], bb[nt][1], bd);
            }
#pragma unroll
            for (int mt = 0; mt < 4; mt++)
#pragma unroll
                for (int nt = 0; nt < 4; nt++)
                    mma_f16(acc[mt][nt][0], acc[mt][nt][1], acc[mt][nt][2], acc[mt][nt][3],
                            a[mt][0], a[mt][1], a[mt][2], a[mt][3],
                            bb[nt][0], bb[nt][1]);
        }
        __syncthreads();
    }

    __half* obase = (bm == 0)
        ? g_qk[inp] + (size_t)b * 128 * HW
        : g_v[inp]  + (size_t)b * Cc * HW + (size_t)(bm - 128) * HW;
#pragma unroll
    for (int mt = 0; mt < 4; mt++) {
        int mloc = mw + mt * 16 + g;
        float bi0 = g_ball[bm + mloc];
        float bi1 = g_ball[bm + mloc + 8];
        __half* op0 = obase + (size_t)mloc * HW + bn;
        __half* op1 = op0 + (size_t)8 * HW;
#pragma unroll
        for (int nt = 0; nt < 4; nt++) {
            int col = nw + nt * 8 + 2 * tg;
            *(__half2*)&op0[col] = __floats2half2_rn(acc[mt][nt][0] + bi0, acc[mt][nt][1] + bi0);
            *(__half2*)&op1[col] = __floats2half2_rn(acc[mt][nt][2] + bi1, acc[mt][nt][3] + bi1);
        }
    }
}

// ---------------- plane transpose (fp16, half2, qk+v merged) -----------------
__global__ void transpose16_kernel(const __half* __restrict__ qk, __half* __restrict__ qkT,
                                   const __half* __restrict__ v, __half* __restrict__ vT)
{
    __shared__ __half2 til[32][17];
    int n = blockIdx.z;
    const __half* in;
    __half* out;
    if (n < 2 * Bz * 128) { in = qk + (size_t)n * HW; out = qkT + (size_t)n * HW; }
    else { int m = n - 2 * Bz * 128; in = v + (size_t)m * HW; out = vT + (size_t)m * HW; }
    int h0 = blockIdx.y * 32, w0 = blockIdx.x * 32;
    int tx = threadIdx.x, ty = threadIdx.y;   // 16 x 16
#pragma unroll
    for (int r = 0; r < 32; r += 16)
        til[ty + r][tx] = *(const __half2*)&in[(size_t)(h0 + ty + r) * LL + w0 + 2 * tx];
    __syncthreads();
#pragma unroll
    for (int r = 0; r < 32; r += 16) {
        int w = ty + r;
        int k = w >> 1, ln = w & 1;
        __half2 A = til[2 * tx][k];
        __half2 B = til[2 * tx + 1][k];
        __half a = ln ? __high2half(A) : __low2half(A);
        __half b = ln ? __high2half(B) : __low2half(B);
        *(__half2*)&out[(size_t)(w0 + w) * LL + h0 + 2 * tx] = __halves2half2(a, b);
    }
}

// ---------------- energy (merged 4 variants) via fp16 MMA --------------------
__global__ __launch_bounds__(256)
void energy_kernel()
{
    __shared__ __align__(16) __half Qs[64 * 104];   // [c][i] stride 104
    __shared__ __align__(16) __half Ks[64 * 104];
    int cfg = blockIdx.y;
    int dir = cfg & 1;
    int isH = (cfg < 2);
    const __half* Q = isH ? g_qkT[dir]     : g_qk[dir];
    const __half* K = isH ? g_qkT[1 - dir] : g_qk[1 - dir];
    K += (size_t)64 * HW;   // keys are channels 64..127
    float* E = isH ? g_eH[dir] : g_eW[dir];
    int maskDiag = isH;

    int bl = blockIdx.x;
    int b = bl / LL, line = bl % LL;
    const size_t QKB = (size_t)128 * HW;
    const __half* Qp = Q + (size_t)b * QKB + (size_t)line * LL;
    const __half* Kp = K + (size_t)b * QKB + (size_t)line * LL;
    int t = threadIdx.x;
    int warp = t >> 5, lane = t & 31;
    int g = lane >> 2, tg = lane & 3;
    int mw = (warp >> 2) * 48;
    int nw = (warp & 3) * 24;

    for (int idx = t; idx < 64 * 12; idx += 256) {
        int c = idx / 12, j8 = (idx % 12) * 8;
        *(uint4*)&Qs[c * 104 + j8] = *(const uint4*)&Qp[(size_t)c * HW + j8];
        *(uint4*)&Ks[c * 104 + j8] = *(const uint4*)&Kp[(size_t)c * HW + j8];
    }
    __syncthreads();

    uint32_t qsB = smem_u32(Qs);
    uint32_t ksB = smem_u32(Ks);
    int aMat = lane >> 3;
    int aC = ((aMat >> 1) & 1) * 8 + (lane & 7);
    int aI = (aMat & 1) * 8;
    int bC = ((lane >> 3) & 1) * 8 + (lane & 7);

    float acc[3][3][4];
#pragma unroll
    for (int i = 0; i < 3; i++)
#pragma unroll
        for (int j = 0; j < 3; j++)
#pragma unroll
            for (int r = 0; r < 4; r++) acc[i][j][r] = 0.f;

#pragma unroll
    for (int kk = 0; kk < 64; kk += 16) {
        uint32_t a[3][4], bb[3][2];
#pragma unroll
        for (int mt = 0; mt < 3; mt++) {
            uint32_t ad = qsB + (uint32_t)(((kk + aC) * 104 + mw + mt * 16 + aI) * 2);
            ldsm_x4_t(a[mt][0], a[mt][1], a[mt][2], a[mt][3], ad);
        }
#pragma unroll
        for (int nt = 0; nt < 3; nt++) {
            uint32_t bd = ksB + (uint32_t)(((kk + bC) * 104 + nw + nt * 8) * 2);
            ldsm_x2_t(bb[nt][0], bb[nt][1], bd);
        }
#pragma unroll
        for (int mt = 0; mt < 3; mt++)
#pragma unroll
            for (int nt = 0; nt < 3; nt++)
                mma_f16(acc[mt][nt][0], acc[mt][nt][1], acc[mt][nt][2], acc[mt][nt][3],
                        a[mt][0], a[mt][1], a[mt][2], a[mt][3],
                        bb[nt][0], bb[nt][1]);
    }

    float* Eb = E + (size_t)bl * LL * LL;
#pragma unroll
    for (int mt = 0; mt < 3; mt++) {
        int i0 = mw + mt * 16 + g;
        int i1 = i0 + 8;
#pragma unroll
        for (int nt = 0; nt < 3; nt++) {
            int j0 = nw + nt * 8 + 2 * tg;
            float v0 = acc[mt][nt][0], v1 = acc[mt][nt][1];
            float v2 = acc[mt][nt][2], v3 = acc[mt][nt][3];
            if (maskDiag) {
                if (i0 == j0)     v0 = -1e30f;
                if (i0 == j0 + 1) v1 = -1e30f;
                if (i1 == j0)     v2 = -1e30f;
                if (i1 == j0 + 1) v3 = -1e30f;
            }
            *(float2*)&Eb[(size_t)i0 * LL + j0] = make_float2(v0, v1);
            *(float2*)&Eb[(size_t)i1 * LL + j0] = make_float2(v2, v3);
        }
    }
}

// ---------------- joint softmax; fp32 logits in, fp16 attention out ----------
__global__ void softmax_kernel()
{
    int dir  = blockIdx.y;
    int warp = (blockIdx.x * blockDim.x + threadIdx.x) >> 5;
    int lane = threadIdx.x & 31;
    int b  = warp / HW;
    int hw = warp % HW;
    int h = hw / LL, w = hw % LL;
    size_t offH = (((size_t)b * LL + w) * LL + h) * LL;
    size_t offW = (((size_t)b * LL + h) * LL + w) * LL;
    const float* rH = &g_eH[dir][offH];
    const float* rW = &g_eW[dir][offW];
    __half* oH = &g_aH[dir][offH];
    __half* oW = &g_aW[dir][offW];
    float v[6];
#pragma unroll
    for (int i = 0; i < 3; i++) v[i]     = rH[lane + 32 * i];
#pragma unroll
    for (int i = 0; i < 3; i++) v[3 + i] = rW[lane + 32 * i];
    float m = v[0];
#pragma unroll
    for (int i = 1; i < 6; i++) m = fmaxf(m, v[i]);
#pragma unroll
    for (int o = 16; o > 0; o >>= 1) m = fmaxf(m, __shfl_xor_sync(0xffffffffu, m, o));
    float s = 0.f;
#pragma unroll
    for (int i = 0; i < 6; i++) { v[i] = __expf(v[i] - m); s += v[i]; }
#pragma unroll
    for (int o = 16; o > 0; o >>= 1) s += __shfl_xor_sync(0xffffffffu, s, o);
    float inv = 1.f / s;
#pragma unroll
    for (int i = 0; i < 3; i++) oH[lane + 32 * i] = __float2half(v[i]     * inv);
#pragma unroll
    for (int i = 0; i < 3; i++) oW[lane + 32 * i] = __float2half(v[3 + i] * inv);
}

// ---------------- apply: all 512 channels per block, cp.async double-buffer --
// per (b,line,variant): O[c,i] = sum_k V[c,k] A[i,k], c in 4 slices of 128
#define APL_A (96 * 104)                       // halves
#define APL_V (128 * 104)                      // halves per V stage
#define APPLY_SMEM ((APL_A + 2 * APL_V) * 2)   // 73216 B
__global__ __launch_bounds__(256)
void apply_f16_kernel()
{
    extern __shared__ __align__(16) __half smA[];
    __half* As2 = smA;             // [i][k] stride 104
    __half* Vs0 = smA + APL_A;     // two stages of [c][k] stride 104

    int z = blockIdx.y;
    int half_ = z >> 1;
    int isW = z & 1;
    const __half* Vb = isW ? g_v[half_]  : g_vT[half_];
    const __half* Ab = isW ? g_aW[1 - half_] : g_aH[1 - half_];
    __half* Ob = isW ? g_tW[half_] : g_tH[half_];

    int bl  = blockIdx.x;
    int b = bl / LL, line = bl % LL;
    int t = threadIdx.x;
    int warp = t >> 5, lane = t & 31;
    int g = lane >> 2, tg = lane & 3;
    int mw = (warp >> 2) * 64;
    int nw = (warp & 3) * 24;

    uint32_t asB  = smem_u32(As2);
    uint32_t vs0B = smem_u32(Vs0);

    // A tile via cp.async (group 0, together with V0)
    const __half* Ap = Ab + (size_t)bl * LL * LL;
    for (int idx = t; idx < 96 * 12; idx += 256) {
        int i = idx / 12, j8 = (idx % 12) * 8;
        cp16(asB + (uint32_t)((i * 104 + j8) * 2), &Ap[i * LL + j8]);
    }
    auto loadV = [&](int ct, int s) {
        const __half* Vp = Vb + (((size_t)(b * Cc + ct * 128)) * LL + line) * LL;
        uint32_t dst = vs0B + (uint32_t)(s * APL_V * 2);
#pragma unroll
        for (int r = 0; r < 6; r++) {
            int idx = t + 256 * r;
            int c = idx / 12, j8 = (idx % 12) * 8;
            cp16(dst + (uint32_t)((c * 104 + j8) * 2), &Vp[(size_t)c * HW + j8]);
        }
    };
    loadV(0, 0);
    cp_commit();   // G0 = A + V0

    int aRow = (lane & 7) + ((lane >> 3) & 1) * 8;
    int aK8  = ((lane >> 4) & 1) * 8;
    int bRowN = lane & 7;
    int bK8  = ((lane >> 3) & 1) * 8;

    for (int ct = 0; ct < 4; ct++) {
        if (ct < 3) loadV(ct + 1, (ct + 1) & 1);
        cp_commit();
        asm volatile("cp.async.wait_group 1;" ::: "memory");
        __syncthreads();

        uint32_t vsB = vs0B + (uint32_t)((ct & 1) * APL_V * 2);

        float acc[4][3][4];
#pragma unroll
        for (int i = 0; i < 4; i++)
#pragma unroll
            for (int j = 0; j < 3; j++)
#pragma unroll
                for (int r = 0; r < 4; r++) acc[i][j][r] = 0.f;

#pragma unroll
        for (int kk = 0; kk < 96; kk += 16) {
            uint32_t a[4][4], bb[3][2];
#pragma unroll
            for (int mt = 0; mt < 4; mt++) {
                uint32_t ad = vsB + (uint32_t)(((mw + mt * 16 + aRow) * 104 + kk + aK8) * 2);
                ldsm_x4(a[mt][0], a[mt][1], a[mt][2], a[mt][3], ad);
            }
#pragma unroll
            for (int nt = 0; nt < 3; nt++) {
                uint32_t bd = asB + (uint32_t)(((nw + nt * 8 + bRowN) * 104 + kk + bK8) * 2);
                ldsm_x2(bb[nt][0], bb[nt][1], bd);
            }
#pragma unroll
            for (int mt = 0; mt < 4; mt++)
#pragma unroll
                for (int nt = 0; nt < 3; nt++)
                    mma_f16(acc[mt][nt][0], acc[mt][nt][1], acc[mt][nt][2], acc[mt][nt][3],
                            a[mt][0], a[mt][1], a[mt][2], a[mt][3],
                            bb[nt][0], bb[nt][1]);
        }

        __half* Op = Ob + ((size_t)bl * Cc + ct * 128) * LL;
#pragma unroll
        for (int mt = 0; mt < 4; mt++) {
            int m0g = mw + mt * 16 + g;
            __half* o0 = Op + (size_t)m0g * LL;
            __half* o1 = o0 + (size_t)8 * LL;
#pragma unroll
            for (int nt = 0; nt < 3; nt++) {
                int col = nw + nt * 8 + 2 * tg;
                *(__half2*)&o0[col] = __floats2half2_rn(acc[mt][nt][0], acc[mt][nt][1]);
                *(__half2*)&o1[col] = __floats2half2_rn(acc[mt][nt][2], acc[mt][nt][3]);
            }
        }
        __syncthreads();   // protect stage (ct&1) before next prefetch overwrites
    }
}

// ---------------- final: out = gamma*(tH^T + tW) + residual (wide I/O) -------
__global__ __launch_bounds__(256)
void final_kernel(const float* __restrict__ x, const float* __restrict__ y,
                  const float* __restrict__ gamma, float* __restrict__ out)
{
    __shared__ __align__(16) __half s[96 * 40];   // s[w][h_local], pad 40
    int z  = blockIdx.y;
    int o  = z >> 12;           // B*C = 4096
    int bc = z & 4095;
    int b  = bc >> 9;
    int c  = bc & 511;
    int h0 = blockIdx.x * 32;
    float g = gamma[0];
    const float* res = (o == 0 ? x : y) + (size_t)bc * HW;
    const __half* tH = g_tH[o];
    const __half* tW = g_tW[o];
    int t = threadIdx.x;

    const __half* tHb = tH + (((size_t)b * LL) * Cc + c) * LL + h0;
    for (int idx = t; idx < 384; idx += 256) {
        int w = idx >> 2, c8 = (idx & 3) * 8;
        *(uint4*)&s[w * 40 + c8] = *(const uint4*)&tHb[(size_t)w * Cc * LL + c8];
    }
    __syncthreads();

    const __half* tWb = tW + (((size_t)b * LL + h0) * Cc + c) * LL;
    float* op = out + (size_t)o * BCHW + (size_t)bc * HW;
    for (int idx = t; idx < 768; idx += 256) {
        int h = idx / 24, c4 = (idx % 24) * 4;
        uint2 twu = *(const uint2*)&tWb[(size_t)h * Cc * LL + c4];
        __half2 tw0 = *(__half2*)&twu.x;
        __half2 tw1 = *(__half2*)&twu.y;
        float4 rs = *(const float4*)&res[(size_t)(h0 + h) * LL + c4];
        float4 ov;
        ov.x = g * (__half2float(s[(c4 + 0) * 40 + h]) + __low2float(tw0))  + rs.x;
        ov.y = g * (__half2float(s[(c4 + 1) * 40 + h]) + __high2float(tw0)) + rs.y;
        ov.z = g * (__half2float(s[(c4 + 2) * 40 + h]) + __low2float(tw1))  + rs.z;
        ov.w = g * (__half2float(s[(c4 + 3) * 40 + h]) + __high2float(tw1)) + rs.w;
        *(float4*)&op[(size_t)(h0 + h) * LL + c4] = ov;
    }
}

// ---------------------------------------------------------------------------
extern "C" void kernel_launch(void* const* d_in, const int* in_sizes, int n_in,
                              void* d_out, int out_size)
{
    const float* x     = (const float*)d_in[0];
    const float* y     = (const float*)d_in[1];
    const float* Wq    = (const float*)d_in[2];
    const float* bq    = (const float*)d_in[3];
    const float* Wk    = (const float*)d_in[4];
    const float* bk    = (const float*)d_in[5];
    const float* Wv    = (const float*)d_in[6];
    const float* bv    = (const float*)d_in[7];
    const float* gamma = (const float*)d_in[8];
    float* out = (float*)d_out;
    (void)in_sizes; (void)n_in; (void)out_size;

    __half *xh, *yh, *qk, *qkT, *v, *vT;
    cudaGetSymbolAddress((void**)&xh,  g_xh);
    cudaGetSymbolAddress((void**)&yh,  g_yh);
    cudaGetSymbolAddress((void**)&qk,  g_qk);
    cudaGetSymbolAddress((void**)&qkT, g_qkT);
    cudaGetSymbolAddress((void**)&v,   g_v);
    cudaGetSymbolAddress((void**)&vT,  g_vT);

    cudaFuncSetAttribute(proj_f16_kernel,  cudaFuncAttributeMaxDynamicSharedMemorySize, PROJ_SMEM);
    cudaFuncSetAttribute(apply_f16_kernel, cudaFuncAttributeMaxDynamicSharedMemorySize, APPLY_SMEM);

    // 0) convert inputs + stack weights to fp16
    f2h_kernel<<<dim3(BCHW / 2048, 2), 256>>>(x, y);
    weights_kernel<<<1280, 256>>>(Wq, bq, Wk, bk, Wv, bv);

    // 1) fused projections: single launch computes qk and v for both inputs
    proj_f16_kernel<<<dim3(72, 5, 16), 256, PROJ_SMEM>>>(xh, yh);

    // 2) transposes (qk + v in one launch)
    dim3 tb(16, 16);
    transpose16_kernel<<<dim3(3, 3, 2 * Bz * 128 + 2 * Bz * Cc), tb>>>(qk, qkT, v, vT);

    // 3) energies (4 variants in one launch)
    energy_kernel<<<dim3(Bz * LL, 4), 256>>>();

    // 4) joint softmax -> fp16 attention
    softmax_kernel<<<dim3(9216, 2), 256>>>();

    // 5) applies (4 variants, all channels per block, pipelined)
    apply_f16_kernel<<<dim3(Bz * LL, 4), 256, APPLY_SMEM>>>();

    // 6) combine + residual
    final_kernel<<<dim3(3, 2 * Bz * Cc), 256>>>(x, y, gamma, out);
}

// round 14
// speedup vs baseline: 1.1376x; 1.0083x over previous
#include <cuda_runtime.h>
#include <cuda_fp16.h>
#include <math.h>
#include <stdint.h>

// Problem constants
#define Bz   8
#define Cc   512
#define CQq  64
#define LL   96           // H == W == 96
#define HW   9216         // 96*96
#define BCHW 37748736     // 8*512*9216
#define BQKHW 9437184     // 8*128*9216 (stacked q||k)
#define ELN  7077888      // 8*96*96*96

// ---------------- scratch (device globals; allocation-free rule) ------------
__device__ __half g_xh [BCHW];      // fp16 copies of inputs [B][C][H][W]
__device__ __half g_yh [BCHW];
__device__ __half g_qk [2][BQKHW];  // [B][128][H][W]: ch 0..63 = q, 64..127 = k
__device__ __half g_qkT[2][BQKHW];  // [B][128][W][H]
__device__ __half g_v  [2][BCHW];   // [B][C][H][W]
__device__ __half g_vT [2][BCHW];   // [B][C][W][H]
__device__ float  g_eH [2][ELN];    // energies [B][W][H][Hk] (fp32 logits)
__device__ float  g_eW [2][ELN];    // [B][H][W][Wk]
__device__ __half g_aH [2][ELN];    // softmaxed attention, fp16
__device__ __half g_aW [2][ELN];
__device__ __half g_tH [2][BCHW];   // applyH out  [B][W][C][H]
__device__ __half g_tW [2][BCHW];   // applyW out  [B][H][C][W]
__device__ __half g_Wall[640 * 512]; // fp16 stacked Wq||Wk||Wv
__device__ float  g_ball[640];

// ---------------- helpers ----------------------------------------------------
__device__ __forceinline__ uint32_t pack2(float lo, float hi)
{
    __half2 h = __floats2half2_rn(lo, hi);
    return *reinterpret_cast<uint32_t*>(&h);
}

__device__ __forceinline__ void mma_f16(float& c0, float& c1, float& c2, float& c3,
                                        uint32_t a0, uint32_t a1, uint32_t a2, uint32_t a3,
                                        uint32_t b0, uint32_t b1)
{
    asm volatile(
        "mma.sync.aligned.m16n8k16.row.col.f32.f16.f16.f32 "
        "{%0,%1,%2,%3}, {%4,%5,%6,%7}, {%8,%9}, {%0,%1,%2,%3};"
        : "+f"(c0), "+f"(c1), "+f"(c2), "+f"(c3)
        : "r"(a0), "r"(a1), "r"(a2), "r"(a3), "r"(b0), "r"(b1));
}

__device__ __forceinline__ void ldsm_x4(uint32_t& r0, uint32_t& r1, uint32_t& r2, uint32_t& r3,
                                        uint32_t addr)
{
    asm volatile("ldmatrix.sync.aligned.m8n8.x4.shared.b16 {%0,%1,%2,%3}, [%4];"
                 : "=r"(r0), "=r"(r1), "=r"(r2), "=r"(r3) : "r"(addr));
}
__device__ __forceinline__ void ldsm_x4_t(uint32_t& r0, uint32_t& r1, uint32_t& r2, uint32_t& r3,
                                          uint32_t addr)
{
    asm volatile("ldmatrix.sync.aligned.m8n8.x4.trans.shared.b16 {%0,%1,%2,%3}, [%4];"
                 : "=r"(r0), "=r"(r1), "=r"(r2), "=r"(r3) : "r"(addr));
}
__device__ __forceinline__ void ldsm_x2(uint32_t& r0, uint32_t& r1, uint32_t addr)
{
    asm volatile("ldmatrix.sync.aligned.m8n8.x2.shared.b16 {%0,%1}, [%2];"
                 : "=r"(r0), "=r"(r1) : "r"(addr));
}
__device__ __forceinline__ void ldsm_x2_t(uint32_t& r0, uint32_t& r1, uint32_t addr)
{
    asm volatile("ldmatrix.sync.aligned.m8n8.x2.trans.shared.b16 {%0,%1}, [%2];"
                 : "=r"(r0), "=r"(r1) : "r"(addr));
}
__device__ __forceinline__ uint32_t smem_u32(const void* p)
{
    return (uint32_t)__cvta_generic_to_shared(p);
}
__device__ __forceinline__ void cp16(uint32_t dst, const void* src)
{
    asm volatile("cp.async.cg.shared.global [%0], [%1], 16;" :: "r"(dst), "l"(src));
}
__device__ __forceinline__ void cp_commit() { asm volatile("cp.async.commit_group;"); }

// ---------------- fp32 -> fp16 convert (both inputs, one launch) --------------
__global__ void f2h_kernel(const float* __restrict__ x, const float* __restrict__ y)
{
    const float* src = blockIdx.y ? y : x;
    __half* dst = blockIdx.y ? g_yh : g_xh;
    int i = (blockIdx.x * blockDim.x + threadIdx.x) * 8;
    float4 a = *(const float4*)&src[i];
    float4 b = *(const float4*)&src[i + 4];
    uint4 u = make_uint4(pack2(a.x, a.y), pack2(a.z, a.w), pack2(b.x, b.y), pack2(b.z, b.w));
    *(uint4*)&dst[i] = u;
}

// ---------------- weights: stack Wq||Wk||Wv (fp16) + biases -------------------
__global__ void weights_kernel(const float* __restrict__ Wq, const float* __restrict__ bq,
                               const float* __restrict__ Wk, const float* __restrict__ bk,
                               const float* __restrict__ Wv, const float* __restrict__ bv)
{
    int t = blockIdx.x * blockDim.x + threadIdx.x;   // 0..327679
    int m = t >> 9, k = t & 511;
    float w;
    if (m < 64)       w = Wq[m * 512 + k];
    else if (m < 128) w = Wk[(m - 64) * 512 + k];
    else              w = Wv[(m - 128) * 512 + k];
    g_Wall[t] = __float2half(w);
    if (t < 640) {
        float bb;
        if (t < 64)       bb = bq[t];
        else if (t < 128) bb = bk[t - 64];
        else              bb = bv[t - 128];
        g_ball[t] = bb;
    }
}

// ---------------- fused projection GEMM (qk + v), k-tile 64, 3-stage ---------
#define A_STG 9216                  // halves per stage: 128 rows x stride 72
#define B_STG 8704                  // halves per stage: 64 rows x stride 136
#define STG_H (A_STG + B_STG)       // 17920 halves = 35840 B
#define PROJ_SMEM (3 * STG_H * 2)   // 107520 B
__global__ __launch_bounds__(256)
void proj_f16_kernel(const __half* __restrict__ xh, const __half* __restrict__ yh)
{
    extern __shared__ __align__(16) __half sm[];

    int inp = blockIdx.z >> 3;
    int b   = blockIdx.z & 7;
    int bm = blockIdx.y * 128;
    int bn = blockIdx.x * 128;
    int t  = threadIdx.x;
    int warp = t >> 5, lane = t & 31;
    int g = lane >> 2, tg = lane & 3;
    int mw = (warp >> 2) * 64;
    int nw = (warp & 3) * 32;

    const __half* in = inp ? yh : xh;
    const __half* inb = in + (size_t)b * Cc * HW;

    int aRow = (lane & 7) + ((lane >> 3) & 1) * 8;
    int aK8  = ((lane >> 4) & 1) * 8;
    int bRow = (lane & 7) + ((lane >> 3) & 1) * 8;

    float acc[4][4][4];
#pragma unroll
    for (int i = 0; i < 4; i++)
#pragma unroll
        for (int j = 0; j < 4; j++)
#pragma unroll
            for (int r = 0; r < 4; r++) acc[i][j][r] = 0.f;

    auto load_chunk = [&](int c, int s) {
        uint32_t aD = smem_u32(sm + s * STG_H);
        uint32_t bD = aD + A_STG * 2;
        int k0 = c * 64;
#pragma unroll
        for (int r = 0; r < 8; r++) {
            int idx = t + 256 * r;
            if (idx < 1024) {
                int row = idx >> 3, ch = idx & 7;
                cp16(aD + (uint32_t)((row * 72 + ch * 8) * 2),
                     &g_Wall[(size_t)(bm + row) * Cc + k0 + ch * 8]);
            } else {
                int j = idx - 1024;
                int row = j >> 4, ch = j & 15;
                cp16(bD + (uint32_t)((row * 136 + ch * 8) * 2),
                     &inb[(size_t)(k0 + row) * HW + bn + ch * 8]);
            }
        }
    };

    load_chunk(0, 0); cp_commit();
    load_chunk(1, 1); cp_commit();

    const int NK = Cc / 64;   // 8
    for (int i = 0; i < NK; i++) {
        asm volatile("cp.async.wait_group 1;" ::: "memory");
        __syncthreads();
        if (i + 2 < NK) load_chunk(i + 2, (i + 2) % 3);
        cp_commit();

        uint32_t aBase = smem_u32(sm + (i % 3) * STG_H);
        uint32_t bBase = aBase + A_STG * 2;
#pragma unroll
        for (int kk = 0; kk < 64; kk += 16) {
            uint32_t a[4][4], bb[4][2];
#pragma unroll
            for (int mt = 0; mt < 4; mt++) {
                uint32_t ad = aBase + (uint32_t)(((mw + mt * 16 + aRow) * 72 + kk + aK8) * 2);
                ldsm_x4(a[mt][0], a[mt][1], a[mt][2], a[mt][3], ad);
            }
#pragma unroll
            for (int nt = 0; nt < 4; nt++) {
                uint32_t bd = bBase + (uint32_t)(((kk + bRow) * 136 + nw + nt * 8) * 2);
                ldsm_x2_t(bb[nt][0], bb[nt][1], bd);
            }
#pragma unroll
            for (int mt = 0; mt < 4; mt++)
#pragma unroll
                for (int nt = 0; nt < 4; nt++)
                    mma_f16(acc[mt][nt][0], acc[mt][nt][1], acc[mt][nt][2], acc[mt][nt][3],
                            a[mt][0], a[mt][1], a[mt][2], a[mt][3],
                            bb[nt][0], bb[nt][1]);
        }
        __syncthreads();
    }

    __half* obase = (bm == 0)
        ? g_qk[inp] + (size_t)b * 128 * HW
        : g_v[inp]  + (size_t)b * Cc * HW + (size_t)(bm - 128) * HW;
#pragma unroll
    for (int mt = 0; mt < 4; mt++) {
        int mloc = mw + mt * 16 + g;
        float bi0 = g_ball[bm + mloc];
        float bi1 = g_ball[bm + mloc + 8];
        __half* op0 = obase + (size_t)mloc * HW + bn;
        __half* op1 = op0 + (size_t)8 * HW;
#pragma unroll
        for (int nt = 0; nt < 4; nt++) {
            int col = nw + nt * 8 + 2 * tg;
            *(__half2*)&op0[col] = __floats2half2_rn(acc[mt][nt][0] + bi0, acc[mt][nt][1] + bi0);
            *(__half2*)&op1[col] = __floats2half2_rn(acc[mt][nt][2] + bi1, acc[mt][nt][3] + bi1);
        }
    }
}

// ---------------- plane transpose (fp16, half2, qk+v merged) -----------------
__global__ void transpose16_kernel(const __half* __restrict__ qk, __half* __restrict__ qkT,
                                   const __half* __restrict__ v, __half* __restrict__ vT)
{
    __shared__ __half2 til[32][17];
    int n = blockIdx.z;
    const __half* in;
    __half* out;
    if (n < 2 * Bz * 128) { in = qk + (size_t)n * HW; out = qkT + (size_t)n * HW; }
    else { int m = n - 2 * Bz * 128; in = v + (size_t)m * HW; out = vT + (size_t)m * HW; }
    int h0 = blockIdx.y * 32, w0 = blockIdx.x * 32;
    int tx = threadIdx.x, ty = threadIdx.y;   // 16 x 16
#pragma unroll
    for (int r = 0; r < 32; r += 16)
        til[ty + r][tx] = *(const __half2*)&in[(size_t)(h0 + ty + r) * LL + w0 + 2 * tx];
    __syncthreads();
#pragma unroll
    for (int r = 0; r < 32; r += 16) {
        int w = ty + r;
        int k = w >> 1, ln = w & 1;
        __half2 A = til[2 * tx][k];
        __half2 B = til[2 * tx + 1][k];
        __half a = ln ? __high2half(A) : __low2half(A);
        __half b = ln ? __high2half(B) : __low2half(B);
        *(__half2*)&out[(size_t)(w0 + w) * LL + h0 + 2 * tx] = __halves2half2(a, b);
    }
}

// ---------------- energy (merged 4 variants) via fp16 MMA --------------------
__global__ __launch_bounds__(256)
void energy_kernel()
{
    __shared__ __align__(16) __half Qs[64 * 104];   // [c][i] stride 104
    __shared__ __align__(16) __half Ks[64 * 104];
    int cfg = blockIdx.y;
    int dir = cfg & 1;
    int isH = (cfg < 2);
    const __half* Q = isH ? g_qkT[dir]     : g_qk[dir];
    const __half* K = isH ? g_qkT[1 - dir] : g_qk[1 - dir];
    K += (size_t)64 * HW;   // keys are channels 64..127
    float* E = isH ? g_eH[dir] : g_eW[dir];
    int maskDiag = isH;

    int bl = blockIdx.x;
    int b = bl / LL, line = bl % LL;
    const size_t QKB = (size_t)128 * HW;
    const __half* Qp = Q + (size_t)b * QKB + (size_t)line * LL;
    const __half* Kp = K + (size_t)b * QKB + (size_t)line * LL;
    int t = threadIdx.x;
    int warp = t >> 5, lane = t & 31;
    int g = lane >> 2, tg = lane & 3;
    int mw = (warp >> 2) * 48;
    int nw = (warp & 3) * 24;

    for (int idx = t; idx < 64 * 12; idx += 256) {
        int c = idx / 12, j8 = (idx % 12) * 8;
        *(uint4*)&Qs[c * 104 + j8] = *(const uint4*)&Qp[(size_t)c * HW + j8];
        *(uint4*)&Ks[c * 104 + j8] = *(const uint4*)&Kp[(size_t)c * HW + j8];
    }
    __syncthreads();

    uint32_t qsB = smem_u32(Qs);
    uint32_t ksB = smem_u32(Ks);
    int aMat = lane >> 3;
    int aC = ((aMat >> 1) & 1) * 8 + (lane & 7);
    int aI = (aMat & 1) * 8;
    int bC = ((lane >> 3) & 1) * 8 + (lane & 7);

    float acc[3][3][4];
#pragma unroll
    for (int i = 0; i < 3; i++)
#pragma unroll
        for (int j = 0; j < 3; j++)
#pragma unroll
            for (int r = 0; r < 4; r++) acc[i][j][r] = 0.f;

#pragma unroll
    for (int kk = 0; kk < 64; kk += 16) {
        uint32_t a[3][4], bb[3][2];
#pragma unroll
        for (int mt = 0; mt < 3; mt++) {
            uint32_t ad = qsB + (uint32_t)(((kk + aC) * 104 + mw + mt * 16 + aI) * 2);
            ldsm_x4_t(a[mt][0], a[mt][1], a[mt][2], a[mt][3], ad);
        }
#pragma unroll
        for (int nt = 0; nt < 3; nt++) {
            uint32_t bd = ksB + (uint32_t)(((kk + bC) * 104 + nw + nt * 8) * 2);
            ldsm_x2_t(bb[nt][0], bb[nt][1], bd);
        }
#pragma unroll
        for (int mt = 0; mt < 3; mt++)
#pragma unroll
            for (int nt = 0; nt < 3; nt++)
                mma_f16(acc[mt][nt][0], acc[mt][nt][1], acc[mt][nt][2], acc[mt][nt][3],
                        a[mt][0], a[mt][1], a[mt][2], a[mt][3],
                        bb[nt][0], bb[nt][1]);
    }

    float* Eb = E + (size_t)bl * LL * LL;
#pragma unroll
    for (int mt = 0; mt < 3; mt++) {
        int i0 = mw + mt * 16 + g;
        int i1 = i0 + 8;
#pragma unroll
        for (int nt = 0; nt < 3; nt++) {
            int j0 = nw + nt * 8 + 2 * tg;
            float v0 = acc[mt][nt][0], v1 = acc[mt][nt][1];
            float v2 = acc[mt][nt][2], v3 = acc[mt][nt][3];
            if (maskDiag) {
                if (i0 == j0)     v0 = -1e30f;
                if (i0 == j0 + 1) v1 = -1e30f;
                if (i1 == j0)     v2 = -1e30f;
                if (i1 == j0 + 1) v3 = -1e30f;
            }
            *(float2*)&Eb[(size_t)i0 * LL + j0] = make_float2(v0, v1);
            *(float2*)&Eb[(size_t)i1 * LL + j0] = make_float2(v2, v3);
        }
    }
}

// ---------------- joint softmax; float2 logit loads, half2 att stores --------
// lane l handles elements 2l..2l+1 (all lanes) and 64+2l..64+2l+1 (lanes<16)
__global__ void softmax_kernel()
{
    int dir  = blockIdx.y;
    int warp = (blockIdx.x * blockDim.x + threadIdx.x) >> 5;
    int lane = threadIdx.x & 31;
    int b  = warp / HW;
    int hw = warp % HW;
    int h = hw / LL, w = hw % LL;
    size_t offH = (((size_t)b * LL + w) * LL + h) * LL;
    size_t offW = (((size_t)b * LL + h) * LL + w) * LL;
    const float* rH = &g_eH[dir][offH];
    const float* rW = &g_eW[dir][offW];
    __half* oH = &g_aH[dir][offH];
    __half* oW = &g_aW[dir][offW];

    bool full = (lane < 16);
    float2 vH0 = *(const float2*)&rH[2 * lane];
    float2 vW0 = *(const float2*)&rW[2 * lane];
    float2 vH1 = full ? *(const float2*)&rH[64 + 2 * lane] : make_float2(-1e30f, -1e30f);
    float2 vW1 = full ? *(const float2*)&rW[64 + 2 * lane] : make_float2(-1e30f, -1e30f);

    float m = fmaxf(fmaxf(fmaxf(vH0.x, vH0.y), fmaxf(vW0.x, vW0.y)),
                    fmaxf(fmaxf(vH1.x, vH1.y), fmaxf(vW1.x, vW1.y)));
#pragma unroll
    for (int o = 16; o > 0; o >>= 1) m = fmaxf(m, __shfl_xor_sync(0xffffffffu, m, o));

    vH0.x = __expf(vH0.x - m); vH0.y = __expf(vH0.y - m);
    vW0.x = __expf(vW0.x - m); vW0.y = __expf(vW0.y - m);
    float s = vH0.x + vH0.y + vW0.x + vW0.y;
    if (full) {
        vH1.x = __expf(vH1.x - m); vH1.y = __expf(vH1.y - m);
        vW1.x = __expf(vW1.x - m); vW1.y = __expf(vW1.y - m);
        s += vH1.x + vH1.y + vW1.x + vW1.y;
    }
#pragma unroll
    for (int o = 16; o > 0; o >>= 1) s += __shfl_xor_sync(0xffffffffu, s, o);
    float inv = 1.f / s;

    *(__half2*)&oH[2 * lane] = __floats2half2_rn(vH0.x * inv, vH0.y * inv);
    *(__half2*)&oW[2 * lane] = __floats2half2_rn(vW0.x * inv, vW0.y * inv);
    if (full) {
        *(__half2*)&oH[64 + 2 * lane] = __floats2half2_rn(vH1.x * inv, vH1.y * inv);
        *(__half2*)&oW[64 + 2 * lane] = __floats2half2_rn(vW1.x * inv, vW1.y * inv);
    }
}

// ---------------- apply: all 512 channels per block, cp.async double-buffer --
#define APL_A (96 * 104)                       // halves
#define APL_V (128 * 104)                      // halves per V stage
#define APPLY_SMEM ((APL_A + 2 * APL_V) * 2)   // 73216 B
__global__ __launch_bounds__(256)
void apply_f16_kernel()
{
    extern __shared__ __align__(16) __half smA[];
    __half* As2 = smA;             // [i][k] stride 104
    __half* Vs0 = smA + APL_A;     // two stages of [c][k] stride 104

    int z = blockIdx.y;
    int half_ = z >> 1;
    int isW = z & 1;
    const __half* Vb = isW ? g_v[half_]  : g_vT[half_];
    const __half* Ab = isW ? g_aW[1 - half_] : g_aH[1 - half_];
    __half* Ob = isW ? g_tW[half_] : g_tH[half_];

    int bl  = blockIdx.x;
    int b = bl / LL, line = bl % LL;
    int t = threadIdx.x;
    int warp = t >> 5, lane = t & 31;
    int g = lane >> 2, tg = lane & 3;
    int mw = (warp >> 2) * 64;
    int nw = (warp & 3) * 24;

    uint32_t asB  = smem_u32(As2);
    uint32_t vs0B = smem_u32(Vs0);

    const __half* Ap = Ab + (size_t)bl * LL * LL;
    for (int idx = t; idx < 96 * 12; idx += 256) {
        int i = idx / 12, j8 = (idx % 12) * 8;
        cp16(asB + (uint32_t)((i * 104 + j8) * 2), &Ap[i * LL + j8]);
    }
    auto loadV = [&](int ct, int s) {
        const __half* Vp = Vb + (((size_t)(b * Cc + ct * 128)) * LL + line) * LL;
        uint32_t dst = vs0B + (uint32_t)(s * APL_V * 2);
#pragma unroll
        for (int r = 0; r < 6; r++) {
            int idx = t + 256 * r;
            int c = idx / 12, j8 = (idx % 12) * 8;
            cp16(dst + (uint32_t)((c * 104 + j8) * 2), &Vp[(size_t)c * HW + j8]);
        }
    };
    loadV(0, 0);
    cp_commit();   // G0 = A + V0

    int aRow = (lane & 7) + ((lane >> 3) & 1) * 8;
    int aK8  = ((lane >> 4) & 1) * 8;
    int bRowN = lane & 7;
    int bK8  = ((lane >> 3) & 1) * 8;

    for (int ct = 0; ct < 4; ct++) {
        if (ct < 3) loadV(ct + 1, (ct + 1) & 1);
        cp_commit();
        asm volatile("cp.async.wait_group 1;" ::: "memory");
        __syncthreads();

        uint32_t vsB = vs0B + (uint32_t)((ct & 1) * APL_V * 2);

        float acc[4][3][4];
#pragma unroll
        for (int i = 0; i < 4; i++)
#pragma unroll
            for (int j = 0; j < 3; j++)
#pragma unroll
                for (int r = 0; r < 4; r++) acc[i][j][r] = 0.f;

#pragma unroll
        for (int kk = 0; kk < 96; kk += 16) {
            uint32_t a[4][4], bb[3][2];
#pragma unroll
            for (int mt = 0; mt < 4; mt++) {
                uint32_t ad = vsB + (uint32_t)(((mw + mt * 16 + aRow) * 104 + kk + aK8) * 2);
                ldsm_x4(a[mt][0], a[mt][1], a[mt][2], a[mt][3], ad);
            }
#pragma unroll
            for (int nt = 0; nt < 3; nt++) {
                uint32_t bd = asB + (uint32_t)(((nw + nt * 8 + bRowN) * 104 + kk + bK8) * 2);
                ldsm_x2(bb[nt][0], bb[nt][1], bd);
            }
#pragma unroll
            for (int mt = 0; mt < 4; mt++)
#pragma unroll
                for (int nt = 0; nt < 3; nt++)
                    mma_f16(acc[mt][nt][0], acc[mt][nt][1], acc[mt][nt][2], acc[mt][nt][3],
                            a[mt][0], a[mt][1], a[mt][2], a[mt][3],
                            bb[nt][0], bb[nt][1]);
        }

        __half* Op = Ob + ((size_t)bl * Cc + ct * 128) * LL;
#pragma unroll
        for (int mt = 0; mt < 4; mt++) {
            int m0g = mw + mt * 16 + g;
            __half* o0 = Op + (size_t)m0g * LL;
            __half* o1 = o0 + (size_t)8 * LL;
#pragma unroll
            for (int nt = 0; nt < 3; nt++) {
                int col = nw + nt * 8 + 2 * tg;
                *(__half2*)&o0[col] = __floats2half2_rn(acc[mt][nt][0], acc[mt][nt][1]);
                *(__half2*)&o1[col] = __floats2half2_rn(acc[mt][nt][2], acc[mt][nt][3]);
            }
        }
        __syncthreads();   // protect stage (ct&1) before next prefetch overwrites
    }
}

// ---------------- final: out = gamma*(tH^T + tW) + residual ------------------
// s layout [h_local][w] (stride 100): scatter on load (4-way), contiguous reads
__global__ __launch_bounds__(256)
void final_kernel(const float* __restrict__ x, const float* __restrict__ y,
                  const float* __restrict__ gamma, float* __restrict__ out)
{
    __shared__ __half s[32 * 100];   // s[h][w], stride 100 halves
    int z  = blockIdx.y;
    int o  = z >> 12;           // B*C = 4096
    int bc = z & 4095;
    int b  = bc >> 9;
    int c  = bc & 511;
    int h0 = blockIdx.x * 32;
    float g = gamma[0];
    const float* res = (o == 0 ? x : y) + (size_t)bc * HW;
    const __half* tH = g_tH[o];
    const __half* tW = g_tW[o];
    int t = threadIdx.x;

    // load tH slab [w][h0..h0+31], scatter-transpose into s[h][w]
    const __half* tHb = tH + (((size_t)b * LL) * Cc + c) * LL + h0;
    for (int idx = t; idx < 384; idx += 256) {
        int w = idx >> 2, c8 = (idx & 3) * 8;
        uint4 vv = *(const uint4*)&tHb[(size_t)w * Cc * LL + c8];
        const __half* hv = (const __half*)&vv;
#pragma unroll
        for (int j = 0; j < 8; j++)
            s[(c8 + j) * 100 + w] = hv[j];
    }
    __syncthreads();

    const __half* tWb = tW + (((size_t)b * LL + h0) * Cc + c) * LL;
    float* op = out + (size_t)o * BCHW + (size_t)bc * HW;
    // output: 32 h x 24 float4 chunks = 768; s reads contiguous per thread
    for (int idx = t; idx < 768; idx += 256) {
        int h = idx / 24, w4 = (idx % 24) * 4;
        uint2 su = *(const uint2*)&s[h * 100 + w4];
        __half2 s0 = *(__half2*)&su.x;
        __half2 s1 = *(__half2*)&su.y;
        uint2 twu = *(const uint2*)&tWb[(size_t)h * Cc * LL + w4];
        __half2 tw0 = *(__half2*)&twu.x;
        __half2 tw1 = *(__half2*)&twu.y;
        float4 rs = *(const float4*)&res[(size_t)(h0 + h) * LL + w4];
        float4 ov;
        ov.x = g * (__low2float(s0)  + __low2float(tw0))  + rs.x;
        ov.y = g * (__high2float(s0) + __high2float(tw0)) + rs.y;
        ov.z = g * (__low2float(s1)  + __low2float(tw1))  + rs.z;
        ov.w = g * (__high2float(s1) + __high2float(tw1)) + rs.w;
        *(float4*)&op[(size_t)(h0 + h) * LL + w4] = ov;
    }
}

// ---------------------------------------------------------------------------
extern "C" void kernel_launch(void* const* d_in, const int* in_sizes, int n_in,
                              void* d_out, int out_size)
{
    const float* x     = (const float*)d_in[0];
    const float* y     = (const float*)d_in[1];
    const float* Wq    = (const float*)d_in[2];
    const float* bq    = (const float*)d_in[3];
    const float* Wk    = (const float*)d_in[4];
    const float* bk    = (const float*)d_in[5];
    const float* Wv    = (const float*)d_in[6];
    const float* bv    = (const float*)d_in[7];
    const float* gamma = (const float*)d_in[8];
    float* out = (float*)d_out;
    (void)in_sizes; (void)n_in; (void)out_size;

    __half *xh, *yh, *qk, *qkT, *v, *vT;
    cudaGetSymbolAddress((void**)&xh,  g_xh);
    cudaGetSymbolAddress((void**)&yh,  g_yh);
    cudaGetSymbolAddress((void**)&qk,  g_qk);
    cudaGetSymbolAddress((void**)&qkT, g_qkT);
    cudaGetSymbolAddress((void**)&v,   g_v);
    cudaGetSymbolAddress((void**)&vT,  g_vT);

    cudaFuncSetAttribute(proj_f16_kernel,  cudaFuncAttributeMaxDynamicSharedMemorySize, PROJ_SMEM);
    cudaFuncSetAttribute(apply_f16_kernel, cudaFuncAttributeMaxDynamicSharedMemorySize, APPLY_SMEM);

    // 0) convert inputs + stack weights to fp16
    f2h_kernel<<<dim3(BCHW / 2048, 2), 256>>>(x, y);
    weights_kernel<<<1280, 256>>>(Wq, bq, Wk, bk, Wv, bv);

    // 1) fused projections: single launch computes qk and v for both inputs
    proj_f16_kernel<<<dim3(72, 5, 16), 256, PROJ_SMEM>>>(xh, yh);

    // 2) transposes (qk + v in one launch)
    dim3 tb(16, 16);
    transpose16_kernel<<<dim3(3, 3, 2 * Bz * 128 + 2 * Bz * Cc), tb>>>(qk, qkT, v, vT);

    // 3) energies (4 variants in one launch)
    energy_kernel<<<dim3(Bz * LL, 4), 256>>>();

    // 4) joint softmax -> fp16 attention
    softmax_kernel<<<dim3(9216, 2), 256>>>();

    // 5) applies (4 variants, all channels per block, pipelined)
    apply_f16_kernel<<<dim3(Bz * LL, 4), 256, APPLY_SMEM>>>();

    // 6) combine + residual
    final_kernel<<<dim3(3, 2 * Bz * Cc), 256>>>(x, y, gamma, out);
}

// round 15
// speedup vs baseline: 1.1394x; 1.0016x over previous
#include <cuda_runtime.h>
#include <cuda_fp16.h>
#include <math.h>
#include <stdint.h>

// Problem constants
#define Bz   8
#define Cc   512
#define CQq  64
#define LL   96           // H == W == 96
#define HW   9216         // 96*96
#define BCHW 37748736     // 8*512*9216
#define BQKHW 9437184     // 8*128*9216 (stacked q||k)
#define ELN  7077888      // 8*96*96*96

// ---------------- scratch (device globals; allocation-free rule) ------------
__device__ __half g_xh [BCHW];      // fp16 copies of inputs [B][C][H][W]
__device__ __half g_yh [BCHW];
__device__ __half g_qk [2][BQKHW];  // [B][128][H][W]: ch 0..63 = q, 64..127 = k
__device__ __half g_qkT[2][BQKHW];  // [B][128][W][H]
__device__ __half g_v  [2][BCHW];   // [B][C][H][W]
__device__ __half g_vT [2][BCHW];   // [B][C][W][H]
__device__ float  g_eH [2][ELN];    // energies [B][W][H][Hk] (fp32 logits)
__device__ float  g_eW [2][ELN];    // [B][H][W][Wk]
__device__ __half g_aH [2][ELN];    // softmaxed attention, fp16
__device__ __half g_aW [2][ELN];
__device__ __half g_tH [2][BCHW];   // applyH out  [B][W][C][H]
__device__ __half g_tW [2][BCHW];   // applyW out  [B][H][C][W]
__device__ __half g_Wall[640 * 512]; // fp16 stacked Wq||Wk||Wv
__device__ float  g_ball[640];

// ---------------- helpers ----------------------------------------------------
__device__ __forceinline__ uint32_t pack2(float lo, float hi)
{
    __half2 h = __floats2half2_rn(lo, hi);
    return *reinterpret_cast<uint32_t*>(&h);
}

__device__ __forceinline__ void mma_f16(float& c0, float& c1, float& c2, float& c3,
                                        uint32_t a0, uint32_t a1, uint32_t a2, uint32_t a3,
                                        uint32_t b0, uint32_t b1)
{
    asm volatile(
        "mma.sync.aligned.m16n8k16.row.col.f32.f16.f16.f32 "
        "{%0,%1,%2,%3}, {%4,%5,%6,%7}, {%8,%9}, {%0,%1,%2,%3};"
        : "+f"(c0), "+f"(c1), "+f"(c2), "+f"(c3)
        : "r"(a0), "r"(a1), "r"(a2), "r"(a3), "r"(b0), "r"(b1));
}

__device__ __forceinline__ void ldsm_x4(uint32_t& r0, uint32_t& r1, uint32_t& r2, uint32_t& r3,
                                        uint32_t addr)
{
    asm volatile("ldmatrix.sync.aligned.m8n8.x4.shared.b16 {%0,%1,%2,%3}, [%4];"
                 : "=r"(r0), "=r"(r1), "=r"(r2), "=r"(r3) : "r"(addr));
}
__device__ __forceinline__ void ldsm_x4_t(uint32_t& r0, uint32_t& r1, uint32_t& r2, uint32_t& r3,
                                          uint32_t addr)
{
    asm volatile("ldmatrix.sync.aligned.m8n8.x4.trans.shared.b16 {%0,%1,%2,%3}, [%4];"
                 : "=r"(r0), "=r"(r1), "=r"(r2), "=r"(r3) : "r"(addr));
}
__device__ __forceinline__ void ldsm_x2(uint32_t& r0, uint32_t& r1, uint32_t addr)
{
    asm volatile("ldmatrix.sync.aligned.m8n8.x2.shared.b16 {%0,%1}, [%2];"
                 : "=r"(r0), "=r"(r1) : "r"(addr));
}
__device__ __forceinline__ void ldsm_x2_t(uint32_t& r0, uint32_t& r1, uint32_t addr)
{
    asm volatile("ldmatrix.sync.aligned.m8n8.x2.trans.shared.b16 {%0,%1}, [%2];"
                 : "=r"(r0), "=r"(r1) : "r"(addr));
}
__device__ __forceinline__ uint32_t smem_u32(const void* p)
{
    return (uint32_t)__cvta_generic_to_shared(p);
}
__device__ __forceinline__ void cp16(uint32_t dst, const void* src)
{
    asm volatile("cp.async.cg.shared.global [%0], [%1], 16;" :: "r"(dst), "l"(src));
}
__device__ __forceinline__ void cp_commit() { asm volatile("cp.async.commit_group;"); }

// ---------------- fp32 -> fp16 convert (both inputs, one launch) --------------
__global__ void f2h_kernel(const float* __restrict__ x, const float* __restrict__ y)
{
    const float* src = blockIdx.y ? y : x;
    __half* dst = blockIdx.y ? g_yh : g_xh;
    int i = (blockIdx.x * blockDim.x + threadIdx.x) * 8;
    float4 a = *(const float4*)&src[i];
    float4 b = *(const float4*)&src[i + 4];
    uint4 u = make_uint4(pack2(a.x, a.y), pack2(a.z, a.w), pack2(b.x, b.y), pack2(b.z, b.w));
    *(uint4*)&dst[i] = u;
}

// ---------------- weights: stack Wq||Wk||Wv (fp16) + biases -------------------
__global__ void weights_kernel(const float* __restrict__ Wq, const float* __restrict__ bq,
                               const float* __restrict__ Wk, const float* __restrict__ bk,
                               const float* __restrict__ Wv, const float* __restrict__ bv)
{
    int t = blockIdx.x * blockDim.x + threadIdx.x;   // 0..327679
    int m = t >> 9, k = t & 511;
    float w;
    if (m < 64)       w = Wq[m * 512 + k];
    else if (m < 128) w = Wk[(m - 64) * 512 + k];
    else              w = Wv[(m - 128) * 512 + k];
    g_Wall[t] = __float2half(w);
    if (t < 640) {
        float bb;
        if (t < 64)       bb = bq[t];
        else if (t < 128) bb = bk[t - 64];
        else              bb = bv[t - 128];
        g_ball[t] = bb;
    }
}

// ---------------- fused projection GEMM (qk + v), k-tile 64, 3-stage ---------
#define A_STG 9216                  // halves per stage: 128 rows x stride 72
#define B_STG 8704                  // halves per stage: 64 rows x stride 136
#define STG_H (A_STG + B_STG)       // 17920 halves = 35840 B
#define PROJ_SMEM (3 * STG_H * 2)   // 107520 B
__global__ __launch_bounds__(256)
void proj_f16_kernel(const __half* __restrict__ xh, const __half* __restrict__ yh)
{
    extern __shared__ __align__(16) __half sm[];

    int inp = blockIdx.z >> 3;
    int b   = blockIdx.z & 7;
    int bm = blockIdx.y * 128;
    int bn = blockIdx.x * 128;
    int t  = threadIdx.x;
    int warp = t >> 5, lane = t & 31;
    int g = lane >> 2, tg = lane & 3;
    int mw = (warp >> 2) * 64;
    int nw = (warp & 3) * 32;

    const __half* in = inp ? yh : xh;
    const __half* inb = in + (size_t)b * Cc * HW;

    int aRow = (lane & 7) + ((lane >> 3) & 1) * 8;
    int aK8  = ((lane >> 4) & 1) * 8;
    int bRow = (lane & 7) + ((lane >> 3) & 1) * 8;

    float acc[4][4][4];
#pragma unroll
    for (int i = 0; i < 4; i++)
#pragma unroll
        for (int j = 0; j < 4; j++)
#pragma unroll
            for (int r = 0; r < 4; r++) acc[i][j][r] = 0.f;

    auto load_chunk = [&](int c, int s) {
        uint32_t aD = smem_u32(sm + s * STG_H);
        uint32_t bD = aD + A_STG * 2;
        int k0 = c * 64;
#pragma unroll
        for (int r = 0; r < 8; r++) {
            int idx = t + 256 * r;
            if (idx < 1024) {
                int row = idx >> 3, ch = idx & 7;
                cp16(aD + (uint32_t)((row * 72 + ch * 8) * 2),
                     &g_Wall[(size_t)(bm + row) * Cc + k0 + ch * 8]);
            } else {
                int j = idx - 1024;
                int row = j >> 4, ch = j & 15;
                cp16(bD + (uint32_t)((row * 136 + ch * 8) * 2),
                     &inb[(size_t)(k0 + row) * HW + bn + ch * 8]);
            }
        }
    };

    load_chunk(0, 0); cp_commit();
    load_chunk(1, 1); cp_commit();

    const int NK = Cc / 64;   // 8
    for (int i = 0; i < NK; i++) {
        asm volatile("cp.async.wait_group 1;" ::: "memory");
        __syncthreads();
        if (i + 2 < NK) load_chunk(i + 2, (i + 2) % 3);
        cp_commit();

        uint32_t aBase = smem_u32(sm + (i % 3) * STG_H);
        uint32_t bBase = aBase + A_STG * 2;
#pragma unroll
        for (int kk = 0; kk < 64; kk += 16) {
            uint32_t a[4][4], bb[4][2];
#pragma unroll
            for (int mt = 0; mt < 4; mt++) {
                uint32_t ad = aBase + (uint32_t)(((mw + mt * 16 + aRow) * 72 + kk + aK8) * 2);
                ldsm_x4(a[mt][0], a[mt][1], a[mt][2], a[mt][3], ad);
            }
#pragma unroll
            for (int nt = 0; nt < 4; nt++) {
                uint32_t bd = bBase + (uint32_t)(((kk + bRow) * 136 + nw + nt * 8) * 2);
                ldsm_x2_t(bb[nt][0], bb[nt][1], bd);
            }
#pragma unroll
            for (int mt = 0; mt < 4; mt++)
#pragma unroll
                for (int nt = 0; nt < 4; nt++)
                    mma_f16(acc[mt][nt][0], acc[mt][nt][1], acc[mt][nt][2], acc[mt][nt][3],
                            a[mt][0], a[mt][1], a[mt][2], a[mt][3],
                            bb[nt][0], bb[nt][1]);
        }
        __syncthreads();
    }

    __half* obase = (bm == 0)
        ? g_qk[inp] + (size_t)b * 128 * HW
        : g_v[inp]  + (size_t)b * Cc * HW + (size_t)(bm - 128) * HW;
#pragma unroll
    for (int mt = 0; mt < 4; mt++) {
        int mloc = mw + mt * 16 + g;
        float bi0 = g_ball[bm + mloc];
        float bi1 = g_ball[bm + mloc + 8];
        __half* op0 = obase + (size_t)mloc * HW + bn;
        __half* op1 = op0 + (size_t)8 * HW;
#pragma unroll
        for (int nt = 0; nt < 4; nt++) {
            int col = nw + nt * 8 + 2 * tg;
            *(__half2*)&op0[col] = __floats2half2_rn(acc[mt][nt][0] + bi0, acc[mt][nt][1] + bi0);
            *(__half2*)&op1[col] = __floats2half2_rn(acc[mt][nt][2] + bi1, acc[mt][nt][3] + bi1);
        }
    }
}

// ---------------- plane transpose (fp16, half2, 32x32 tiles) -----------------
__global__ void transpose16_kernel(const __half* __restrict__ in, __half* __restrict__ out)
{
    __shared__ __half2 til[32][17];
    int n = blockIdx.z;
    const __half* ip = in  + (size_t)n * HW;
    __half*       op = out + (size_t)n * HW;
    int h0 = blockIdx.y * 32, w0 = blockIdx.x * 32;
    int tx = threadIdx.x, ty = threadIdx.y;   // 16 x 16
#pragma unroll
    for (int r = 0; r < 32; r += 16)
        til[ty + r][tx] = *(const __half2*)&ip[(size_t)(h0 + ty + r) * LL + w0 + 2 * tx];
    __syncthreads();
#pragma unroll
    for (int r = 0; r < 32; r += 16) {
        int w = ty + r;
        int k = w >> 1, ln = w & 1;
        __half2 A = til[2 * tx][k];
        __half2 B = til[2 * tx + 1][k];
        __half a = ln ? __high2half(A) : __low2half(A);
        __half b = ln ? __high2half(B) : __low2half(B);
        *(__half2*)&op[(size_t)(w0 + w) * LL + h0 + 2 * tx] = __halves2half2(a, b);
    }
}

// ---------------- energy (merged 4 variants) via fp16 MMA --------------------
__global__ __launch_bounds__(256)
void energy_kernel()
{
    __shared__ __align__(16) __half Qs[64 * 104];   // [c][i] stride 104
    __shared__ __align__(16) __half Ks[64 * 104];
    int cfg = blockIdx.y;
    int dir = cfg & 1;
    int isH = (cfg < 2);
    const __half* Q = isH ? g_qkT[dir]     : g_qk[dir];
    const __half* K = isH ? g_qkT[1 - dir] : g_qk[1 - dir];
    K += (size_t)64 * HW;   // keys are channels 64..127
    float* E = isH ? g_eH[dir] : g_eW[dir];
    int maskDiag = isH;

    int bl = blockIdx.x;
    int b = bl / LL, line = bl % LL;
    const size_t QKB = (size_t)128 * HW;
    const __half* Qp = Q + (size_t)b * QKB + (size_t)line * LL;
    const __half* Kp = K + (size_t)b * QKB + (size_t)line * LL;
    int t = threadIdx.x;
    int warp = t >> 5, lane = t & 31;
    int g = lane >> 2, tg = lane & 3;
    int mw = (warp >> 2) * 48;
    int nw = (warp & 3) * 24;

    for (int idx = t; idx < 64 * 12; idx += 256) {
        int c = idx / 12, j8 = (idx % 12) * 8;
        *(uint4*)&Qs[c * 104 + j8] = *(const uint4*)&Qp[(size_t)c * HW + j8];
        *(uint4*)&Ks[c * 104 + j8] = *(const uint4*)&Kp[(size_t)c * HW + j8];
    }
    __syncthreads();

    uint32_t qsB = smem_u32(Qs);
    uint32_t ksB = smem_u32(Ks);
    int aMat = lane >> 3;
    int aC = ((aMat >> 1) & 1) * 8 + (lane & 7);
    int aI = (aMat & 1) * 8;
    int bC = ((lane >> 3) & 1) * 8 + (lane & 7);

    float acc[3][3][4];
#pragma unroll
    for (int i = 0; i < 3; i++)
#pragma unroll
        for (int j = 0; j < 3; j++)
#pragma unroll
            for (int r = 0; r < 4; r++) acc[i][j][r] = 0.f;

#pragma unroll
    for (int kk = 0; kk < 64; kk += 16) {
        uint32_t a[3][4], bb[3][2];
#pragma unroll
        for (int mt = 0; mt < 3; mt++) {
            uint32_t ad = qsB + (uint32_t)(((kk + aC) * 104 + mw + mt * 16 + aI) * 2);
            ldsm_x4_t(a[mt][0], a[mt][1], a[mt][2], a[mt][3], ad);
        }
#pragma unroll
        for (int nt = 0; nt < 3; nt++) {
            uint32_t bd = ksB + (uint32_t)(((kk + bC) * 104 + nw + nt * 8) * 2);
            ldsm_x2_t(bb[nt][0], bb[nt][1], bd);
        }
#pragma unroll
        for (int mt = 0; mt < 3; mt++)
#pragma unroll
            for (int nt = 0; nt < 3; nt++)
                mma_f16(acc[mt][nt][0], acc[mt][nt][1], acc[mt][nt][2], acc[mt][nt][3],
                        a[mt][0], a[mt][1], a[mt][2], a[mt][3],
                        bb[nt][0], bb[nt][1]);
    }

    float* Eb = E + (size_t)bl * LL * LL;
#pragma unroll
    for (int mt = 0; mt < 3; mt++) {
        int i0 = mw + mt * 16 + g;
        int i1 = i0 + 8;
#pragma unroll
        for (int nt = 0; nt < 3; nt++) {
            int j0 = nw + nt * 8 + 2 * tg;
            float v0 = acc[mt][nt][0], v1 = acc[mt][nt][1];
            float v2 = acc[mt][nt][2], v3 = acc[mt][nt][3];
            if (maskDiag) {
                if (i0 == j0)     v0 = -1e30f;
                if (i0 == j0 + 1) v1 = -1e30f;
                if (i1 == j0)     v2 = -1e30f;
                if (i1 == j0 + 1) v3 = -1e30f;
            }
            *(float2*)&Eb[(size_t)i0 * LL + j0] = make_float2(v0, v1);
            *(float2*)&Eb[(size_t)i1 * LL + j0] = make_float2(v2, v3);
        }
    }
}

// ---------------- joint softmax; float2 logit loads, half2 att stores --------
__global__ void softmax_kernel()
{
    int dir  = blockIdx.y;
    int warp = (blockIdx.x * blockDim.x + threadIdx.x) >> 5;
    int lane = threadIdx.x & 31;
    int b  = warp / HW;
    int hw = warp % HW;
    int h = hw / LL, w = hw % LL;
    size_t offH = (((size_t)b * LL + w) * LL + h) * LL;
    size_t offW = (((size_t)b * LL + h) * LL + w) * LL;
    const float* rH = &g_eH[dir][offH];
    const float* rW = &g_eW[dir][offW];
    __half* oH = &g_aH[dir][offH];
    __half* oW = &g_aW[dir][offW];

    bool full = (lane < 16);
    float2 vH0 = *(const float2*)&rH[2 * lane];
    float2 vW0 = *(const float2*)&rW[2 * lane];
    float2 vH1 = full ? *(const float2*)&rH[64 + 2 * lane] : make_float2(-1e30f, -1e30f);
    float2 vW1 = full ? *(const float2*)&rW[64 + 2 * lane] : make_float2(-1e30f, -1e30f);

    float m = fmaxf(fmaxf(fmaxf(vH0.x, vH0.y), fmaxf(vW0.x, vW0.y)),
                    fmaxf(fmaxf(vH1.x, vH1.y), fmaxf(vW1.x, vW1.y)));
#pragma unroll
    for (int o = 16; o > 0; o >>= 1) m = fmaxf(m, __shfl_xor_sync(0xffffffffu, m, o));

    vH0.x = __expf(vH0.x - m); vH0.y = __expf(vH0.y - m);
    vW0.x = __expf(vW0.x - m); vW0.y = __expf(vW0.y - m);
    float s = vH0.x + vH0.y + vW0.x + vW0.y;
    if (full) {
        vH1.x = __expf(vH1.x - m); vH1.y = __expf(vH1.y - m);
        vW1.x = __expf(vW1.x - m); vW1.y = __expf(vW1.y - m);
        s += vH1.x + vH1.y + vW1.x + vW1.y;
    }
#pragma unroll
    for (int o = 16; o > 0; o >>= 1) s += __shfl_xor_sync(0xffffffffu, s, o);
    float inv = 1.f / s;

    *(__half2*)&oH[2 * lane] = __floats2half2_rn(vH0.x * inv, vH0.y * inv);
    *(__half2*)&oW[2 * lane] = __floats2half2_rn(vW0.x * inv, vW0.y * inv);
    if (full) {
        *(__half2*)&oH[64 + 2 * lane] = __floats2half2_rn(vH1.x * inv, vH1.y * inv);
        *(__half2*)&oW[64 + 2 * lane] = __floats2half2_rn(vW1.x * inv, vW1.y * inv);
    }
}

// ---------------- apply: all 512 channels per block, cp.async double-buffer --
#define APL_A (96 * 104)                       // halves
#define APL_V (128 * 104)                      // halves per V stage
#define APPLY_SMEM ((APL_A + 2 * APL_V) * 2)   // 73216 B
__global__ __launch_bounds__(256)
void apply_f16_kernel()
{
    extern __shared__ __align__(16) __half smA[];
    __half* As2 = smA;             // [i][k] stride 104
    __half* Vs0 = smA + APL_A;     // two stages of [c][k] stride 104

    int z = blockIdx.y;
    int half_ = z >> 1;
    int isW = z & 1;
    const __half* Vb = isW ? g_v[half_]  : g_vT[half_];
    const __half* Ab = isW ? g_aW[1 - half_] : g_aH[1 - half_];
    __half* Ob = isW ? g_tW[half_] : g_tH[half_];

    int bl  = blockIdx.x;
    int b = bl / LL, line = bl % LL;
    int t = threadIdx.x;
    int warp = t >> 5, lane = t & 31;
    int g = lane >> 2, tg = lane & 3;
    int mw = (warp >> 2) * 64;
    int nw = (warp & 3) * 24;

    uint32_t asB  = smem_u32(As2);
    uint32_t vs0B = smem_u32(Vs0);

    const __half* Ap = Ab + (size_t)bl * LL * LL;
    for (int idx = t; idx < 96 * 12; idx += 256) {
        int i = idx / 12, j8 = (idx % 12) * 8;
        cp16(asB + (uint32_t)((i * 104 + j8) * 2), &Ap[i * LL + j8]);
    }
    auto loadV = [&](int ct, int s) {
        const __half* Vp = Vb + (((size_t)(b * Cc + ct * 128)) * LL + line) * LL;
        uint32_t dst = vs0B + (uint32_t)(s * APL_V * 2);
#pragma unroll
        for (int r = 0; r < 6; r++) {
            int idx = t + 256 * r;
            int c = idx / 12, j8 = (idx % 12) * 8;
            cp16(dst + (uint32_t)((c * 104 + j8) * 2), &Vp[(size_t)c * HW + j8]);
        }
    };
    loadV(0, 0);
    cp_commit();   // G0 = A + V0

    int aRow = (lane & 7) + ((lane >> 3) & 1) * 8;
    int aK8  = ((lane >> 4) & 1) * 8;
    int bRowN = lane & 7;
    int bK8  = ((lane >> 3) & 1) * 8;

    for (int ct = 0; ct < 4; ct++) {
        if (ct < 3) loadV(ct + 1, (ct + 1) & 1);
        cp_commit();
        asm volatile("cp.async.wait_group 1;" ::: "memory");
        __syncthreads();

        uint32_t vsB = vs0B + (uint32_t)((ct & 1) * APL_V * 2);

        float acc[4][3][4];
#pragma unroll
        for (int i = 0; i < 4; i++)
#pragma unroll
            for (int j = 0; j < 3; j++)
#pragma unroll
                for (int r = 0; r < 4; r++) acc[i][j][r] = 0.f;

#pragma unroll
        for (int kk = 0; kk < 96; kk += 16) {
            uint32_t a[4][4], bb[3][2];
#pragma unroll
            for (int mt = 0; mt < 4; mt++) {
                uint32_t ad = vsB + (uint32_t)(((mw + mt * 16 + aRow) * 104 + kk + aK8) * 2);
                ldsm_x4(a[mt][0], a[mt][1], a[mt][2], a[mt][3], ad);
            }
#pragma unroll
            for (int nt = 0; nt < 3; nt++) {
                uint32_t bd = asB + (uint32_t)(((nw + nt * 8 + bRowN) * 104 + kk + bK8) * 2);
                ldsm_x2(bb[nt][0], bb[nt][1], bd);
            }
#pragma unroll
            for (int mt = 0; mt < 4; mt++)
#pragma unroll
                for (int nt = 0; nt < 3; nt++)
                    mma_f16(acc[mt][nt][0], acc[mt][nt][1], acc[mt][nt][2], acc[mt][nt][3],
                            a[mt][0], a[mt][1], a[mt][2], a[mt][3],
                            bb[nt][0], bb[nt][1]);
        }

        __half* Op = Ob + ((size_t)bl * Cc + ct * 128) * LL;
#pragma unroll
        for (int mt = 0; mt < 4; mt++) {
            int m0g = mw + mt * 16 + g;
            __half* o0 = Op + (size_t)m0g * LL;
            __half* o1 = o0 + (size_t)8 * LL;
#pragma unroll
            for (int nt = 0; nt < 3; nt++) {
                int col = nw + nt * 8 + 2 * tg;
                *(__half2*)&o0[col] = __floats2half2_rn(acc[mt][nt][0], acc[mt][nt][1]);
                *(__half2*)&o1[col] = __floats2half2_rn(acc[mt][nt][2], acc[mt][nt][3]);
            }
        }
        __syncthreads();   // protect stage (ct&1) before next prefetch overwrites
    }
}

// ---------------- final: out = gamma*(tH^T + tW) + residual ------------------
__global__ __launch_bounds__(256)
void final_kernel(const float* __restrict__ x, const float* __restrict__ y,
                  const float* __restrict__ gamma, float* __restrict__ out)
{
    __shared__ __half s[32 * 100];   // s[h][w], stride 100 halves
    int z  = blockIdx.y;
    int o  = z >> 12;           // B*C = 4096
    int bc = z & 4095;
    int b  = bc >> 9;
    int c  = bc & 511;
    int h0 = blockIdx.x * 32;
    float g = gamma[0];
    const float* res = (o == 0 ? x : y) + (size_t)bc * HW;
    const __half* tH = g_tH[o];
    const __half* tW = g_tW[o];
    int t = threadIdx.x;

    const __half* tHb = tH + (((size_t)b * LL) * Cc + c) * LL + h0;
    for (int idx = t; idx < 384; idx += 256) {
        int w = idx >> 2, c8 = (idx & 3) * 8;
        uint4 vv = *(const uint4*)&tHb[(size_t)w * Cc * LL + c8];
        const __half* hv = (const __half*)&vv;
#pragma unroll
        for (int j = 0; j < 8; j++)
            s[(c8 + j) * 100 + w] = hv[j];
    }
    __syncthreads();

    const __half* tWb = tW + (((size_t)b * LL + h0) * Cc + c) * LL;
    float* op = out + (size_t)o * BCHW + (size_t)bc * HW;
    for (int idx = t; idx < 768; idx += 256) {
        int h = idx / 24, w4 = (idx % 24) * 4;
        uint2 su = *(const uint2*)&s[h * 100 + w4];
        __half2 s0 = *(__half2*)&su.x;
        __half2 s1 = *(__half2*)&su.y;
        uint2 twu = *(const uint2*)&tWb[(size_t)h * Cc * LL + w4];
        __half2 tw0 = *(__half2*)&twu.x;
        __half2 tw1 = *(__half2*)&twu.y;
        float4 rs = *(const float4*)&res[(size_t)(h0 + h) * LL + w4];
        float4 ov;
        ov.x = g * (__low2float(s0)  + __low2float(tw0))  + rs.x;
        ov.y = g * (__high2float(s0) + __high2float(tw0)) + rs.y;
        ov.z = g * (__low2float(s1)  + __low2float(tw1))  + rs.z;
        ov.w = g * (__high2float(s1) + __high2float(tw1)) + rs.w;
        *(float4*)&op[(size_t)(h0 + h) * LL + w4] = ov;
    }
}

// ---------------------------------------------------------------------------
extern "C" void kernel_launch(void* const* d_in, const int* in_sizes, int n_in,
                              void* d_out, int out_size)
{
    const float* x     = (const float*)d_in[0];
    const float* y     = (const float*)d_in[1];
    const float* Wq    = (const float*)d_in[2];
    const float* bq    = (const float*)d_in[3];
    const float* Wk    = (const float*)d_in[4];
    const float* bk    = (const float*)d_in[5];
    const float* Wv    = (const float*)d_in[6];
    const float* bv    = (const float*)d_in[7];
    const float* gamma = (const float*)d_in[8];
    float* out = (float*)d_out;
    (void)in_sizes; (void)n_in; (void)out_size;

    __half *xh, *yh, *qk, *qkT, *v, *vT;
    cudaGetSymbolAddress((void**)&xh,  g_xh);
    cudaGetSymbolAddress((void**)&yh,  g_yh);
    cudaGetSymbolAddress((void**)&qk,  g_qk);
    cudaGetSymbolAddress((void**)&qkT, g_qkT);
    cudaGetSymbolAddress((void**)&v,   g_v);
    cudaGetSymbolAddress((void**)&vT,  g_vT);

    cudaFuncSetAttribute(proj_f16_kernel,  cudaFuncAttributeMaxDynamicSharedMemorySize, PROJ_SMEM);
    cudaFuncSetAttribute(apply_f16_kernel, cudaFuncAttributeMaxDynamicSharedMemorySize, APPLY_SMEM);

    // side stream + events for capturing a parallel v-transpose branch
    cudaStream_t s2;
    cudaStreamCreateWithFlags(&s2, cudaStreamNonBlocking);
    cudaEvent_t ev1, ev2;
    cudaEventCreateWithFlags(&ev1, cudaEventDisableTiming);
    cudaEventCreateWithFlags(&ev2, cudaEventDisableTiming);

    dim3 tb(16, 16);

    // 0) convert inputs + stack weights to fp16
    f2h_kernel<<<dim3(BCHW / 2048, 2), 256>>>(x, y);
    weights_kernel<<<1280, 256>>>(Wq, bq, Wk, bk, Wv, bv);

    // 1) fused projections: single launch computes qk and v for both inputs
    proj_f16_kernel<<<dim3(72, 5, 16), 256, PROJ_SMEM>>>(xh, yh);

    // fork: v-transpose on side stream (only apply needs vT)
    cudaEventRecord(ev1, 0);
    cudaStreamWaitEvent(s2, ev1, 0);
    transpose16_kernel<<<dim3(3, 3, 2 * Bz * Cc), tb, 0, s2>>>(v, vT);

    // main stream: qk transpose -> energies -> softmax
    transpose16_kernel<<<dim3(3, 3, 2 * Bz * 128), tb>>>(qk, qkT);
    energy_kernel<<<dim3(Bz * LL, 4), 256>>>();
    softmax_kernel<<<dim3(9216, 2), 256>>>();

    // join: apply needs both softmax output and vT
    cudaEventRecord(ev2, s2);
    cudaStreamWaitEvent(0, ev2, 0);

    // 5) applies (4 variants, all channels per block, pipelined)
    apply_f16_kernel<<<dim3(Bz * LL, 4), 256, APPLY_SMEM>>>();

    // 6) combine + residual
    final_kernel<<<dim3(3, 2 * Bz * Cc), 256>>>(x, y, gamma, out);
}

// round 16
// speedup vs baseline: 1.1599x; 1.0180x over previous
#include <cuda_runtime.h>
#include <cuda_fp16.h>
#include <math.h>
#include <stdint.h>

// Problem constants
#define Bz   8
#define Cc   512
#define CQq  64
#define LL   96           // H == W == 96
#define HW   9216         // 96*96
#define BCHW 37748736     // 8*512*9216
#define BQKHW 9437184     // 8*128*9216 (stacked q||k)
#define ELN  7077888      // 8*96*96*96

// ---------------- scratch (device globals; allocation-free rule) ------------
__device__ __half g_xh [BCHW];      // fp16 copies of inputs [B][C][H][W]
__device__ __half g_yh [BCHW];
__device__ __half g_qk [2][BQKHW];  // [B][128][H][W]: ch 0..63 = q, 64..127 = k
__device__ __half g_qkT[2][BQKHW];  // [B][128][W][H]
__device__ __half g_v  [2][BCHW];   // [B][C][H][W]
__device__ __half g_vT [2][BCHW];   // [B][C][W][H]
__device__ float  g_eH [2][ELN];    // energies [B][W][H][Hk] (fp32 logits)
__device__ float  g_eW [2][ELN];    // [B][H][W][Wk]
__device__ __half g_aH [2][ELN];    // softmaxed attention, fp16
__device__ __half g_aW [2][ELN];
__device__ __half g_tH [2][BCHW];   // applyH out  [B][W][C][H]
__device__ __half g_tW [2][BCHW];   // applyW out  [B][H][C][W]
__device__ __half g_Wall[640 * 512]; // fp16 stacked Wq||Wk||Wv
__device__ float  g_ball[640];

// ---------------- helpers ----------------------------------------------------
__device__ __forceinline__ uint32_t pack2(float lo, float hi)
{
    __half2 h = __floats2half2_rn(lo, hi);
    return *reinterpret_cast<uint32_t*>(&h);
}

__device__ __forceinline__ void mma_f16(float& c0, float& c1, float& c2, float& c3,
                                        uint32_t a0, uint32_t a1, uint32_t a2, uint32_t a3,
                                        uint32_t b0, uint32_t b1)
{
    asm volatile(
        "mma.sync.aligned.m16n8k16.row.col.f32.f16.f16.f32 "
        "{%0,%1,%2,%3}, {%4,%5,%6,%7}, {%8,%9}, {%0,%1,%2,%3};"
        : "+f"(c0), "+f"(c1), "+f"(c2), "+f"(c3)
        : "r"(a0), "r"(a1), "r"(a2), "r"(a3), "r"(b0), "r"(b1));
}

__device__ __forceinline__ void ldsm_x4(uint32_t& r0, uint32_t& r1, uint32_t& r2, uint32_t& r3,
                                        uint32_t addr)
{
    asm volatile("ldmatrix.sync.aligned.m8n8.x4.shared.b16 {%0,%1,%2,%3}, [%4];"
                 : "=r"(r0), "=r"(r1), "=r"(r2), "=r"(r3) : "r"(addr));
}
__device__ __forceinline__ void ldsm_x4_t(uint32_t& r0, uint32_t& r1, uint32_t& r2, uint32_t& r3,
                                          uint32_t addr)
{
    asm volatile("ldmatrix.sync.aligned.m8n8.x4.trans.shared.b16 {%0,%1,%2,%3}, [%4];"
                 : "=r"(r0), "=r"(r1), "=r"(r2), "=r"(r3) : "r"(addr));
}
__device__ __forceinline__ void ldsm_x2(uint32_t& r0, uint32_t& r1, uint32_t addr)
{
    asm volatile("ldmatrix.sync.aligned.m8n8.x2.shared.b16 {%0,%1}, [%2];"
                 : "=r"(r0), "=r"(r1) : "r"(addr));
}
__device__ __forceinline__ void ldsm_x2_t(uint32_t& r0, uint32_t& r1, uint32_t addr)
{
    asm volatile("ldmatrix.sync.aligned.m8n8.x2.trans.shared.b16 {%0,%1}, [%2];"
                 : "=r"(r0), "=r"(r1) : "r"(addr));
}
__device__ __forceinline__ uint32_t smem_u32(const void* p)
{
    return (uint32_t)__cvta_generic_to_shared(p);
}
__device__ __forceinline__ void cp16(uint32_t dst, const void* src)
{
    asm volatile("cp.async.cg.shared.global [%0], [%1], 16;" :: "r"(dst), "l"(src));
}
__device__ __forceinline__ void cp_commit() { asm volatile("cp.async.commit_group;"); }

// ---------------- fp32 -> fp16 convert (both inputs, one launch) --------------
__global__ void f2h_kernel(const float* __restrict__ x, const float* __restrict__ y)
{
    const float* src = blockIdx.y ? y : x;
    __half* dst = blockIdx.y ? g_yh : g_xh;
    int i = (blockIdx.x * blockDim.x + threadIdx.x) * 8;
    float4 a = *(const float4*)&src[i];
    float4 b = *(const float4*)&src[i + 4];
    uint4 u = make_uint4(pack2(a.x, a.y), pack2(a.z, a.w), pack2(b.x, b.y), pack2(b.z, b.w));
    *(uint4*)&dst[i] = u;
}

// ---------------- weights: stack Wq||Wk||Wv (fp16) + biases -------------------
__global__ void weights_kernel(const float* __restrict__ Wq, const float* __restrict__ bq,
                               const float* __restrict__ Wk, const float* __restrict__ bk,
                               const float* __restrict__ Wv, const float* __restrict__ bv)
{
    int t = blockIdx.x * blockDim.x + threadIdx.x;   // 0..327679
    int m = t >> 9, k = t & 511;
    float w;
    if (m < 64)       w = Wq[m * 512 + k];
    else if (m < 128) w = Wk[(m - 64) * 512 + k];
    else              w = Wv[(m - 128) * 512 + k];
    g_Wall[t] = __float2half(w);
    if (t < 640) {
        float bb;
        if (t < 64)       bb = bq[t];
        else if (t < 128) bb = bk[t - 64];
        else              bb = bv[t - 128];
        g_ball[t] = bb;
    }
}

// ---------------- fused projection GEMM (qk + v), k-tile 64, 3-stage ---------
#define A_STG 9216                  // halves per stage: 128 rows x stride 72
#define B_STG 8704                  // halves per stage: 64 rows x stride 136
#define STG_H (A_STG + B_STG)       // 17920 halves = 35840 B
#define PROJ_SMEM (3 * STG_H * 2)   // 107520 B
__global__ __launch_bounds__(256)
void proj_f16_kernel(const __half* __restrict__ xh, const __half* __restrict__ yh)
{
    extern __shared__ __align__(16) __half sm[];

    int inp = blockIdx.z >> 3;
    int b   = blockIdx.z & 7;
    int bm = blockIdx.y * 128;
    int bn = blockIdx.x * 128;
    int t  = threadIdx.x;
    int warp = t >> 5, lane = t & 31;
    int g = lane >> 2, tg = lane & 3;
    int mw = (warp >> 2) * 64;
    int nw = (warp & 3) * 32;

    const __half* in = inp ? yh : xh;
    const __half* inb = in + (size_t)b * Cc * HW;

    int aRow = (lane & 7) + ((lane >> 3) & 1) * 8;
    int aK8  = ((lane >> 4) & 1) * 8;
    int bRow = (lane & 7) + ((lane >> 3) & 1) * 8;

    float acc[4][4][4];
#pragma unroll
    for (int i = 0; i < 4; i++)
#pragma unroll
        for (int j = 0; j < 4; j++)
#pragma unroll
            for (int r = 0; r < 4; r++) acc[i][j][r] = 0.f;

    auto load_chunk = [&](int c, int s) {
        uint32_t aD = smem_u32(sm + s * STG_H);
        uint32_t bD = aD + A_STG * 2;
        int k0 = c * 64;
#pragma unroll
        for (int r = 0; r < 8; r++) {
            int idx = t + 256 * r;
            if (idx < 1024) {
                int row = idx >> 3, ch = idx & 7;
                cp16(aD + (uint32_t)((row * 72 + ch * 8) * 2),
                     &g_Wall[(size_t)(bm + row) * Cc + k0 + ch * 8]);
            } else {
                int j = idx - 1024;
                int row = j >> 4, ch = j & 15;
                cp16(bD + (uint32_t)((row * 136 + ch * 8) * 2),
                     &inb[(size_t)(k0 + row) * HW + bn + ch * 8]);
            }
        }
    };

    load_chunk(0, 0); cp_commit();
    load_chunk(1, 1); cp_commit();

    const int NK = Cc / 64;   // 8
    for (int i = 0; i < NK; i++) {
        asm volatile("cp.async.wait_group 1;" ::: "memory");
        __syncthreads();
        if (i + 2 < NK) load_chunk(i + 2, (i + 2) % 3);
        cp_commit();

        uint32_t aBase = smem_u32(sm + (i % 3) * STG_H);
        uint32_t bBase = aBase + A_STG * 2;
#pragma unroll
        for (int kk = 0; kk < 64; kk += 16) {
            uint32_t a[4][4], bb[4][2];
#pragma unroll
            for (int mt = 0; mt < 4; mt++) {
                uint32_t ad = aBase + (uint32_t)(((mw + mt * 16 + aRow) * 72 + kk + aK8) * 2);
                ldsm_x4(a[mt][0], a[mt][1], a[mt][2], a[mt][3], ad);
            }
#pragma unroll
            for (int nt = 0; nt < 4; nt++) {
                uint32_t bd = bBase + (uint32_t)(((kk + bRow) * 136 + nw + nt * 8) * 2);
                ldsm_x2_t(bb[nt][0], bb[nt][1], bd);
            }
#pragma unroll
            for (int mt = 0; mt < 4; mt++)
#pragma unroll
                for (int nt = 0; nt < 4; nt++)
                    mma_f16(acc[mt][nt][0], acc[mt][nt][1], acc[mt][nt][2], acc[mt][nt][3],
                            a[mt][0], a[mt][1], a[mt][2], a[mt][3],
                            bb[nt][0], bb[nt][1]);
        }
        __syncthreads();
    }

    __half* obase = (bm == 0)
        ? g_qk[inp] + (size_t)b * 128 * HW
        : g_v[inp]  + (size_t)b * Cc * HW + (size_t)(bm - 128) * HW;
#pragma unroll
    for (int mt = 0; mt < 4; mt++) {
        int mloc = mw + mt * 16 + g;
        float bi0 = g_ball[bm + mloc];
        float bi1 = g_ball[bm + mloc + 8];
        __half* op0 = obase + (size_t)mloc * HW + bn;
        __half* op1 = op0 + (size_t)8 * HW;
#pragma unroll
        for (int nt = 0; nt < 4; nt++) {
            int col = nw + nt * 8 + 2 * tg;
            *(__half2*)&op0[col] = __floats2half2_rn(acc[mt][nt][0] + bi0, acc[mt][nt][1] + bi0);
            *(__half2*)&op1[col] = __floats2half2_rn(acc[mt][nt][2] + bi1, acc[mt][nt][3] + bi1);
        }
    }
}

// ---------------- plane transpose (fp16, half2, 32x32 tiles) -----------------
__global__ void transpose16_kernel(const __half* __restrict__ in, __half* __restrict__ out)
{
    __shared__ __half2 til[32][17];
    int n = blockIdx.z;
    const __half* ip = in  + (size_t)n * HW;
    __half*       op = out + (size_t)n * HW;
    int h0 = blockIdx.y * 32, w0 = blockIdx.x * 32;
    int tx = threadIdx.x, ty = threadIdx.y;   // 16 x 16
#pragma unroll
    for (int r = 0; r < 32; r += 16)
        til[ty + r][tx] = *(const __half2*)&ip[(size_t)(h0 + ty + r) * LL + w0 + 2 * tx];
    __syncthreads();
#pragma unroll
    for (int r = 0; r < 32; r += 16) {
        int w = ty + r;
        int k = w >> 1, ln = w & 1;
        __half2 A = til[2 * tx][k];
        __half2 B = til[2 * tx + 1][k];
        __half a = ln ? __high2half(A) : __low2half(A);
        __half b = ln ? __high2half(B) : __low2half(B);
        *(__half2*)&op[(size_t)(w0 + w) * LL + h0 + 2 * tx] = __halves2half2(a, b);
    }
}

// ---------------- energy (merged 4 variants) via fp16 MMA --------------------
__global__ __launch_bounds__(256)
void energy_kernel()
{
    __shared__ __align__(16) __half Qs[64 * 104];   // [c][i] stride 104
    __shared__ __align__(16) __half Ks[64 * 104];
    int cfg = blockIdx.y;
    int dir = cfg & 1;
    int isH = (cfg < 2);
    const __half* Q = isH ? g_qkT[dir]     : g_qk[dir];
    const __half* K = isH ? g_qkT[1 - dir] : g_qk[1 - dir];
    K += (size_t)64 * HW;   // keys are channels 64..127
    float* E = isH ? g_eH[dir] : g_eW[dir];
    int maskDiag = isH;

    int bl = blockIdx.x;
    int b = bl / LL, line = bl % LL;
    const size_t QKB = (size_t)128 * HW;
    const __half* Qp = Q + (size_t)b * QKB + (size_t)line * LL;
    const __half* Kp = K + (size_t)b * QKB + (size_t)line * LL;
    int t = threadIdx.x;
    int warp = t >> 5, lane = t & 31;
    int g = lane >> 2, tg = lane & 3;
    int mw = (warp >> 2) * 48;
    int nw = (warp & 3) * 24;

    for (int idx = t; idx < 64 * 12; idx += 256) {
        int c = idx / 12, j8 = (idx % 12) * 8;
        *(uint4*)&Qs[c * 104 + j8] = *(const uint4*)&Qp[(size_t)c * HW + j8];
        *(uint4*)&Ks[c * 104 + j8] = *(const uint4*)&Kp[(size_t)c * HW + j8];
    }
    __syncthreads();

    uint32_t qsB = smem_u32(Qs);
    uint32_t ksB = smem_u32(Ks);
    int aMat = lane >> 3;
    int aC = ((aMat >> 1) & 1) * 8 + (lane & 7);
    int aI = (aMat & 1) * 8;
    int bC = ((lane >> 3) & 1) * 8 + (lane & 7);

    float acc[3][3][4];
#pragma unroll
    for (int i = 0; i < 3; i++)
#pragma unroll
        for (int j = 0; j < 3; j++)
#pragma unroll
            for (int r = 0; r < 4; r++) acc[i][j][r] = 0.f;

#pragma unroll
    for (int kk = 0; kk < 64; kk += 16) {
        uint32_t a[3][4], bb[3][2];
#pragma unroll
        for (int mt = 0; mt < 3; mt++) {
            uint32_t ad = qsB + (uint32_t)(((kk + aC) * 104 + mw + mt * 16 + aI) * 2);
            ldsm_x4_t(a[mt][0], a[mt][1], a[mt][2], a[mt][3], ad);
        }
#pragma unroll
        for (int nt = 0; nt < 3; nt++) {
            uint32_t bd = ksB + (uint32_t)(((kk + bC) * 104 + nw + nt * 8) * 2);
            ldsm_x2_t(bb[nt][0], bb[nt][1], bd);
        }
#pragma unroll
        for (int mt = 0; mt < 3; mt++)
#pragma unroll
            for (int nt = 0; nt < 3; nt++)
                mma_f16(acc[mt][nt][0], acc[mt][nt][1], acc[mt][nt][2], acc[mt][nt][3],
                        a[mt][0], a[mt][1], a[mt][2], a[mt][3],
                        bb[nt][0], bb[nt][1]);
    }

    float* Eb = E + (size_t)bl * LL * LL;
#pragma unroll
    for (int mt = 0; mt < 3; mt++) {
        int i0 = mw + mt * 16 + g;
        int i1 = i0 + 8;
#pragma unroll
        for (int nt = 0; nt < 3; nt++) {
            int j0 = nw + nt * 8 + 2 * tg;
            float v0 = acc[mt][nt][0], v1 = acc[mt][nt][1];
            float v2 = acc[mt][nt][2], v3 = acc[mt][nt][3];
            if (maskDiag) {
                if (i0 == j0)     v0 = -1e30f;
                if (i0 == j0 + 1) v1 = -1e30f;
                if (i1 == j0)     v2 = -1e30f;
                if (i1 == j0 + 1) v3 = -1e30f;
            }
            *(float2*)&Eb[(size_t)i0 * LL + j0] = make_float2(v0, v1);
            *(float2*)&Eb[(size_t)i1 * LL + j0] = make_float2(v2, v3);
        }
    }
}

// ---------------- joint softmax; float2 logit loads, half2 att stores --------
__global__ void softmax_kernel()
{
    int dir  = blockIdx.y;
    int warp = (blockIdx.x * blockDim.x + threadIdx.x) >> 5;
    int lane = threadIdx.x & 31;
    int b  = warp / HW;
    int hw = warp % HW;
    int h = hw / LL, w = hw % LL;
    size_t offH = (((size_t)b * LL + w) * LL + h) * LL;
    size_t offW = (((size_t)b * LL + h) * LL + w) * LL;
    const float* rH = &g_eH[dir][offH];
    const float* rW = &g_eW[dir][offW];
    __half* oH = &g_aH[dir][offH];
    __half* oW = &g_aW[dir][offW];

    bool full = (lane < 16);
    float2 vH0 = *(const float2*)&rH[2 * lane];
    float2 vW0 = *(const float2*)&rW[2 * lane];
    float2 vH1 = full ? *(const float2*)&rH[64 + 2 * lane] : make_float2(-1e30f, -1e30f);
    float2 vW1 = full ? *(const float2*)&rW[64 + 2 * lane] : make_float2(-1e30f, -1e30f);

    float m = fmaxf(fmaxf(fmaxf(vH0.x, vH0.y), fmaxf(vW0.x, vW0.y)),
                    fmaxf(fmaxf(vH1.x, vH1.y), fmaxf(vW1.x, vW1.y)));
#pragma unroll
    for (int o = 16; o > 0; o >>= 1) m = fmaxf(m, __shfl_xor_sync(0xffffffffu, m, o));

    vH0.x = __expf(vH0.x - m); vH0.y = __expf(vH0.y - m);
    vW0.x = __expf(vW0.x - m); vW0.y = __expf(vW0.y - m);
    float s = vH0.x + vH0.y + vW0.x + vW0.y;
    if (full) {
        vH1.x = __expf(vH1.x - m); vH1.y = __expf(vH1.y - m);
        vW1.x = __expf(vW1.x - m); vW1.y = __expf(vW1.y - m);
        s += vH1.x + vH1.y + vW1.x + vW1.y;
    }
#pragma unroll
    for (int o = 16; o > 0; o >>= 1) s += __shfl_xor_sync(0xffffffffu, s, o);
    float inv = 1.f / s;

    *(__half2*)&oH[2 * lane] = __floats2half2_rn(vH0.x * inv, vH0.y * inv);
    *(__half2*)&oW[2 * lane] = __floats2half2_rn(vW0.x * inv, vW0.y * inv);
    if (full) {
        *(__half2*)&oH[64 + 2 * lane] = __floats2half2_rn(vH1.x * inv, vH1.y * inv);
        *(__half2*)&oW[64 + 2 * lane] = __floats2half2_rn(vW1.x * inv, vW1.y * inv);
    }
}

// ---------------- apply: all 512 channels per block, cp.async double-buffer --
#define APL_A (96 * 104)                       // halves
#define APL_V (128 * 104)                      // halves per V stage
#define APPLY_SMEM ((APL_A + 2 * APL_V) * 2)   // 73216 B
__global__ __launch_bounds__(256)
void apply_f16_kernel()
{
    extern __shared__ __align__(16) __half smA[];
    __half* As2 = smA;             // [i][k] stride 104
    __half* Vs0 = smA + APL_A;     // two stages of [c][k] stride 104

    int z = blockIdx.y;
    int half_ = z >> 1;
    int isW = z & 1;
    const __half* Vb = isW ? g_v[half_]  : g_vT[half_];
    const __half* Ab = isW ? g_aW[1 - half_] : g_aH[1 - half_];
    __half* Ob = isW ? g_tW[half_] : g_tH[half_];

    int bl  = blockIdx.x;
    int b = bl / LL, line = bl % LL;
    int t = threadIdx.x;
    int warp = t >> 5, lane = t & 31;
    int g = lane >> 2, tg = lane & 3;
    int mw = (warp >> 2) * 64;
    int nw = (warp & 3) * 24;

    uint32_t asB  = smem_u32(As2);
    uint32_t vs0B = smem_u32(Vs0);

    const __half* Ap = Ab + (size_t)bl * LL * LL;
    for (int idx = t; idx < 96 * 12; idx += 256) {
        int i = idx / 12, j8 = (idx % 12) * 8;
        cp16(asB + (uint32_t)((i * 104 + j8) * 2), &Ap[i * LL + j8]);
    }
    auto loadV = [&](int ct, int s) {
        const __half* Vp = Vb + (((size_t)(b * Cc + ct * 128)) * LL + line) * LL;
        uint32_t dst = vs0B + (uint32_t)(s * APL_V * 2);
#pragma unroll
        for (int r = 0; r < 6; r++) {
            int idx = t + 256 * r;
            int c = idx / 12, j8 = (idx % 12) * 8;
            cp16(dst + (uint32_t)((c * 104 + j8) * 2), &Vp[(size_t)c * HW + j8]);
        }
    };
    loadV(0, 0);
    cp_commit();   // G0 = A + V0

    int aRow = (lane & 7) + ((lane >> 3) & 1) * 8;
    int aK8  = ((lane >> 4) & 1) * 8;
    int bRowN = lane & 7;
    int bK8  = ((lane >> 3) & 1) * 8;

    for (int ct = 0; ct < 4; ct++) {
        if (ct < 3) loadV(ct + 1, (ct + 1) & 1);
        cp_commit();
        asm volatile("cp.async.wait_group 1;" ::: "memory");
        __syncthreads();

        uint32_t vsB = vs0B + (uint32_t)((ct & 1) * APL_V * 2);

        float acc[4][3][4];
#pragma unroll
        for (int i = 0; i < 4; i++)
#pragma unroll
            for (int j = 0; j < 3; j++)
#pragma unroll
                for (int r = 0; r < 4; r++) acc[i][j][r] = 0.f;

#pragma unroll
        for (int kk = 0; kk < 96; kk += 16) {
            uint32_t a[4][4], bb[3][2];
#pragma unroll
            for (int mt = 0; mt < 4; mt++) {
                uint32_t ad = vsB + (uint32_t)(((mw + mt * 16 + aRow) * 104 + kk + aK8) * 2);
                ldsm_x4(a[mt][0], a[mt][1], a[mt][2], a[mt][3], ad);
            }
#pragma unroll
            for (int nt = 0; nt < 3; nt++) {
                uint32_t bd = asB + (uint32_t)(((nw + nt * 8 + bRowN) * 104 + kk + bK8) * 2);
                ldsm_x2(bb[nt][0], bb[nt][1], bd);
            }
#pragma unroll
            for (int mt = 0; mt < 4; mt++)
#pragma unroll
                for (int nt = 0; nt < 3; nt++)
                    mma_f16(acc[mt][nt][0], acc[mt][nt][1], acc[mt][nt][2], acc[mt][nt][3],
                            a[mt][0], a[mt][1], a[mt][2], a[mt][3],
                            bb[nt][0], bb[nt][1]);
        }

        __half* Op = Ob + ((size_t)bl * Cc + ct * 128) * LL;
#pragma unroll
        for (int mt = 0; mt < 4; mt++) {
            int m0g = mw + mt * 16 + g;
            __half* o0 = Op + (size_t)m0g * LL;
            __half* o1 = o0 + (size_t)8 * LL;
#pragma unroll
            for (int nt = 0; nt < 3; nt++) {
                int col = nw + nt * 8 + 2 * tg;
                *(__half2*)&o0[col] = __floats2half2_rn(acc[mt][nt][0], acc[mt][nt][1]);
                *(__half2*)&o1[col] = __floats2half2_rn(acc[mt][nt][2], acc[mt][nt][3]);
            }
        }
        __syncthreads();   // protect stage (ct&1) before next prefetch overwrites
    }
}

// ---------------- final: out = gamma*(tH^T + tW) + residual(fp16) ------------
__global__ __launch_bounds__(256)
void final_kernel(const float* __restrict__ gamma, float* __restrict__ out)
{
    __shared__ __half s[32 * 100];   // s[h][w], stride 100 halves
    int z  = blockIdx.y;
    int o  = z >> 12;           // B*C = 4096
    int bc = z & 4095;
    int b  = bc >> 9;
    int c  = bc & 511;
    int h0 = blockIdx.x * 32;
    float g = gamma[0];
    const __half* res = (o == 0 ? g_xh : g_yh) + (size_t)bc * HW;
    const __half* tH = g_tH[o];
    const __half* tW = g_tW[o];
    int t = threadIdx.x;

    const __half* tHb = tH + (((size_t)b * LL) * Cc + c) * LL + h0;
    for (int idx = t; idx < 384; idx += 256) {
        int w = idx >> 2, c8 = (idx & 3) * 8;
        uint4 vv = *(const uint4*)&tHb[(size_t)w * Cc * LL + c8];
        const __half* hv = (const __half*)&vv;
#pragma unroll
        for (int j = 0; j < 8; j++)
            s[(c8 + j) * 100 + w] = hv[j];
    }
    __syncthreads();

    const __half* tWb = tW + (((size_t)b * LL + h0) * Cc + c) * LL;
    float* op = out + (size_t)o * BCHW + (size_t)bc * HW;
    for (int idx = t; idx < 768; idx += 256) {
        int h = idx / 24, w4 = (idx % 24) * 4;
        uint2 su = *(const uint2*)&s[h * 100 + w4];
        __half2 s0 = *(__half2*)&su.x;
        __half2 s1 = *(__half2*)&su.y;
        uint2 twu = *(const uint2*)&tWb[(size_t)h * Cc * LL + w4];
        __half2 tw0 = *(__half2*)&twu.x;
        __half2 tw1 = *(__half2*)&twu.y;
        uint2 rsu = *(const uint2*)&res[(size_t)(h0 + h) * LL + w4];
        __half2 rs0 = *(__half2*)&rsu.x;
        __half2 rs1 = *(__half2*)&rsu.y;
        float4 ov;
        ov.x = g * (__low2float(s0)  + __low2float(tw0))  + __low2float(rs0);
        ov.y = g * (__high2float(s0) + __high2float(tw0)) + __high2float(rs0);
        ov.z = g * (__low2float(s1)  + __low2float(tw1))  + __low2float(rs1);
        ov.w = g * (__high2float(s1) + __high2float(tw1)) + __high2float(rs1);
        *(float4*)&op[(size_t)(h0 + h) * LL + w4] = ov;
    }
}

// ---------------------------------------------------------------------------
extern "C" void kernel_launch(void* const* d_in, const int* in_sizes, int n_in,
                              void* d_out, int out_size)
{
    const float* x     = (const float*)d_in[0];
    const float* y     = (const float*)d_in[1];
    const float* Wq    = (const float*)d_in[2];
    const float* bq    = (const float*)d_in[3];
    const float* Wk    = (const float*)d_in[4];
    const float* bk    = (const float*)d_in[5];
    const float* Wv    = (const float*)d_in[6];
    const float* bv    = (const float*)d_in[7];
    const float* gamma = (const float*)d_in[8];
    float* out = (float*)d_out;
    (void)in_sizes; (void)n_in; (void)out_size;

    __half *xh, *yh, *qk, *qkT, *v, *vT;
    cudaGetSymbolAddress((void**)&xh,  g_xh);
    cudaGetSymbolAddress((void**)&yh,  g_yh);
    cudaGetSymbolAddress((void**)&qk,  g_qk);
    cudaGetSymbolAddress((void**)&qkT, g_qkT);
    cudaGetSymbolAddress((void**)&v,   g_v);
    cudaGetSymbolAddress((void**)&vT,  g_vT);

    cudaFuncSetAttribute(proj_f16_kernel,  cudaFuncAttributeMaxDynamicSharedMemorySize, PROJ_SMEM);
    cudaFuncSetAttribute(apply_f16_kernel, cudaFuncAttributeMaxDynamicSharedMemorySize, APPLY_SMEM);

    // side stream + events for capturing a parallel v-transpose branch
    cudaStream_t s2;
    cudaStreamCreateWithFlags(&s2, cudaStreamNonBlocking);
    cudaEvent_t ev1, ev2;
    cudaEventCreateWithFlags(&ev1, cudaEventDisableTiming);
    cudaEventCreateWithFlags(&ev2, cudaEventDisableTiming);

    dim3 tb(16, 16);

    // 0) convert inputs + stack weights to fp16
    f2h_kernel<<<dim3(BCHW / 2048, 2), 256>>>(x, y);
    weights_kernel<<<1280, 256>>>(Wq, bq, Wk, bk, Wv, bv);

    // 1) fused projections: single launch computes qk and v for both inputs
    proj_f16_kernel<<<dim3(72, 5, 16), 256, PROJ_SMEM>>>(xh, yh);

    // fork: v-transpose on side stream (only apply needs vT)
    cudaEventRecord(ev1, 0);
    cudaStreamWaitEvent(s2, ev1, 0);
    transpose16_kernel<<<dim3(3, 3, 2 * Bz * Cc), tb, 0, s2>>>(v, vT);

    // main stream: qk transpose -> energies -> softmax
    transpose16_kernel<<<dim3(3, 3, 2 * Bz * 128), tb>>>(qk, qkT);
    energy_kernel<<<dim3(Bz * LL, 4), 256>>>();
    softmax_kernel<<<dim3(9216, 2), 256>>>();

    // join: apply needs both softmax output and vT
    cudaEventRecord(ev2, s2);
    cudaStreamWaitEvent(0, ev2, 0);

    // 5) applies (4 variants, all channels per block, pipelined)
    apply_f16_kernel<<<dim3(Bz * LL, 4), 256, APPLY_SMEM>>>();

    // 6) combine + residual (fp16 residual from g_xh/g_yh)
    final_kernel<<<dim3(3, 2 * Bz * Cc), 256>>>(gamma, out);
}

// round 17
// speedup vs baseline: 1.1801x; 1.0174x over previous
#include <cuda_runtime.h>
#include <cuda_fp16.h>
#include <math.h>
#include <stdint.h>

// Problem constants
#define Bz   8
#define Cc   512
#define CQq  64
#define LL   96           // H == W == 96
#define HW   9216         // 96*96
#define BCHW 37748736     // 8*512*9216
#define BQKHW 9437184     // 8*128*9216 (stacked q||k)
#define ELN  7077888      // 8*96*96*96
#define BHW  73728        // 8*9216

// ---------------- scratch (device globals; allocation-free rule) ------------
__device__ __half g_xh [BCHW];      // fp16 copies of inputs [B][C][H][W]
__device__ __half g_yh [BCHW];
__device__ __half g_qk [2][BQKHW];  // [B][128][H][W]: ch 0..63 = q, 64..127 = k
__device__ __half g_qkT[2][BQKHW];  // [B][128][W][H]
__device__ __half g_v  [2][BCHW];   // [B][C][H][W]
__device__ __half g_vT [2][BCHW];   // [B][C][W][H]
__device__ __half g_aH [2][ELN];    // unnormalized att numerators, fp16
__device__ __half g_aW [2][ELN];
__device__ float  g_mH [2][BHW];    // per-row max   (H rows: [b][w][h])
__device__ float  g_sH [2][BHW];    // per-row sumexp
__device__ float  g_mW [2][BHW];    // (W rows: [b][h][w])
__device__ float  g_sW [2][BHW];
__device__ float  g_scH[2][BHW];    // combined scales
__device__ float  g_scW[2][BHW];
__device__ __half g_tH [2][BCHW];   // applyH out  [B][W][C][H]
__device__ __half g_tW [2][BCHW];   // applyW out  [B][H][C][W]
__device__ __half g_Wall[640 * 512]; // fp16 stacked Wq||Wk||Wv
__device__ float  g_ball[640];

// ---------------- helpers ----------------------------------------------------
__device__ __forceinline__ uint32_t pack2(float lo, float hi)
{
    __half2 h = __floats2half2_rn(lo, hi);
    return *reinterpret_cast<uint32_t*>(&h);
}

__device__ __forceinline__ void mma_f16(float& c0, float& c1, float& c2, float& c3,
                                        uint32_t a0, uint32_t a1, uint32_t a2, uint32_t a3,
                                        uint32_t b0, uint32_t b1)
{
    asm volatile(
        "mma.sync.aligned.m16n8k16.row.col.f32.f16.f16.f32 "
        "{%0,%1,%2,%3}, {%4,%5,%6,%7}, {%8,%9}, {%0,%1,%2,%3};"
        : "+f"(c0), "+f"(c1), "+f"(c2), "+f"(c3)
        : "r"(a0), "r"(a1), "r"(a2), "r"(a3), "r"(b0), "r"(b1));
}

__device__ __forceinline__ void ldsm_x4(uint32_t& r0, uint32_t& r1, uint32_t& r2, uint32_t& r3,
                                        uint32_t addr)
{
    asm volatile("ldmatrix.sync.aligned.m8n8.x4.shared.b16 {%0,%1,%2,%3}, [%4];"
                 : "=r"(r0), "=r"(r1), "=r"(r2), "=r"(r3) : "r"(addr));
}
__device__ __forceinline__ void ldsm_x4_t(uint32_t& r0, uint32_t& r1, uint32_t& r2, uint32_t& r3,
                                          uint32_t addr)
{
    asm volatile("ldmatrix.sync.aligned.m8n8.x4.trans.shared.b16 {%0,%1,%2,%3}, [%4];"
                 : "=r"(r0), "=r"(r1), "=r"(r2), "=r"(r3) : "r"(addr));
}
__device__ __forceinline__ void ldsm_x2(uint32_t& r0, uint32_t& r1, uint32_t addr)
{
    asm volatile("ldmatrix.sync.aligned.m8n8.x2.shared.b16 {%0,%1}, [%2];"
                 : "=r"(r0), "=r"(r1) : "r"(addr));
}
__device__ __forceinline__ void ldsm_x2_t(uint32_t& r0, uint32_t& r1, uint32_t addr)
{
    asm volatile("ldmatrix.sync.aligned.m8n8.x2.trans.shared.b16 {%0,%1}, [%2];"
                 : "=r"(r0), "=r"(r1) : "r"(addr));
}
__device__ __forceinline__ uint32_t smem_u32(const void* p)
{
    return (uint32_t)__cvta_generic_to_shared(p);
}
__device__ __forceinline__ void cp16(uint32_t dst, const void* src)
{
    asm volatile("cp.async.cg.shared.global [%0], [%1], 16;" :: "r"(dst), "l"(src));
}
__device__ __forceinline__ void cp_commit() { asm volatile("cp.async.commit_group;"); }

// ---------------- fp32 -> fp16 convert (both inputs, one launch) --------------
__global__ void f2h_kernel(const float* __restrict__ x, const float* __restrict__ y)
{
    const float* src = blockIdx.y ? y : x;
    __half* dst = blockIdx.y ? g_yh : g_xh;
    int i = (blockIdx.x * blockDim.x + threadIdx.x) * 8;
    float4 a = *(const float4*)&src[i];
    float4 b = *(const float4*)&src[i + 4];
    uint4 u = make_uint4(pack2(a.x, a.y), pack2(a.z, a.w), pack2(b.x, b.y), pack2(b.z, b.w));
    *(uint4*)&dst[i] = u;
}

// ---------------- weights: stack Wq||Wk||Wv (fp16) + biases -------------------
__global__ void weights_kernel(const float* __restrict__ Wq, const float* __restrict__ bq,
                               const float* __restrict__ Wk, const float* __restrict__ bk,
                               const float* __restrict__ Wv, const float* __restrict__ bv)
{
    int t = blockIdx.x * blockDim.x + threadIdx.x;   // 0..327679
    int m = t >> 9, k = t & 511;
    float w;
    if (m < 64)       w = Wq[m * 512 + k];
    else if (m < 128) w = Wk[(m - 64) * 512 + k];
    else              w = Wv[(m - 128) * 512 + k];
    g_Wall[t] = __float2half(w);
    if (t < 640) {
        float bb;
        if (t < 64)       bb = bq[t];
        else if (t < 128) bb = bk[t - 64];
        else              bb = bv[t - 128];
        g_ball[t] = bb;
    }
}

// ---------------- fused projection GEMM (qk + v), k-tile 64, 3-stage ---------
#define A_STG 9216                  // halves per stage: 128 rows x stride 72
#define B_STG 8704                  // halves per stage: 64 rows x stride 136
#define STG_H (A_STG + B_STG)       // 17920 halves = 35840 B
#define PROJ_SMEM (3 * STG_H * 2)   // 107520 B
__global__ __launch_bounds__(256)
void proj_f16_kernel(const __half* __restrict__ xh, const __half* __restrict__ yh)
{
    extern __shared__ __align__(16) __half sm[];

    int inp = blockIdx.z >> 3;
    int b   = blockIdx.z & 7;
    int bm = blockIdx.y * 128;
    int bn = blockIdx.x * 128;
    int t  = threadIdx.x;
    int warp = t >> 5, lane = t & 31;
    int g = lane >> 2, tg = lane & 3;
    int mw = (warp >> 2) * 64;
    int nw = (warp & 3) * 32;

    const __half* in = inp ? yh : xh;
    const __half* inb = in + (size_t)b * Cc * HW;

    int aRow = (lane & 7) + ((lane >> 3) & 1) * 8;
    int aK8  = ((lane >> 4) & 1) * 8;
    int bRow = (lane & 7) + ((lane >> 3) & 1) * 8;

    float acc[4][4][4];
#pragma unroll
    for (int i = 0; i < 4; i++)
#pragma unroll
        for (int j = 0; j < 4; j++)
#pragma unroll
            for (int r = 0; r < 4; r++) acc[i][j][r] = 0.f;

    auto load_chunk = [&](int c, int s) {
        uint32_t aD = smem_u32(sm + s * STG_H);
        uint32_t bD = aD + A_STG * 2;
        int k0 = c * 64;
#pragma unroll
        for (int r = 0; r < 8; r++) {
            int idx = t + 256 * r;
            if (idx < 1024) {
                int row = idx >> 3, ch = idx & 7;
                cp16(aD + (uint32_t)((row * 72 + ch * 8) * 2),
                     &g_Wall[(size_t)(bm + row) * Cc + k0 + ch * 8]);
            } else {
                int j = idx - 1024;
                int row = j >> 4, ch = j & 15;
                cp16(bD + (uint32_t)((row * 136 + ch * 8) * 2),
                     &inb[(size_t)(k0 + row) * HW + bn + ch * 8]);
            }
        }
    };

    load_chunk(0, 0); cp_commit();
    load_chunk(1, 1); cp_commit();

    const int NK = Cc / 64;   // 8
    for (int i = 0; i < NK; i++) {
        asm volatile("cp.async.wait_group 1;" ::: "memory");
        __syncthreads();
        if (i + 2 < NK) load_chunk(i + 2, (i + 2) % 3);
        cp_commit();

        uint32_t aBase = smem_u32(sm + (i % 3) * STG_H);
        uint32_t bBase = aBase + A_STG * 2;
#pragma unroll
        for (int kk = 0; kk < 64; kk += 16) {
            uint32_t a[4][4], bb[4][2];
#pragma unroll
            for (int mt = 0; mt < 4; mt++) {
                uint32_t ad = aBase + (uint32_t)(((mw + mt * 16 + aRow) * 72 + kk + aK8) * 2);
                ldsm_x4(a[mt][0], a[mt][1], a[mt][2], a[mt][3], ad);
            }
#pragma unroll
            for (int nt = 0; nt < 4; nt++) {
                uint32_t bd = bBase + (uint32_t)(((kk + bRow) * 136 + nw + nt * 8) * 2);
                ldsm_x2_t(bb[nt][0], bb[nt][1], bd);
            }
#pragma unroll
            for (int mt = 0; mt < 4; mt++)
#pragma unroll
                for (int nt = 0; nt < 4; nt++)
                    mma_f16(acc[mt][nt][0], acc[mt][nt][1], acc[mt][nt][2], acc[mt][nt][3],
                            a[mt][0], a[mt][1], a[mt][2], a[mt][3],
                            bb[nt][0], bb[nt][1]);
        }
        __syncthreads();
    }

    __half* obase = (bm == 0)
        ? g_qk[inp] + (size_t)b * 128 * HW
        : g_v[inp]  + (size_t)b * Cc * HW + (size_t)(bm - 128) * HW;
#pragma unroll
    for (int mt = 0; mt < 4; mt++) {
        int mloc = mw + mt * 16 + g;
        float bi0 = g_ball[bm + mloc];
        float bi1 = g_ball[bm + mloc + 8];
        __half* op0 = obase + (size_t)mloc * HW + bn;
        __half* op1 = op0 + (size_t)8 * HW;
#pragma unroll
        for (int nt = 0; nt < 4; nt++) {
            int col = nw + nt * 8 + 2 * tg;
            *(__half2*)&op0[col] = __floats2half2_rn(acc[mt][nt][0] + bi0, acc[mt][nt][1] + bi0);
            *(__half2*)&op1[col] = __floats2half2_rn(acc[mt][nt][2] + bi1, acc[mt][nt][3] + bi1);
        }
    }
}

// ---------------- plane transpose (fp16, half2, 32x32 tiles) -----------------
__global__ void transpose16_kernel(const __half* __restrict__ in, __half* __restrict__ out)
{
    __shared__ __half2 til[32][17];
    int n = blockIdx.z;
    const __half* ip = in  + (size_t)n * HW;
    __half*       op = out + (size_t)n * HW;
    int h0 = blockIdx.y * 32, w0 = blockIdx.x * 32;
    int tx = threadIdx.x, ty = threadIdx.y;   // 16 x 16
#pragma unroll
    for (int r = 0; r < 32; r += 16)
        til[ty + r][tx] = *(const __half2*)&ip[(size_t)(h0 + ty + r) * LL + w0 + 2 * tx];
    __syncthreads();
#pragma unroll
    for (int r = 0; r < 32; r += 16) {
        int w = ty + r;
        int k = w >> 1, ln = w & 1;
        __half2 A = til[2 * tx][k];
        __half2 B = til[2 * tx + 1][k];
        __half a = ln ? __high2half(A) : __low2half(A);
        __half b = ln ? __high2half(B) : __low2half(B);
        *(__half2*)&op[(size_t)(w0 + w) * LL + h0 + 2 * tx] = __halves2half2(a, b);
    }
}

// ---------------- energy + fused row softmax numerators ----------------------
// writes fp16 num = exp(e - rowmax) into att; rowmax/rowsum into stats arrays
__global__ __launch_bounds__(256)
void energy_kernel()
{
    __shared__ __align__(16) __half Qs[64 * 104];   // [c][i] stride 104
    __shared__ __align__(16) __half Ks[64 * 104];
    __shared__ float redM[4][96];
    __shared__ float redS[4][96];
    int cfg = blockIdx.y;
    int dir = cfg & 1;
    int isH = (cfg < 2);
    const __half* Q = isH ? g_qkT[dir]     : g_qk[dir];
    const __half* K = isH ? g_qkT[1 - dir] : g_qk[1 - dir];
    K += (size_t)64 * HW;   // keys are channels 64..127
    __half* att = isH ? g_aH[dir] : g_aW[dir];
    float* gm = isH ? g_mH[dir] : g_mW[dir];
    float* gs = isH ? g_sH[dir] : g_sW[dir];
    int maskDiag = isH;

    int bl = blockIdx.x;
    int b = bl / LL, line = bl % LL;
    const size_t QKB = (size_t)128 * HW;
    const __half* Qp = Q + (size_t)b * QKB + (size_t)line * LL;
    const __half* Kp = K + (size_t)b * QKB + (size_t)line * LL;
    int t = threadIdx.x;
    int warp = t >> 5, lane = t & 31;
    int g = lane >> 2, tg = lane & 3;
    int mw = (warp >> 2) * 48;
    int nw = (warp & 3) * 24;
    int warpN = warp & 3;

    for (int idx = t; idx < 64 * 12; idx += 256) {
        int c = idx / 12, j8 = (idx % 12) * 8;
        *(uint4*)&Qs[c * 104 + j8] = *(const uint4*)&Qp[(size_t)c * HW + j8];
        *(uint4*)&Ks[c * 104 + j8] = *(const uint4*)&Kp[(size_t)c * HW + j8];
    }
    __syncthreads();

    uint32_t qsB = smem_u32(Qs);
    uint32_t ksB = smem_u32(Ks);
    int aMat = lane >> 3;
    int aC = ((aMat >> 1) & 1) * 8 + (lane & 7);
    int aI = (aMat & 1) * 8;
    int bC = ((lane >> 3) & 1) * 8 + (lane & 7);

    float acc[3][3][4];
#pragma unroll
    for (int i = 0; i < 3; i++)
#pragma unroll
        for (int j = 0; j < 3; j++)
#pragma unroll
            for (int r = 0; r < 4; r++) acc[i][j][r] = 0.f;

#pragma unroll
    for (int kk = 0; kk < 64; kk += 16) {
        uint32_t a[3][4], bb[3][2];
#pragma unroll
        for (int mt = 0; mt < 3; mt++) {
            uint32_t ad = qsB + (uint32_t)(((kk + aC) * 104 + mw + mt * 16 + aI) * 2);
            ldsm_x4_t(a[mt][0], a[mt][1], a[mt][2], a[mt][3], ad);
        }
#pragma unroll
        for (int nt = 0; nt < 3; nt++) {
            uint32_t bd = ksB + (uint32_t)(((kk + bC) * 104 + nw + nt * 8) * 2);
            ldsm_x2_t(bb[nt][0], bb[nt][1], bd);
        }
#pragma unroll
        for (int mt = 0; mt < 3; mt++)
#pragma unroll
            for (int nt = 0; nt < 3; nt++)
                mma_f16(acc[mt][nt][0], acc[mt][nt][1], acc[mt][nt][2], acc[mt][nt][3],
                        a[mt][0], a[mt][1], a[mt][2], a[mt][3],
                        bb[nt][0], bb[nt][1]);
    }

    // mask diagonal (H direction)
    if (maskDiag) {
#pragma unroll
        for (int mt = 0; mt < 3; mt++) {
            int i0 = mw + mt * 16 + g, i1 = i0 + 8;
#pragma unroll
            for (int nt = 0; nt < 3; nt++) {
                int j0 = nw + nt * 8 + 2 * tg;
                if (i0 == j0)     acc[mt][nt][0] = -1e30f;
                if (i0 == j0 + 1) acc[mt][nt][1] = -1e30f;
                if (i1 == j0)     acc[mt][nt][2] = -1e30f;
                if (i1 == j0 + 1) acc[mt][nt][3] = -1e30f;
            }
        }
    }

    // row max: per-thread over nt, quad shuffle (tg), cross-warp via smem
    float rmax[3][2];
#pragma unroll
    for (int mt = 0; mt < 3; mt++)
#pragma unroll
        for (int r2 = 0; r2 < 2; r2++) {
            float v = fmaxf(acc[mt][0][2 * r2], acc[mt][0][2 * r2 + 1]);
            v = fmaxf(v, fmaxf(acc[mt][1][2 * r2], acc[mt][1][2 * r2 + 1]));
            v = fmaxf(v, fmaxf(acc[mt][2][2 * r2], acc[mt][2][2 * r2 + 1]));
            v = fmaxf(v, __shfl_xor_sync(0xffffffffu, v, 1));
            v = fmaxf(v, __shfl_xor_sync(0xffffffffu, v, 2));
            rmax[mt][r2] = v;
        }
#pragma unroll
    for (int mt = 0; mt < 3; mt++) {
        redM[warpN][mw + mt * 16 + g]     = rmax[mt][0];
        redM[warpN][mw + mt * 16 + g + 8] = rmax[mt][1];
    }
    __syncthreads();
    float rowm[3][2];
#pragma unroll
    for (int mt = 0; mt < 3; mt++)
#pragma unroll
        for (int r2 = 0; r2 < 2; r2++) {
            int row = mw + mt * 16 + g + 8 * r2;
            rowm[mt][r2] = fmaxf(fmaxf(redM[0][row], redM[1][row]),
                                 fmaxf(redM[2][row], redM[3][row]));
        }

    // exponentiate in place + row sums
#pragma unroll
    for (int mt = 0; mt < 3; mt++)
#pragma unroll
        for (int r2 = 0; r2 < 2; r2++) {
            float ssum = 0.f;
#pragma unroll
            for (int nt = 0; nt < 3; nt++) {
                float e0 = __expf(acc[mt][nt][2 * r2]     - rowm[mt][r2]);
                float e1 = __expf(acc[mt][nt][2 * r2 + 1] - rowm[mt][r2]);
                acc[mt][nt][2 * r2]     = e0;
                acc[mt][nt][2 * r2 + 1] = e1;
                ssum += e0 + e1;
            }
            ssum += __shfl_xor_sync(0xffffffffu, ssum, 1);
            ssum += __shfl_xor_sync(0xffffffffu, ssum, 2);
            redS[warpN][mw + mt * 16 + g + 8 * r2] = ssum;
        }
    __syncthreads();

    // write stats (one writer per row)
    if (warpN == 0 && tg == 0) {
#pragma unroll
        for (int mt = 0; mt < 3; mt++)
#pragma unroll
            for (int r2 = 0; r2 < 2; r2++) {
                int row = mw + mt * 16 + g + 8 * r2;
                float rs = redS[0][row] + redS[1][row] + redS[2][row] + redS[3][row];
                gm[(size_t)bl * LL + row] = rowm[mt][r2];
                gs[(size_t)bl * LL + row] = rs;
            }
    }

    // write fp16 numerators
    __half* Ab = att + (size_t)bl * LL * LL;
#pragma unroll
    for (int mt = 0; mt < 3; mt++) {
        int i0 = mw + mt * 16 + g;
        int i1 = i0 + 8;
#pragma unroll
        for (int nt = 0; nt < 3; nt++) {
            int j0 = nw + nt * 8 + 2 * tg;
            *(__half2*)&Ab[(size_t)i0 * LL + j0] = __floats2half2_rn(acc[mt][nt][0], acc[mt][nt][1]);
            *(__half2*)&Ab[(size_t)i1 * LL + j0] = __floats2half2_rn(acc[mt][nt][2], acc[mt][nt][3]);
        }
    }
}

// ---------------- combine H/W row stats into per-row scales ------------------
__global__ void combine_kernel()
{
    int i = blockIdx.x * blockDim.x + threadIdx.x;   // 0..BHW-1
    int dir = blockIdx.y;
    int b = i / HW;
    int hw = i % HW;
    int h = hw / LL, w = hw % LL;
    int idxH = (b * LL + w) * LL + h;
    int idxW = (b * LL + h) * LL + w;
    float mH = g_mH[dir][idxH], sH = g_sH[dir][idxH];
    float mW = g_mW[dir][idxW], sW = g_sW[dir][idxW];
    float m = fmaxf(mH, mW);
    float eh = __expf(mH - m), ew = __expf(mW - m);
    float inv = 1.f / (sH * eh + sW * ew);
    g_scH[dir][idxH] = eh * inv;
    g_scW[dir][idxW] = ew * inv;
}

// ---------------- apply: all 512 channels per block, cp.async double-buffer --
// epilogue rescales columns by combined softmax scale
#define APL_A (96 * 104)                       // halves
#define APL_V (128 * 104)                      // halves per V stage
#define APPLY_SMEM ((APL_A + 2 * APL_V) * 2)   // 73216 B
__global__ __launch_bounds__(256)
void apply_f16_kernel()
{
    extern __shared__ __align__(16) __half smA[];
    __half* As2 = smA;             // [i][k] stride 104
    __half* Vs0 = smA + APL_A;     // two stages of [c][k] stride 104

    int z = blockIdx.y;
    int half_ = z >> 1;
    int isW = z & 1;
    int dir = 1 - half_;
    const __half* Vb = isW ? g_v[half_]  : g_vT[half_];
    const __half* Ab = isW ? g_aW[dir] : g_aH[dir];
    const float* scp = isW ? g_scW[dir] : g_scH[dir];
    __half* Ob = isW ? g_tW[half_] : g_tH[half_];

    int bl  = blockIdx.x;
    int b = bl / LL, line = bl % LL;
    int t = threadIdx.x;
    int warp = t >> 5, lane = t & 31;
    int g = lane >> 2, tg = lane & 3;
    int mw = (warp >> 2) * 64;
    int nw = (warp & 3) * 24;

    scp += (size_t)bl * LL;

    uint32_t asB  = smem_u32(As2);
    uint32_t vs0B = smem_u32(Vs0);

    const __half* Ap = Ab + (size_t)bl * LL * LL;
    for (int idx = t; idx < 96 * 12; idx += 256) {
        int i = idx / 12, j8 = (idx % 12) * 8;
        cp16(asB + (uint32_t)((i * 104 + j8) * 2), &Ap[i * LL + j8]);
    }
    auto loadV = [&](int ct, int s) {
        const __half* Vp = Vb + (((size_t)(b * Cc + ct * 128)) * LL + line) * LL;
        uint32_t dst = vs0B + (uint32_t)(s * APL_V * 2);
#pragma unroll
        for (int r = 0; r < 6; r++) {
            int idx = t + 256 * r;
            int c = idx / 12, j8 = (idx % 12) * 8;
            cp16(dst + (uint32_t)((c * 104 + j8) * 2), &Vp[(size_t)c * HW + j8]);
        }
    };
    loadV(0, 0);
    cp_commit();   // G0 = A + V0

    int aRow = (lane & 7) + ((lane >> 3) & 1) * 8;
    int aK8  = ((lane >> 4) & 1) * 8;
    int bRowN = lane & 7;
    int bK8  = ((lane >> 3) & 1) * 8;

    for (int ct = 0; ct < 4; ct++) {
        if (ct < 3) loadV(ct + 1, (ct + 1) & 1);
        cp_commit();
        asm volatile("cp.async.wait_group 1;" ::: "memory");
        __syncthreads();

        uint32_t vsB = vs0B + (uint32_t)((ct & 1) * APL_V * 2);

        float acc[4][3][4];
#pragma unroll
        for (int i = 0; i < 4; i++)
#pragma unroll
            for (int j = 0; j < 3; j++)
#pragma unroll
                for (int r = 0; r < 4; r++) acc[i][j][r] = 0.f;

#pragma unroll
        for (int kk = 0; kk < 96; kk += 16) {
            uint32_t a[4][4], bb[3][2];
#pragma unroll
            for (int mt = 0; mt < 4; mt++) {
                uint32_t ad = vsB + (uint32_t)(((mw + mt * 16 + aRow) * 104 + kk + aK8) * 2);
                ldsm_x4(a[mt][0], a[mt][1], a[mt][2], a[mt][3], ad);
            }
#pragma unroll
            for (int nt = 0; nt < 3; nt++) {
                uint32_t bd = asB + (uint32_t)(((nw + nt * 8 + bRowN) * 104 + kk + bK8) * 2);
                ldsm_x2(bb[nt][0], bb[nt][1], bd);
            }
#pragma unroll
            for (int mt = 0; mt < 4; mt++)
#pragma unroll
                for (int nt = 0; nt < 3; nt++)
                    mma_f16(acc[mt][nt][0], acc[mt][nt][1], acc[mt][nt][2], acc[mt][nt][3],
                            a[mt][0], a[mt][1], a[mt][2], a[mt][3],
                            bb[nt][0], bb[nt][1]);
        }

        __half* Op = Ob + ((size_t)bl * Cc + ct * 128) * LL;
#pragma unroll
        for (int mt = 0; mt < 4; mt++) {
            int m0g = mw + mt * 16 + g;
            __half* o0 = Op + (size_t)m0g * LL;
            __half* o1 = o0 + (size_t)8 * LL;
#pragma unroll
            for (int nt = 0; nt < 3; nt++) {
                int col = nw + nt * 8 + 2 * tg;
                float2 sc2 = *(const float2*)&scp[col];
                *(__half2*)&o0[col] = __floats2half2_rn(acc[mt][nt][0] * sc2.x,
                                                        acc[mt][nt][1] * sc2.y);
                *(__half2*)&o1[col] = __floats2half2_rn(acc[mt][nt][2] * sc2.x,
                                                        acc[mt][nt][3] * sc2.y);
            }
        }
        __syncthreads();   // protect stage (ct&1) before next prefetch overwrites
    }
}

// ---------------- final: out = gamma*(tH^T + tW) + residual(fp16) ------------
__global__ __launch_bounds__(256)
void final_kernel(const float* __restrict__ gamma, float* __restrict__ out)
{
    __shared__ __half s[32 * 100];   // s[h][w], stride 100 halves
    int z  = blockIdx.y;
    int o  = z >> 12;           // B*C = 4096
    int bc = z & 4095;
    int b  = bc >> 9;
    int c  = bc & 511;
    int h0 = blockIdx.x * 32;
    float g = gamma[0];
    const __half* res = (o == 0 ? g_xh : g_yh) + (size_t)bc * HW;
    const __half* tH = g_tH[o];
    const __half* tW = g_tW[o];
    int t = threadIdx.x;

    const __half* tHb = tH + (((size_t)b * LL) * Cc + c) * LL + h0;
    for (int idx = t; idx < 384; idx += 256) {
        int w = idx >> 2, c8 = (idx & 3) * 8;
        uint4 vv = *(const uint4*)&tHb[(size_t)w * Cc * LL + c8];
        const __half* hv = (const __half*)&vv;
#pragma unroll
        for (int j = 0; j < 8; j++)
            s[(c8 + j) * 100 + w] = hv[j];
    }
    __syncthreads();

    const __half* tWb = tW + (((size_t)b * LL + h0) * Cc + c) * LL;
    float* op = out + (size_t)o * BCHW + (size_t)bc * HW;
    for (int idx = t; idx < 768; idx += 256) {
        int h = idx / 24, w4 = (idx % 24) * 4;
        uint2 su = *(const uint2*)&s[h * 100 + w4];
        __half2 s0 = *(__half2*)&su.x;
        __half2 s1 = *(__half2*)&su.y;
        uint2 twu = *(const uint2*)&tWb[(size_t)h * Cc * LL + w4];
        __half2 tw0 = *(__half2*)&twu.x;
        __half2 tw1 = *(__half2*)&twu.y;
        uint2 rsu = *(const uint2*)&res[(size_t)(h0 + h) * LL + w4];
        __half2 rs0 = *(__half2*)&rsu.x;
        __half2 rs1 = *(__half2*)&rsu.y;
        float4 ov;
        ov.x = g * (__low2float(s0)  + __low2float(tw0))  + __low2float(rs0);
        ov.y = g * (__high2float(s0) + __high2float(tw0)) + __high2float(rs0);
        ov.z = g * (__low2float(s1)  + __low2float(tw1))  + __low2float(rs1);
        ov.w = g * (__high2float(s1) + __high2float(tw1)) + __high2float(rs1);
        *(float4*)&op[(size_t)(h0 + h) * LL + w4] = ov;
    }
}

// ---------------------------------------------------------------------------
extern "C" void kernel_launch(void* const* d_in, const int* in_sizes, int n_in,
                              void* d_out, int out_size)
{
    const float* x     = (const float*)d_in[0];
    const float* y     = (const float*)d_in[1];
    const float* Wq    = (const float*)d_in[2];
    const float* bq    = (const float*)d_in[3];
    const float* Wk    = (const float*)d_in[4];
    const float* bk    = (const float*)d_in[5];
    const float* Wv    = (const float*)d_in[6];
    const float* bv    = (const float*)d_in[7];
    const float* gamma = (const float*)d_in[8];
    float* out = (float*)d_out;
    (void)in_sizes; (void)n_in; (void)out_size;

    __half *xh, *yh, *qk, *qkT, *v, *vT;
    cudaGetSymbolAddress((void**)&xh,  g_xh);
    cudaGetSymbolAddress((void**)&yh,  g_yh);
    cudaGetSymbolAddress((void**)&qk,  g_qk);
    cudaGetSymbolAddress((void**)&qkT, g_qkT);
    cudaGetSymbolAddress((void**)&v,   g_v);
    cudaGetSymbolAddress((void**)&vT,  g_vT);

    cudaFuncSetAttribute(proj_f16_kernel,  cudaFuncAttributeMaxDynamicSharedMemorySize, PROJ_SMEM);
    cudaFuncSetAttribute(apply_f16_kernel, cudaFuncAttributeMaxDynamicSharedMemorySize, APPLY_SMEM);

    // side stream + events for capturing a parallel v-transpose branch
    cudaStream_t s2;
    cudaStreamCreateWithFlags(&s2, cudaStreamNonBlocking);
    cudaEvent_t ev1, ev2;
    cudaEventCreateWithFlags(&ev1, cudaEventDisableTiming);
    cudaEventCreateWithFlags(&ev2, cudaEventDisableTiming);

    dim3 tb(16, 16);

    // 0) convert inputs + stack weights to fp16
    f2h_kernel<<<dim3(BCHW / 2048, 2), 256>>>(x, y);
    weights_kernel<<<1280, 256>>>(Wq, bq, Wk, bk, Wv, bv);

    // 1) fused projections: single launch computes qk and v for both inputs
    proj_f16_kernel<<<dim3(72, 5, 16), 256, PROJ_SMEM>>>(xh, yh);

    // fork: v-transpose on side stream (only apply needs vT)
    cudaEventRecord(ev1, 0);
    cudaStreamWaitEvent(s2, ev1, 0);
    transpose16_kernel<<<dim3(3, 3, 2 * Bz * Cc), tb, 0, s2>>>(v, vT);

    // main stream: qk transpose -> energy (+fused row softmax) -> combine
    transpose16_kernel<<<dim3(3, 3, 2 * Bz * 128), tb>>>(qk, qkT);
    energy_kernel<<<dim3(Bz * LL, 4), 256>>>();
    combine_kernel<<<dim3(BHW / 256, 2), 256>>>();

    // join: apply needs combine output and vT
    cudaEventRecord(ev2, s2);
    cudaStreamWaitEvent(0, ev2, 0);

    // 5) applies (4 variants, all channels per block, pipelined, scaled epilogue)
    apply_f16_kernel<<<dim3(Bz * LL, 4), 256, APPLY_SMEM>>>();

    // 6) combine + residual (fp16 residual from g_xh/g_yh)
    final_kernel<<<dim3(3, 2 * Bz * Cc), 256>>>(gamma, out);
}